// round 1
// baseline (speedup 1.0000x reference)
#include <cuda_runtime.h>
#include <math.h>

// ---------------- problem constants ----------------
#define NTOK   4096              // B*N = 2*2048
#define DIMC   1024
#define NHEADS 16
#define DHEAD  64
#define MLPHID 716
#define FW     3788              // 3*DIM + MLP_HID
#define NSEQ   2048
#define LN_EPS 1e-6f

// ---------------- scratch (static device globals; no runtime alloc) ------
__device__ float g_norm [NTOK * DIMC];     // 16 MB
__device__ float g_fused[NTOK * FW];       // 62 MB  (qkv | mlp_hidden), LN'd in place
__device__ float g_attn [NTOK * DIMC];     // 16 MB  attention output, head-concat layout
__device__ float g_comb [NTOK * 2 * DIMC]; // 32 MB  [attn_out | mlp_out]

// ============================================================
// LayerNorm over DIM=1024, one block (256 thr) per row
// ============================================================
__global__ void ln_kernel(const float* __restrict__ x,
                          const float* __restrict__ g,
                          const float* __restrict__ b,
                          float* __restrict__ out)
{
    int row = blockIdx.x;
    int tid = threadIdx.x;                 // 256 threads, 4 floats each
    const float4 v  = reinterpret_cast<const float4*>(x + (size_t)row * DIMC)[tid];

    float s  = v.x + v.y + v.z + v.w;
    float sq = v.x*v.x + v.y*v.y + v.z*v.z + v.w*v.w;
    #pragma unroll
    for (int o = 16; o > 0; o >>= 1) {
        s  += __shfl_xor_sync(0xffffffffu, s,  o);
        sq += __shfl_xor_sync(0xffffffffu, sq, o);
    }
    __shared__ float ws[8], wq[8];
    int warp = tid >> 5, lane = tid & 31;
    if (lane == 0) { ws[warp] = s; wq[warp] = sq; }
    __syncthreads();
    if (warp == 0) {
        float s2  = (lane < 8) ? ws[lane] : 0.f;
        float sq2 = (lane < 8) ? wq[lane] : 0.f;
        #pragma unroll
        for (int o = 4; o > 0; o >>= 1) {
            s2  += __shfl_xor_sync(0xffffffffu, s2,  o);
            sq2 += __shfl_xor_sync(0xffffffffu, sq2, o);
        }
        if (lane == 0) { ws[0] = s2; wq[0] = sq2; }
    }
    __syncthreads();
    float mean = ws[0] * (1.f / DIMC);
    float var  = wq[0] * (1.f / DIMC) - mean * mean;
    float rstd = rsqrtf(var + LN_EPS);

    float4 gg = reinterpret_cast<const float4*>(g)[tid];
    float4 bb = reinterpret_cast<const float4*>(b)[tid];
    float4 o4;
    o4.x = (v.x - mean) * rstd * gg.x + bb.x;
    o4.y = (v.y - mean) * rstd * gg.y + bb.y;
    o4.z = (v.z - mean) * rstd * gg.z + bb.z;
    o4.w = (v.w - mean) * rstd * gg.w + bb.w;
    reinterpret_cast<float4*>(out + (size_t)row * DIMC)[tid] = o4;
}

// ============================================================
// Generic SGEMM: C[M,N] = A[M,K] @ B[K,N] (+ bias[N]) (+ resid)
// 128x128 tile, BK=8, 256 threads, 8x8 microtile (4+4 split).
// M must be a multiple of 128; N,K arbitrary with N%4==0, K%4==0.
// ============================================================
__global__ void __launch_bounds__(256, 2)
sgemm_kernel(const float* __restrict__ A, int lda,
             const float* __restrict__ B, int ldb,
             float* __restrict__ C, int ldc,
             const float* __restrict__ bias,
             const float* __restrict__ resid, int ldr,
             int M, int N, int K)
{
    __shared__ float As[8][128];
    __shared__ float Bs[8][128];

    int tid = threadIdx.x;
    int bm  = blockIdx.y * 128;
    int bn  = blockIdx.x * 128;
    int tx  = tid & 15;          // 0..15 -> col groups
    int ty  = tid >> 4;          // 0..15 -> row groups

    // A tile loader: each thread 1 float4 along K
    int arow = tid >> 1;               // 0..127
    int acol = (tid & 1) * 4;          // 0 or 4
    // B tile loader: each thread 1 float4 along N
    int brow = tid >> 5;               // 0..7
    int bcol = (tid & 31) * 4;         // 0..124

    float acc[8][8];
    #pragma unroll
    for (int i = 0; i < 8; i++)
        #pragma unroll
        for (int j = 0; j < 8; j++) acc[i][j] = 0.f;

    for (int k0 = 0; k0 < K; k0 += 8) {
        float4 av = make_float4(0.f, 0.f, 0.f, 0.f);
        if (k0 + acol < K)   // K%4==0 -> full float4 in range
            av = *reinterpret_cast<const float4*>(A + (size_t)(bm + arow) * lda + k0 + acol);
        As[acol + 0][arow] = av.x;
        As[acol + 1][arow] = av.y;
        As[acol + 2][arow] = av.z;
        As[acol + 3][arow] = av.w;

        float4 bv = make_float4(0.f, 0.f, 0.f, 0.f);
        if ((k0 + brow < K) && (bn + bcol < N))  // N%4==0 -> full float4
            bv = *reinterpret_cast<const float4*>(B + (size_t)(k0 + brow) * ldb + bn + bcol);
        *reinterpret_cast<float4*>(&Bs[brow][bcol]) = bv;

        __syncthreads();

        #pragma unroll
        for (int kk = 0; kk < 8; kk++) {
            float a0[4], a1[4], b0[4], b1[4];
            *reinterpret_cast<float4*>(a0) = *reinterpret_cast<const float4*>(&As[kk][ty * 4]);
            *reinterpret_cast<float4*>(a1) = *reinterpret_cast<const float4*>(&As[kk][ty * 4 + 64]);
            *reinterpret_cast<float4*>(b0) = *reinterpret_cast<const float4*>(&Bs[kk][tx * 4]);
            *reinterpret_cast<float4*>(b1) = *reinterpret_cast<const float4*>(&Bs[kk][tx * 4 + 64]);
            #pragma unroll
            for (int i = 0; i < 4; i++) {
                #pragma unroll
                for (int j = 0; j < 4; j++) {
                    acc[i    ][j    ] = fmaf(a0[i], b0[j], acc[i    ][j    ]);
                    acc[i    ][j + 4] = fmaf(a0[i], b1[j], acc[i    ][j + 4]);
                    acc[i + 4][j    ] = fmaf(a1[i], b0[j], acc[i + 4][j    ]);
                    acc[i + 4][j + 4] = fmaf(a1[i], b1[j], acc[i + 4][j + 4]);
                }
            }
        }
        __syncthreads();
    }

    // epilogue
    #pragma unroll
    for (int ii = 0; ii < 2; ii++) {
        #pragma unroll
        for (int i = 0; i < 4; i++) {
            int r = bm + ii * 64 + ty * 4 + i;
            #pragma unroll
            for (int jj = 0; jj < 2; jj++) {
                #pragma unroll
                for (int j = 0; j < 4; j++) {
                    int c = bn + jj * 64 + tx * 4 + j;
                    if (c < N) {
                        float val = acc[ii * 4 + i][jj * 4 + j];
                        if (bias)  val += bias[c];
                        if (resid) val += resid[(size_t)r * ldr + c];
                        C[(size_t)r * ldc + c] = val;
                    }
                }
            }
        }
    }
}

// ============================================================
// Per-head Q/K layernorm over DHEAD=64, in place inside g_fused.
// One warp per (token, q|k, head). 256 threads = 8 warps/block.
// ============================================================
__global__ void qkln_kernel(float* __restrict__ fused,
                            const float* __restrict__ qg, const float* __restrict__ qb,
                            const float* __restrict__ kg, const float* __restrict__ kb)
{
    int gid   = blockIdx.x * 8 + (threadIdx.x >> 5);
    int lane  = threadIdx.x & 31;
    int token = gid >> 5;
    int rem   = gid & 31;
    int qk    = rem >> 4;       // 0 = q, 1 = k
    int head  = rem & 15;

    float* p = fused + (size_t)token * FW + qk * DIMC + head * DHEAD;
    float v0 = p[lane];
    float v1 = p[lane + 32];

    float s = v0 + v1;
    #pragma unroll
    for (int o = 16; o > 0; o >>= 1) s += __shfl_xor_sync(0xffffffffu, s, o);
    float mean = s * (1.f / 64.f);

    float d0 = v0 - mean, d1 = v1 - mean;
    float sq = d0 * d0 + d1 * d1;
    #pragma unroll
    for (int o = 16; o > 0; o >>= 1) sq += __shfl_xor_sync(0xffffffffu, sq, o);
    float rstd = rsqrtf(sq * (1.f / 64.f) + LN_EPS);

    const float* g = qk ? kg : qg;
    const float* b = qk ? kb : qb;
    p[lane]      = d0 * rstd * g[lane]      + b[lane];
    p[lane + 32] = d1 * rstd * g[lane + 32] + b[lane + 32];
}

// ============================================================
// GELU (tanh approx) in place on mlp_hidden slice of g_fused.
// grid (ceil(716/256), NTOK)
// ============================================================
__global__ void gelu_kernel(float* __restrict__ fused)
{
    int j = blockIdx.x * 256 + threadIdx.x;
    if (j < MLPHID) {
        float* p = fused + (size_t)blockIdx.y * FW + 3 * DIMC + j;
        float x = *p;
        float u = 0.7978845608028654f * (x + 0.044715f * x * x * x);
        *p = 0.5f * x * (1.f + tanhf(u));
    }
}

// ============================================================
// Attention: one block per (b, h, 128-query tile). One thread = one query.
// Q in registers, K/V streamed through SMEM in 64-row tiles, online softmax.
// ============================================================
__global__ void __launch_bounds__(128)
attn_kernel(const float* __restrict__ fused, float* __restrict__ aout)
{
    __shared__ float Kt[64][64];
    __shared__ float Vt[64][64];

    int tid = threadIdx.x;
    int h   = blockIdx.y;
    int bb  = blockIdx.z;
    int qn  = blockIdx.x * 128 + tid;
    int tq  = bb * NSEQ + qn;

    const float* qp = fused + (size_t)tq * FW + h * DHEAD;
    float q[DHEAD];
    #pragma unroll
    for (int d = 0; d < DHEAD; d++) q[d] = qp[d];

    float acc[DHEAD];
    #pragma unroll
    for (int d = 0; d < DHEAD; d++) acc[d] = 0.f;
    float m = -1e30f, l = 0.f;
    const float scale = 0.125f;           // 1/sqrt(64)

    int kvbase = bb * NSEQ;
    for (int kt = 0; kt < NSEQ; kt += 64) {
        // cooperative load of K/V tile (coalesced 64-float rows)
        #pragma unroll 8
        for (int i = 0; i < 32; i++) {
            int idx = i * 128 + tid;
            int row = idx >> 6, col = idx & 63;
            const float* base = fused + (size_t)(kvbase + kt + row) * FW + h * DHEAD + col;
            Kt[row][col] = base[DIMC];       // K slab at +1024
            Vt[row][col] = base[2 * DIMC];   // V slab at +2048
        }
        __syncthreads();

        for (int j = 0; j < 64; j++) {
            float s0 = 0.f, s1 = 0.f, s2 = 0.f, s3 = 0.f;
            #pragma unroll
            for (int d = 0; d < DHEAD; d += 4) {
                s0 = fmaf(q[d    ], Kt[j][d    ], s0);
                s1 = fmaf(q[d + 1], Kt[j][d + 1], s1);
                s2 = fmaf(q[d + 2], Kt[j][d + 2], s2);
                s3 = fmaf(q[d + 3], Kt[j][d + 3], s3);
            }
            float s    = ((s0 + s1) + (s2 + s3)) * scale;
            float mnew = fmaxf(m, s);
            float corr = __expf(m - mnew);
            float p    = __expf(s - mnew);
            l = l * corr + p;
            m = mnew;
            #pragma unroll
            for (int d = 0; d < DHEAD; d++)
                acc[d] = fmaf(acc[d], corr, p * Vt[j][d]);
        }
        __syncthreads();
    }

    float rl = 1.f / l;
    float* op = aout + (size_t)tq * DIMC + h * DHEAD;
    #pragma unroll
    for (int d = 0; d < DHEAD; d++) op[d] = acc[d] * rl;
}

// ============================================================
// launch
// ============================================================
extern "C" void kernel_launch(void* const* d_in, const int* in_sizes, int n_in,
                              void* d_out, int out_size)
{
    const float* x      = (const float*)d_in[0];
    const float* norm_g = (const float*)d_in[1];
    const float* norm_b = (const float*)d_in[2];
    const float* W1     = (const float*)d_in[3];
    const float* b1     = (const float*)d_in[4];
    const float* qn_g   = (const float*)d_in[5];
    const float* qn_b   = (const float*)d_in[6];
    const float* kn_g   = (const float*)d_in[7];
    const float* kn_b   = (const float*)d_in[8];
    const float* Wao    = (const float*)d_in[9];
    const float* bao    = (const float*)d_in[10];
    const float* Wmo    = (const float*)d_in[11];
    const float* bmo    = (const float*)d_in[12];
    const float* W2     = (const float*)d_in[13];
    const float* b2     = (const float*)d_in[14];
    float*       out    = (float*)d_out;

    float *norm, *fused, *attn, *comb;
    cudaGetSymbolAddress((void**)&norm,  g_norm);
    cudaGetSymbolAddress((void**)&fused, g_fused);
    cudaGetSymbolAddress((void**)&attn,  g_attn);
    cudaGetSymbolAddress((void**)&comb,  g_comb);

    // 1) layernorm(x)
    ln_kernel<<<NTOK, 256>>>(x, norm_g, norm_b, norm);

    // 2) fused = norm @ W1 + b1   [4096 x 3788]
    {
        dim3 grid((FW + 127) / 128, NTOK / 128);   // 30 x 32
        sgemm_kernel<<<grid, 256>>>(norm, DIMC, W1, FW, fused, FW,
                                    b1, nullptr, 0, NTOK, FW, DIMC);
    }

    // 3) per-head LN on q and k slabs (in place)
    qkln_kernel<<<(NTOK * 32) / 8, 256>>>(fused, qn_g, qn_b, kn_g, kn_b);

    // 4) gelu on mlp_hidden slab (in place)
    gelu_kernel<<<dim3((MLPHID + 255) / 256, NTOK), 256>>>(fused);

    // 5) attention -> g_attn (head-concat layout [token, 1024])
    attn_kernel<<<dim3(NSEQ / 128, NHEADS, 2), 128>>>(fused, attn);

    // 6) attn_out = attn @ Wao + bao  -> comb[:, 0:1024]
    {
        dim3 grid(DIMC / 128, NTOK / 128);         // 8 x 32
        sgemm_kernel<<<grid, 256>>>(attn, DIMC, Wao, DIMC, comb, 2 * DIMC,
                                    bao, nullptr, 0, NTOK, DIMC, DIMC);
    }

    // 7) mlp_out = gelu_hidden @ Wmo + bmo -> comb[:, 1024:2048]
    {
        dim3 grid(DIMC / 128, NTOK / 128);
        sgemm_kernel<<<grid, 256>>>(fused + 3 * DIMC, FW, Wmo, DIMC,
                                    comb + DIMC, 2 * DIMC,
                                    bmo, nullptr, 0, NTOK, DIMC, MLPHID);
    }

    // 8) out = x + comb @ W2 + b2
    {
        dim3 grid(DIMC / 128, NTOK / 128);
        sgemm_kernel<<<grid, 256>>>(comb, 2 * DIMC, W2, DIMC, out, DIMC,
                                    b2, x, DIMC, NTOK, DIMC, 2 * DIMC);
    }
}

// round 3
// speedup vs baseline: 1.7872x; 1.7872x over previous
#include <cuda_runtime.h>
#include <math.h>
#include <stdint.h>

// ---------------- problem constants ----------------
#define NTOK   4096              // B*N = 2*2048
#define DIMC   1024
#define NHEADS 16
#define DHEAD  64
#define MLPHID 716
#define FW     3788              // 3*DIM + MLP_HID (true width)
#define FWP    3840              // padded to 30*128
#define KHPAD  736               // MLPHID padded to mult of 32
#define NSEQ   2048
#define LN_EPS 1e-6f

typedef unsigned long long u64;

// ---------------- scratch (static device globals) ------
__device__ float g_norm [NTOK * DIMC];
__device__ float g_fused[NTOK * FWP];
__device__ float g_attn [NTOK * DIMC];
__device__ float g_comb [NTOK * 2 * DIMC];
__device__ float g_w1t  [FWP  * DIMC];        // [N=3840][K=1024]
__device__ float g_waot [DIMC * DIMC];        // [1024][1024]
__device__ float g_wmot [DIMC * KHPAD];       // [1024][736]
__device__ float g_w2t  [DIMC * 2 * DIMC];    // [1024][2048]

// ================= helpers =================
__device__ __forceinline__ uint32_t tf32cvt(float x) {
    uint32_t u;
    asm("cvt.rna.tf32.f32 %0, %1;" : "=r"(u) : "f"(x));
    return u;
}

__device__ __forceinline__ void mma_tf32(float& d0, float& d1, float& d2, float& d3,
                                         uint32_t a0, uint32_t a1, uint32_t a2, uint32_t a3,
                                         uint32_t b0, uint32_t b1)
{
    asm volatile(
        "mma.sync.aligned.m16n8k8.row.col.f32.tf32.tf32.f32 "
        "{%0,%1,%2,%3}, {%4,%5,%6,%7}, {%8,%9}, {%0,%1,%2,%3};"
        : "+f"(d0), "+f"(d1), "+f"(d2), "+f"(d3)
        : "r"(a0), "r"(a1), "r"(a2), "r"(a3), "r"(b0), "r"(b1));
}

// f32x2 packed math
__device__ __forceinline__ u64 f2fma(u64 a, u64 b, u64 c) {
    u64 d; asm("fma.rn.f32x2 %0,%1,%2,%3;" : "=l"(d) : "l"(a), "l"(b), "l"(c)); return d;
}
__device__ __forceinline__ u64 f2mul(u64 a, u64 b) {
    u64 d; asm("mul.rn.f32x2 %0,%1,%2;" : "=l"(d) : "l"(a), "l"(b)); return d;
}
__device__ __forceinline__ u64 f2add(u64 a, u64 b) {
    u64 d; asm("add.rn.f32x2 %0,%1,%2;" : "=l"(d) : "l"(a), "l"(b)); return d;
}
__device__ __forceinline__ u64 pack2(float x) {
    u64 r; asm("mov.b64 %0,{%1,%1};" : "=l"(r) : "f"(x)); return r;
}
__device__ __forceinline__ void unpk(u64 v, float& lo, float& hi) {
    asm("mov.b64 {%0,%1},%2;" : "=f"(lo), "=f"(hi) : "l"(v));
}

// ============================================================
// weight transpose: Wt[n][k] = W[k][n], zero-filled to Kpad/Npad
// ============================================================
__global__ void transpose_kernel(const float* __restrict__ W, int K, int N,
                                 float* __restrict__ Wt, int Kpad, int Npad)
{
    __shared__ float t[32][33];
    int n0 = blockIdx.x * 32, k0 = blockIdx.y * 32;
    int tx = threadIdx.x, ty = threadIdx.y;
    #pragma unroll
    for (int i = 0; i < 32; i += 8) {
        int k = k0 + ty + i, n = n0 + tx;
        t[ty + i][tx] = (k < K && n < N) ? W[(size_t)k * N + n] : 0.f;
    }
    __syncthreads();
    #pragma unroll
    for (int i = 0; i < 32; i += 8) {
        int n = n0 + ty + i, k = k0 + tx;
        if (n < Npad && k < Kpad) Wt[(size_t)n * Kpad + k] = t[tx][ty + i];
    }
}

// ============================================================
// LayerNorm over DIM=1024, one block (256 thr) per row
// ============================================================
__global__ void ln_kernel(const float* __restrict__ x,
                          const float* __restrict__ g,
                          const float* __restrict__ b,
                          float* __restrict__ out)
{
    int row = blockIdx.x;
    int tid = threadIdx.x;
    const float4 v = reinterpret_cast<const float4*>(x + (size_t)row * DIMC)[tid];

    float s  = v.x + v.y + v.z + v.w;
    float sq = v.x*v.x + v.y*v.y + v.z*v.z + v.w*v.w;
    #pragma unroll
    for (int o = 16; o > 0; o >>= 1) {
        s  += __shfl_xor_sync(0xffffffffu, s,  o);
        sq += __shfl_xor_sync(0xffffffffu, sq, o);
    }
    __shared__ float ws[8], wq[8];
    int warp = tid >> 5, lane = tid & 31;
    if (lane == 0) { ws[warp] = s; wq[warp] = sq; }
    __syncthreads();
    if (warp == 0) {
        float s2  = (lane < 8) ? ws[lane] : 0.f;
        float sq2 = (lane < 8) ? wq[lane] : 0.f;
        #pragma unroll
        for (int o = 4; o > 0; o >>= 1) {
            s2  += __shfl_xor_sync(0xffffffffu, s2,  o);
            sq2 += __shfl_xor_sync(0xffffffffu, sq2, o);
        }
        if (lane == 0) { ws[0] = s2; wq[0] = sq2; }
    }
    __syncthreads();
    float mean = ws[0] * (1.f / DIMC);
    float var  = wq[0] * (1.f / DIMC) - mean * mean;
    float rstd = rsqrtf(var + LN_EPS);

    float4 gg = reinterpret_cast<const float4*>(g)[tid];
    float4 bb = reinterpret_cast<const float4*>(b)[tid];
    float4 o4;
    o4.x = (v.x - mean) * rstd * gg.x + bb.x;
    o4.y = (v.y - mean) * rstd * gg.y + bb.y;
    o4.z = (v.z - mean) * rstd * gg.z + bb.z;
    o4.w = (v.w - mean) * rstd * gg.w + bb.w;
    reinterpret_cast<float4*>(out + (size_t)row * DIMC)[tid] = o4;
}

// ============================================================
// tf32 mma.sync GEMM: C[M,Npad] = A[M,K] @ Bt[Npad,K]^T (+bias)(+resid)
// 128x128 CTA tile, BK=32, 256 thr, 8 warps of 64x32, double-buffered.
// SMEM rows padded to 36 floats -> conflict-free fragment LDS.
// ============================================================
#define SSTR  36
#define ABUF  (128 * SSTR)            // 4608 floats
#define BUFSZ (2 * ABUF)              // A + B per buffer
#define GEMM_SMEM (2 * BUFSZ * 4)     // bytes, double-buffered

__global__ void __launch_bounds__(256, 2)
mma_gemm(const float* __restrict__ A, int lda,
         const float* __restrict__ Bt, int ldb,
         float* __restrict__ C, int ldc,
         const float* __restrict__ bias, int nbias,
         const float* __restrict__ resid, int ldr,
         int K)
{
    extern __shared__ float sm[];
    int tid  = threadIdx.x;
    int wid  = tid >> 5, lane = tid & 31;
    int gid2 = lane >> 2, tig = lane & 3;
    int bm = blockIdx.y * 128, bn = blockIdx.x * 128;
    int wm = (wid & 1) * 64, wn = (wid >> 1) * 32;

    float acc[4][4][4];
    #pragma unroll
    for (int i = 0; i < 4; i++)
        #pragma unroll
        for (int j = 0; j < 4; j++)
            #pragma unroll
            for (int r = 0; r < 4; r++) acc[i][j][r] = 0.f;

    int lr = tid >> 3;               // 0..31 row within 128-chunk? (see loop)
    int lc = (tid & 7) * 4;          // k offset 0..28

    // loads one 128x32 A tile + 128x32 B tile into buffer b, with tf32 rounding
    auto load_buf = [&](int k0, int b) {
        float* sA = sm + b * BUFSZ;
        float* sB = sA + ABUF;
        #pragma unroll
        for (int i = 0; i < 4; i++) {
            int r = i * 32 + lr;
            float4 va = *reinterpret_cast<const float4*>(
                A + (size_t)(bm + r) * lda + k0 + lc);
            uint4 ua;
            ua.x = tf32cvt(va.x); ua.y = tf32cvt(va.y);
            ua.z = tf32cvt(va.z); ua.w = tf32cvt(va.w);
            *reinterpret_cast<uint4*>(sA + r * SSTR + lc) = ua;

            float4 vb = *reinterpret_cast<const float4*>(
                Bt + (size_t)(bn + r) * ldb + k0 + lc);
            uint4 ub;
            ub.x = tf32cvt(vb.x); ub.y = tf32cvt(vb.y);
            ub.z = tf32cvt(vb.z); ub.w = tf32cvt(vb.w);
            *reinterpret_cast<uint4*>(sB + r * SSTR + lc) = ub;
        }
    };

    const int nk = K >> 5;
    load_buf(0, 0);
    __syncthreads();

    for (int it = 0; it < nk; it++) {
        int b = it & 1;
        const uint32_t* sA = reinterpret_cast<const uint32_t*>(sm + b * BUFSZ);
        const uint32_t* sB = sA + ABUF;

        #pragma unroll
        for (int kk = 0; kk < 4; kk++) {
            int k8 = kk * 8;
            uint32_t af[4][4], bf[4][2];
            #pragma unroll
            for (int mt = 0; mt < 4; mt++) {
                int row = wm + mt * 16 + gid2;
                af[mt][0] = sA[(row    ) * SSTR + k8 + tig    ];
                af[mt][1] = sA[(row + 8) * SSTR + k8 + tig    ];
                af[mt][2] = sA[(row    ) * SSTR + k8 + tig + 4];
                af[mt][3] = sA[(row + 8) * SSTR + k8 + tig + 4];
            }
            #pragma unroll
            for (int nt = 0; nt < 4; nt++) {
                int col = wn + nt * 8 + gid2;
                bf[nt][0] = sB[col * SSTR + k8 + tig    ];
                bf[nt][1] = sB[col * SSTR + k8 + tig + 4];
            }
            #pragma unroll
            for (int mt = 0; mt < 4; mt++)
                #pragma unroll
                for (int nt = 0; nt < 4; nt++)
                    mma_tf32(acc[mt][nt][0], acc[mt][nt][1],
                             acc[mt][nt][2], acc[mt][nt][3],
                             af[mt][0], af[mt][1], af[mt][2], af[mt][3],
                             bf[nt][0], bf[nt][1]);
        }
        __syncthreads();
        if (it + 1 < nk) {
            load_buf((it + 1) << 5, b ^ 1);
            __syncthreads();
        }
    }

    // epilogue
    #pragma unroll
    for (int mt = 0; mt < 4; mt++) {
        int r0 = bm + wm + mt * 16 + gid2;
        #pragma unroll
        for (int nt = 0; nt < 4; nt++) {
            int c = bn + wn + nt * 8 + tig * 2;
            float2 v0 = make_float2(acc[mt][nt][0], acc[mt][nt][1]);
            float2 v1 = make_float2(acc[mt][nt][2], acc[mt][nt][3]);
            if (bias) {
                float bx = (c     < nbias) ? bias[c]     : 0.f;
                float by = (c + 1 < nbias) ? bias[c + 1] : 0.f;
                v0.x += bx; v0.y += by;
                v1.x += bx; v1.y += by;
            }
            if (resid) {
                float2 ra = *reinterpret_cast<const float2*>(resid + (size_t)r0 * ldr + c);
                float2 rb = *reinterpret_cast<const float2*>(resid + (size_t)(r0 + 8) * ldr + c);
                v0.x += ra.x; v0.y += ra.y;
                v1.x += rb.x; v1.y += rb.y;
            }
            *reinterpret_cast<float2*>(C + (size_t)r0 * ldc + c) = v0;
            *reinterpret_cast<float2*>(C + (size_t)(r0 + 8) * ldc + c) = v1;
        }
    }
}

// ============================================================
// Per-head Q/K layernorm over DHEAD=64 (padded fused stride)
// ============================================================
__global__ void qkln_kernel(float* __restrict__ fused,
                            const float* __restrict__ qg, const float* __restrict__ qb,
                            const float* __restrict__ kg, const float* __restrict__ kb)
{
    int gid   = blockIdx.x * 8 + (threadIdx.x >> 5);
    int lane  = threadIdx.x & 31;
    int token = gid >> 5;
    int rem   = gid & 31;
    int qk    = rem >> 4;
    int head  = rem & 15;

    float* p = fused + (size_t)token * FWP + qk * DIMC + head * DHEAD;
    float v0 = p[lane];
    float v1 = p[lane + 32];

    float s = v0 + v1;
    #pragma unroll
    for (int o = 16; o > 0; o >>= 1) s += __shfl_xor_sync(0xffffffffu, s, o);
    float mean = s * (1.f / 64.f);

    float d0 = v0 - mean, d1 = v1 - mean;
    float sq = d0 * d0 + d1 * d1;
    #pragma unroll
    for (int o = 16; o > 0; o >>= 1) sq += __shfl_xor_sync(0xffffffffu, sq, o);
    float rstd = rsqrtf(sq * (1.f / 64.f) + LN_EPS);

    const float* g = qk ? kg : qg;
    const float* b = qk ? kb : qb;
    p[lane]      = d0 * rstd * g[lane]      + b[lane];
    p[lane + 32] = d1 * rstd * g[lane + 32] + b[lane + 32];
}

// ============================================================
// GELU (tanh approx) in place on mlp_hidden slice
// ============================================================
__global__ void gelu_kernel(float* __restrict__ fused)
{
    int j = blockIdx.x * 256 + threadIdx.x;
    if (j < MLPHID) {
        float* p = fused + (size_t)blockIdx.y * FWP + 3 * DIMC + j;
        float x = *p;
        float u = 0.7978845608028654f * (x + 0.044715f * x * x * x);
        *p = 0.5f * x * (1.f + tanhf(u));
    }
}

// ============================================================
// Attention with f32x2 packed math + chunked tile-max softmax.
// One thread = one query row. K/V 64-row tiles in SMEM.
// ============================================================
__global__ void __launch_bounds__(128)
attn_kernel(const float* __restrict__ fused, float* __restrict__ aout)
{
    __shared__ float Kt[64][64];
    __shared__ float Vt[64][64];

    int tid = threadIdx.x;
    int h   = blockIdx.y;
    int bb  = blockIdx.z;
    int qn  = blockIdx.x * 128 + tid;
    int tq  = bb * NSEQ + qn;

    // load q packed, pre-scaled by 1/sqrt(Dh)
    const ulonglong2* qp = reinterpret_cast<const ulonglong2*>(
        fused + (size_t)tq * FWP + h * DHEAD);
    u64 q2[32];
    u64 sc2 = pack2(0.125f);
    #pragma unroll
    for (int i = 0; i < 16; i++) {
        ulonglong2 t = qp[i];
        q2[2 * i]     = f2mul(t.x, sc2);
        q2[2 * i + 1] = f2mul(t.y, sc2);
    }

    u64 acc2[32];
    #pragma unroll
    for (int i = 0; i < 32; i++) acc2[i] = 0ull;
    float m = -1e30f, l = 0.f;

    int kvbase = bb * NSEQ;
    for (int kt = 0; kt < NSEQ; kt += 64) {
        #pragma unroll 8
        for (int i = 0; i < 32; i++) {
            int idx = i * 128 + tid;
            int row = idx >> 6, col = idx & 63;
            const float* base = fused + (size_t)(kvbase + kt + row) * FWP + h * DHEAD + col;
            Kt[row][col] = base[DIMC];
            Vt[row][col] = base[2 * DIMC];
        }
        __syncthreads();

        #pragma unroll
        for (int c = 0; c < 2; c++) {
            float s[32];
            #pragma unroll 4
            for (int j = 0; j < 32; j++) {
                const ulonglong2* kp = reinterpret_cast<const ulonglong2*>(&Kt[c * 32 + j][0]);
                u64 d0 = 0ull, d1 = 0ull, d2 = 0ull, d3 = 0ull;
                #pragma unroll
                for (int i = 0; i < 8; i++) {
                    ulonglong2 k0 = kp[2 * i];
                    ulonglong2 k1 = kp[2 * i + 1];
                    d0 = f2fma(q2[4 * i],     k0.x, d0);
                    d1 = f2fma(q2[4 * i + 1], k0.y, d1);
                    d2 = f2fma(q2[4 * i + 2], k1.x, d2);
                    d3 = f2fma(q2[4 * i + 3], k1.y, d3);
                }
                u64 dd = f2add(f2add(d0, d1), f2add(d2, d3));
                float lo, hi; unpk(dd, lo, hi);
                s[j] = lo + hi;
            }
            float tmax = s[0];
            #pragma unroll
            for (int j = 1; j < 32; j++) tmax = fmaxf(tmax, s[j]);
            float mnew = fmaxf(m, tmax);
            float corr = __expf(m - mnew);
            m = mnew;
            l *= corr;
            u64 c2 = pack2(corr);
            #pragma unroll
            for (int i = 0; i < 32; i++) acc2[i] = f2mul(acc2[i], c2);
            #pragma unroll 2
            for (int j = 0; j < 32; j++) {
                float p = __expf(s[j] - m);
                l += p;
                u64 p2 = pack2(p);
                const ulonglong2* vp = reinterpret_cast<const ulonglong2*>(&Vt[c * 32 + j][0]);
                #pragma unroll
                for (int i = 0; i < 16; i++) {
                    ulonglong2 vv = vp[i];
                    acc2[2 * i]     = f2fma(vv.x, p2, acc2[2 * i]);
                    acc2[2 * i + 1] = f2fma(vv.y, p2, acc2[2 * i + 1]);
                }
            }
        }
        __syncthreads();
    }

    u64 rl2 = pack2(1.f / l);
    u64* op = reinterpret_cast<u64*>(aout + (size_t)tq * DIMC + h * DHEAD);
    #pragma unroll
    for (int i = 0; i < 32; i++) op[i] = f2mul(acc2[i], rl2);
}

// ============================================================
// launch
// ============================================================
extern "C" void kernel_launch(void* const* d_in, const int* in_sizes, int n_in,
                              void* d_out, int out_size)
{
    const float* x      = (const float*)d_in[0];
    const float* norm_g = (const float*)d_in[1];
    const float* norm_b = (const float*)d_in[2];
    const float* W1     = (const float*)d_in[3];
    const float* b1     = (const float*)d_in[4];
    const float* qn_g   = (const float*)d_in[5];
    const float* qn_b   = (const float*)d_in[6];
    const float* kn_g   = (const float*)d_in[7];
    const float* kn_b   = (const float*)d_in[8];
    const float* Wao    = (const float*)d_in[9];
    const float* bao    = (const float*)d_in[10];
    const float* Wmo    = (const float*)d_in[11];
    const float* bmo    = (const float*)d_in[12];
    const float* W2     = (const float*)d_in[13];
    const float* b2     = (const float*)d_in[14];
    float*       out    = (float*)d_out;

    float *norm, *fused, *attn, *comb, *w1t, *waot, *wmot, *w2t;
    cudaGetSymbolAddress((void**)&norm,  g_norm);
    cudaGetSymbolAddress((void**)&fused, g_fused);
    cudaGetSymbolAddress((void**)&attn,  g_attn);
    cudaGetSymbolAddress((void**)&comb,  g_comb);
    cudaGetSymbolAddress((void**)&w1t,   g_w1t);
    cudaGetSymbolAddress((void**)&waot,  g_waot);
    cudaGetSymbolAddress((void**)&wmot,  g_wmot);
    cudaGetSymbolAddress((void**)&w2t,   g_w2t);

    cudaFuncSetAttribute(mma_gemm, cudaFuncAttributeMaxDynamicSharedMemorySize, GEMM_SMEM);

    dim3 tblk(32, 8);
    // weight transposes (K-major, zero-padded)
    transpose_kernel<<<dim3(FWP / 32, DIMC / 32), tblk>>>(W1, DIMC, FW, w1t, DIMC, FWP);
    transpose_kernel<<<dim3(DIMC / 32, DIMC / 32), tblk>>>(Wao, DIMC, DIMC, waot, DIMC, DIMC);
    transpose_kernel<<<dim3(DIMC / 32, KHPAD / 32), tblk>>>(Wmo, MLPHID, DIMC, wmot, KHPAD, DIMC);
    transpose_kernel<<<dim3(DIMC / 32, 2 * DIMC / 32), tblk>>>(W2, 2 * DIMC, DIMC, w2t, 2 * DIMC, DIMC);

    // 1) layernorm(x)
    ln_kernel<<<NTOK, 256>>>(x, norm_g, norm_b, norm);

    // 2) fused = norm @ W1 + b1   [4096 x 3840(pad)]
    mma_gemm<<<dim3(FWP / 128, NTOK / 128), 256, GEMM_SMEM>>>(
        norm, DIMC, w1t, DIMC, fused, FWP, b1, FW, nullptr, 0, DIMC);

    // 3) per-head LN on q/k
    qkln_kernel<<<(NTOK * 32) / 8, 256>>>(fused, qn_g, qn_b, kn_g, kn_b);

    // 4) gelu on mlp hidden
    gelu_kernel<<<dim3((MLPHID + 255) / 256, NTOK), 256>>>(fused);

    // 5) attention
    attn_kernel<<<dim3(NSEQ / 128, NHEADS, 2), 128>>>(fused, attn);

    // 6) attn_out -> comb[:, :1024]
    mma_gemm<<<dim3(DIMC / 128, NTOK / 128), 256, GEMM_SMEM>>>(
        attn, DIMC, waot, DIMC, comb, 2 * DIMC, bao, DIMC, nullptr, 0, DIMC);

    // 7) mlp_out -> comb[:, 1024:]
    mma_gemm<<<dim3(DIMC / 128, NTOK / 128), 256, GEMM_SMEM>>>(
        fused + 3 * DIMC, FWP, wmot, KHPAD, comb + DIMC, 2 * DIMC,
        bmo, DIMC, nullptr, 0, KHPAD);

    // 8) out = x + comb @ W2 + b2
    mma_gemm<<<dim3(DIMC / 128, NTOK / 128), 256, GEMM_SMEM>>>(
        comb, 2 * DIMC, w2t, 2 * DIMC, out, DIMC, b2, DIMC, x, DIMC, 2 * DIMC);
}

// round 4
// speedup vs baseline: 3.4320x; 1.9203x over previous
#include <cuda_runtime.h>
#include <math.h>
#include <stdint.h>

// ---------------- problem constants ----------------
#define NTOK   4096              // B*N = 2*2048
#define DIMC   1024
#define NHEADS 16
#define DHEAD  64
#define MLPHID 716
#define FW     3788              // 3*DIM + MLP_HID (true width)
#define FWP    3840              // padded to 30*128
#define KHPAD  736               // MLPHID padded to mult of 32
#define NSEQ   2048
#define LN_EPS 1e-6f

// ---------------- scratch (static device globals) ------
__device__ float g_norm [NTOK * DIMC];
__device__ float g_fused[NTOK * FWP];
__device__ float g_attn [NTOK * DIMC];
__device__ float g_comb [NTOK * 2 * DIMC];
__device__ float g_w1t  [FWP  * DIMC];        // [N=3840][K=1024]
__device__ float g_waot [DIMC * DIMC];
__device__ float g_wmot [DIMC * KHPAD];
__device__ float g_w2t  [DIMC * 2 * DIMC];

// ================= helpers =================
__device__ __forceinline__ uint32_t tf32cvt(float x) {
    uint32_t u;
    asm("cvt.rna.tf32.f32 %0, %1;" : "=r"(u) : "f"(x));
    return u;
}

__device__ __forceinline__ void mma_tf32(float& d0, float& d1, float& d2, float& d3,
                                         uint32_t a0, uint32_t a1, uint32_t a2, uint32_t a3,
                                         uint32_t b0, uint32_t b1)
{
    asm volatile(
        "mma.sync.aligned.m16n8k8.row.col.f32.tf32.tf32.f32 "
        "{%0,%1,%2,%3}, {%4,%5,%6,%7}, {%8,%9}, {%0,%1,%2,%3};"
        : "+f"(d0), "+f"(d1), "+f"(d2), "+f"(d3)
        : "r"(a0), "r"(a1), "r"(a2), "r"(a3), "r"(b0), "r"(b1));
}

// ============================================================
// weight transpose: Wt[n][k] = W[k][n], zero-filled to Kpad/Npad
// ============================================================
__global__ void transpose_kernel(const float* __restrict__ W, int K, int N,
                                 float* __restrict__ Wt, int Kpad, int Npad)
{
    __shared__ float t[32][33];
    int n0 = blockIdx.x * 32, k0 = blockIdx.y * 32;
    int tx = threadIdx.x, ty = threadIdx.y;
    #pragma unroll
    for (int i = 0; i < 32; i += 8) {
        int k = k0 + ty + i, n = n0 + tx;
        t[ty + i][tx] = (k < K && n < N) ? W[(size_t)k * N + n] : 0.f;
    }
    __syncthreads();
    #pragma unroll
    for (int i = 0; i < 32; i += 8) {
        int n = n0 + ty + i, k = k0 + tx;
        if (n < Npad && k < Kpad) Wt[(size_t)n * Kpad + k] = t[tx][ty + i];
    }
}

// ============================================================
// LayerNorm over DIM=1024, one block (256 thr) per row
// ============================================================
__global__ void ln_kernel(const float* __restrict__ x,
                          const float* __restrict__ g,
                          const float* __restrict__ b,
                          float* __restrict__ out)
{
    int row = blockIdx.x;
    int tid = threadIdx.x;
    const float4 v = reinterpret_cast<const float4*>(x + (size_t)row * DIMC)[tid];

    float s  = v.x + v.y + v.z + v.w;
    float sq = v.x*v.x + v.y*v.y + v.z*v.z + v.w*v.w;
    #pragma unroll
    for (int o = 16; o > 0; o >>= 1) {
        s  += __shfl_xor_sync(0xffffffffu, s,  o);
        sq += __shfl_xor_sync(0xffffffffu, sq, o);
    }
    __shared__ float ws[8], wq[8];
    int warp = tid >> 5, lane = tid & 31;
    if (lane == 0) { ws[warp] = s; wq[warp] = sq; }
    __syncthreads();
    if (warp == 0) {
        float s2  = (lane < 8) ? ws[lane] : 0.f;
        float sq2 = (lane < 8) ? wq[lane] : 0.f;
        #pragma unroll
        for (int o = 4; o > 0; o >>= 1) {
            s2  += __shfl_xor_sync(0xffffffffu, s2,  o);
            sq2 += __shfl_xor_sync(0xffffffffu, sq2, o);
        }
        if (lane == 0) { ws[0] = s2; wq[0] = sq2; }
    }
    __syncthreads();
    float mean = ws[0] * (1.f / DIMC);
    float var  = wq[0] * (1.f / DIMC) - mean * mean;
    float rstd = rsqrtf(var + LN_EPS);

    float4 gg = reinterpret_cast<const float4*>(g)[tid];
    float4 bb = reinterpret_cast<const float4*>(b)[tid];
    float4 o4;
    o4.x = (v.x - mean) * rstd * gg.x + bb.x;
    o4.y = (v.y - mean) * rstd * gg.y + bb.y;
    o4.z = (v.z - mean) * rstd * gg.z + bb.z;
    o4.w = (v.w - mean) * rstd * gg.w + bb.w;
    reinterpret_cast<float4*>(out + (size_t)row * DIMC)[tid] = o4;
}

// ============================================================
// tf32 mma.sync GEMM (unchanged from round 3)
// ============================================================
#define SSTR  36
#define ABUF  (128 * SSTR)
#define BUFSZ (2 * ABUF)
#define GEMM_SMEM (2 * BUFSZ * 4)

__global__ void __launch_bounds__(256, 2)
mma_gemm(const float* __restrict__ A, int lda,
         const float* __restrict__ Bt, int ldb,
         float* __restrict__ C, int ldc,
         const float* __restrict__ bias, int nbias,
         const float* __restrict__ resid, int ldr,
         int K)
{
    extern __shared__ float sm[];
    int tid  = threadIdx.x;
    int wid  = tid >> 5, lane = tid & 31;
    int gid2 = lane >> 2, tig = lane & 3;
    int bm = blockIdx.y * 128, bn = blockIdx.x * 128;
    int wm = (wid & 1) * 64, wn = (wid >> 1) * 32;

    float acc[4][4][4];
    #pragma unroll
    for (int i = 0; i < 4; i++)
        #pragma unroll
        for (int j = 0; j < 4; j++)
            #pragma unroll
            for (int r = 0; r < 4; r++) acc[i][j][r] = 0.f;

    int lr = tid >> 3;
    int lc = (tid & 7) * 4;

    auto load_buf = [&](int k0, int b) {
        float* sA = sm + b * BUFSZ;
        float* sB = sA + ABUF;
        #pragma unroll
        for (int i = 0; i < 4; i++) {
            int r = i * 32 + lr;
            float4 va = *reinterpret_cast<const float4*>(
                A + (size_t)(bm + r) * lda + k0 + lc);
            uint4 ua;
            ua.x = tf32cvt(va.x); ua.y = tf32cvt(va.y);
            ua.z = tf32cvt(va.z); ua.w = tf32cvt(va.w);
            *reinterpret_cast<uint4*>(sA + r * SSTR + lc) = ua;

            float4 vb = *reinterpret_cast<const float4*>(
                Bt + (size_t)(bn + r) * ldb + k0 + lc);
            uint4 ub;
            ub.x = tf32cvt(vb.x); ub.y = tf32cvt(vb.y);
            ub.z = tf32cvt(vb.z); ub.w = tf32cvt(vb.w);
            *reinterpret_cast<uint4*>(sB + r * SSTR + lc) = ub;
        }
    };

    const int nk = K >> 5;
    load_buf(0, 0);
    __syncthreads();

    for (int it = 0; it < nk; it++) {
        int b = it & 1;
        const uint32_t* sA = reinterpret_cast<const uint32_t*>(sm + b * BUFSZ);
        const uint32_t* sB = sA + ABUF;

        #pragma unroll
        for (int kk = 0; kk < 4; kk++) {
            int k8 = kk * 8;
            uint32_t af[4][4], bf[4][2];
            #pragma unroll
            for (int mt = 0; mt < 4; mt++) {
                int row = wm + mt * 16 + gid2;
                af[mt][0] = sA[(row    ) * SSTR + k8 + tig    ];
                af[mt][1] = sA[(row + 8) * SSTR + k8 + tig    ];
                af[mt][2] = sA[(row    ) * SSTR + k8 + tig + 4];
                af[mt][3] = sA[(row + 8) * SSTR + k8 + tig + 4];
            }
            #pragma unroll
            for (int nt = 0; nt < 4; nt++) {
                int col = wn + nt * 8 + gid2;
                bf[nt][0] = sB[col * SSTR + k8 + tig    ];
                bf[nt][1] = sB[col * SSTR + k8 + tig + 4];
            }
            #pragma unroll
            for (int mt = 0; mt < 4; mt++)
                #pragma unroll
                for (int nt = 0; nt < 4; nt++)
                    mma_tf32(acc[mt][nt][0], acc[mt][nt][1],
                             acc[mt][nt][2], acc[mt][nt][3],
                             af[mt][0], af[mt][1], af[mt][2], af[mt][3],
                             bf[nt][0], bf[nt][1]);
        }
        __syncthreads();
        if (it + 1 < nk) {
            load_buf((it + 1) << 5, b ^ 1);
            __syncthreads();
        }
    }

    #pragma unroll
    for (int mt = 0; mt < 4; mt++) {
        int r0 = bm + wm + mt * 16 + gid2;
        #pragma unroll
        for (int nt = 0; nt < 4; nt++) {
            int c = bn + wn + nt * 8 + tig * 2;
            float2 v0 = make_float2(acc[mt][nt][0], acc[mt][nt][1]);
            float2 v1 = make_float2(acc[mt][nt][2], acc[mt][nt][3]);
            if (bias) {
                float bx = (c     < nbias) ? bias[c]     : 0.f;
                float by = (c + 1 < nbias) ? bias[c + 1] : 0.f;
                v0.x += bx; v0.y += by;
                v1.x += bx; v1.y += by;
            }
            if (resid) {
                float2 ra = *reinterpret_cast<const float2*>(resid + (size_t)r0 * ldr + c);
                float2 rb = *reinterpret_cast<const float2*>(resid + (size_t)(r0 + 8) * ldr + c);
                v0.x += ra.x; v0.y += ra.y;
                v1.x += rb.x; v1.y += rb.y;
            }
            *reinterpret_cast<float2*>(C + (size_t)r0 * ldc + c) = v0;
            *reinterpret_cast<float2*>(C + (size_t)(r0 + 8) * ldc + c) = v1;
        }
    }
}

// ============================================================
// Per-head Q/K layernorm over DHEAD=64 (padded fused stride)
// ============================================================
__global__ void qkln_kernel(float* __restrict__ fused,
                            const float* __restrict__ qg, const float* __restrict__ qb,
                            const float* __restrict__ kg, const float* __restrict__ kb)
{
    int gid   = blockIdx.x * 8 + (threadIdx.x >> 5);
    int lane  = threadIdx.x & 31;
    int token = gid >> 5;
    int rem   = gid & 31;
    int qk    = rem >> 4;
    int head  = rem & 15;

    float* p = fused + (size_t)token * FWP + qk * DIMC + head * DHEAD;
    float v0 = p[lane];
    float v1 = p[lane + 32];

    float s = v0 + v1;
    #pragma unroll
    for (int o = 16; o > 0; o >>= 1) s += __shfl_xor_sync(0xffffffffu, s, o);
    float mean = s * (1.f / 64.f);

    float d0 = v0 - mean, d1 = v1 - mean;
    float sq = d0 * d0 + d1 * d1;
    #pragma unroll
    for (int o = 16; o > 0; o >>= 1) sq += __shfl_xor_sync(0xffffffffu, sq, o);
    float rstd = rsqrtf(sq * (1.f / 64.f) + LN_EPS);

    const float* g = qk ? kg : qg;
    const float* b = qk ? kb : qb;
    p[lane]      = d0 * rstd * g[lane]      + b[lane];
    p[lane + 32] = d1 * rstd * g[lane + 32] + b[lane + 32];
}

// ============================================================
// GELU (tanh approx) in place on mlp_hidden slice
// ============================================================
__global__ void gelu_kernel(float* __restrict__ fused)
{
    int j = blockIdx.x * 256 + threadIdx.x;
    if (j < MLPHID) {
        float* p = fused + (size_t)blockIdx.y * FWP + 3 * DIMC + j;
        float x = *p;
        float u = 0.7978845608028654f * (x + 0.044715f * x * x * x);
        *p = 0.5f * x * (1.f + tanhf(u));
    }
}

// ============================================================
// Flash attention with tf32 mma.sync.
// CTA: 128 queries x (batch, head). 8 warps, 16 query rows each.
// Q persistent in A-fragments; K/V 64-row tiles in SMEM;
// P routed through per-warp SMEM patch for layout conversion.
// ============================================================
#define KSTR 68
#define ATTN_SMEM ((2 * 64 * KSTR + 8 * 16 * KSTR) * 4)   // 69632 B

__global__ void __launch_bounds__(256, 2)
fattn_kernel(const float* __restrict__ fused, float* __restrict__ aout)
{
    extern __shared__ float sm[];
    float* sK = sm;                       // [64][68]
    float* sV = sm + 64 * KSTR;           // [64][68]

    int tid  = threadIdx.x;
    int wid  = tid >> 5, lane = tid & 31;
    int quad = lane >> 2, tiq = lane & 3;
    int h  = blockIdx.y;
    int bb = blockIdx.z;
    int q0 = blockIdx.x * 128;            // CTA query base
    int tq0 = bb * NSEQ + q0;
    int kvb = bb * NSEQ;

    float* sP = sm + 2 * 64 * KSTR + wid * 16 * KSTR;   // per-warp [16][68]

    // ---- stage Q tile (128 x 64) into sm[0 .. 128*KSTR), scaled + tf32 ----
    {
        // 128 rows x 16 float4 = 2048 float4; 8 per thread
        #pragma unroll
        for (int i = 0; i < 8; i++) {
            int idx = i * 256 + tid;
            int r = idx >> 4, c4 = (idx & 15) * 4;
            float4 v = *reinterpret_cast<const float4*>(
                fused + (size_t)(tq0 + r) * FWP + h * DHEAD + c4);
            uint4 u;
            u.x = tf32cvt(v.x * 0.125f); u.y = tf32cvt(v.y * 0.125f);
            u.z = tf32cvt(v.z * 0.125f); u.w = tf32cvt(v.w * 0.125f);
            *reinterpret_cast<uint4*>(sm + r * KSTR + c4) = u;
        }
    }
    __syncthreads();

    // ---- load Q fragments (persistent) ----
    uint32_t qf[8][4];
    {
        const uint32_t* sQ = reinterpret_cast<const uint32_t*>(sm);
        int r0 = wid * 16 + quad;
        #pragma unroll
        for (int kc = 0; kc < 8; kc++) {
            int c = kc * 8 + tiq;
            qf[kc][0] = sQ[(r0    ) * KSTR + c    ];
            qf[kc][1] = sQ[(r0 + 8) * KSTR + c    ];
            qf[kc][2] = sQ[(r0    ) * KSTR + c + 4];
            qf[kc][3] = sQ[(r0 + 8) * KSTR + c + 4];
        }
    }

    float o[8][4];
    #pragma unroll
    for (int i = 0; i < 8; i++)
        #pragma unroll
        for (int j = 0; j < 4; j++) o[i][j] = 0.f;
    float m0 = -1e30f, m1 = -1e30f, l0 = 0.f, l1 = 0.f;

    const uint32_t* uK = reinterpret_cast<const uint32_t*>(sK);
    const uint32_t* uV = reinterpret_cast<const uint32_t*>(sV);
    const uint32_t* uP = reinterpret_cast<const uint32_t*>(sP);

    for (int kt = 0; kt < NSEQ; kt += 64) {
        __syncthreads();   // prior tile fully consumed
        // ---- load K/V tile: 64 rows x 16 float4 each; 4 per thread per mat --
        #pragma unroll
        for (int i = 0; i < 4; i++) {
            int idx = i * 256 + tid;
            int r = idx >> 4, c4 = (idx & 15) * 4;
            const float* base = fused + (size_t)(kvb + kt + r) * FWP + h * DHEAD + c4;
            float4 kv = *reinterpret_cast<const float4*>(base + DIMC);
            uint4 uk;
            uk.x = tf32cvt(kv.x); uk.y = tf32cvt(kv.y);
            uk.z = tf32cvt(kv.z); uk.w = tf32cvt(kv.w);
            *reinterpret_cast<uint4*>(sK + r * KSTR + c4) = uk;
            float4 vv = *reinterpret_cast<const float4*>(base + 2 * DIMC);
            uint4 uv;
            uv.x = tf32cvt(vv.x); uv.y = tf32cvt(vv.y);
            uv.z = tf32cvt(vv.z); uv.w = tf32cvt(vv.w);
            *reinterpret_cast<uint4*>(sV + r * KSTR + c4) = uv;
        }
        __syncthreads();

        // ---- scores S = Q @ K^T : 8 nfrags x 8 kchunks ----
        float sc[8][4];
        #pragma unroll
        for (int i = 0; i < 8; i++)
            #pragma unroll
            for (int j = 0; j < 4; j++) sc[i][j] = 0.f;

        #pragma unroll
        for (int kc = 0; kc < 8; kc++) {
            int k8 = kc * 8 + tiq;
            #pragma unroll
            for (int nf = 0; nf < 8; nf++) {
                uint32_t b0 = uK[(nf * 8 + quad) * KSTR + k8    ];
                uint32_t b1 = uK[(nf * 8 + quad) * KSTR + k8 + 4];
                mma_tf32(sc[nf][0], sc[nf][1], sc[nf][2], sc[nf][3],
                         qf[kc][0], qf[kc][1], qf[kc][2], qf[kc][3], b0, b1);
            }
        }

        // ---- online softmax (rows quad, quad+8; stats within lane quad) ----
        float rm0 = -1e30f, rm1 = -1e30f;
        #pragma unroll
        for (int nf = 0; nf < 8; nf++) {
            rm0 = fmaxf(rm0, fmaxf(sc[nf][0], sc[nf][1]));
            rm1 = fmaxf(rm1, fmaxf(sc[nf][2], sc[nf][3]));
        }
        rm0 = fmaxf(rm0, __shfl_xor_sync(0xffffffffu, rm0, 1));
        rm0 = fmaxf(rm0, __shfl_xor_sync(0xffffffffu, rm0, 2));
        rm1 = fmaxf(rm1, __shfl_xor_sync(0xffffffffu, rm1, 1));
        rm1 = fmaxf(rm1, __shfl_xor_sync(0xffffffffu, rm1, 2));

        float mn0 = fmaxf(m0, rm0), mn1 = fmaxf(m1, rm1);
        float c0 = __expf(m0 - mn0), c1 = __expf(m1 - mn1);
        m0 = mn0; m1 = mn1;

        float rs0 = 0.f, rs1 = 0.f;
        #pragma unroll
        for (int nf = 0; nf < 8; nf++) {
            float p0 = __expf(sc[nf][0] - m0);
            float p1 = __expf(sc[nf][1] - m0);
            float p2 = __expf(sc[nf][2] - m1);
            float p3 = __expf(sc[nf][3] - m1);
            rs0 += p0 + p1; rs1 += p2 + p3;
            // store P (accumulator layout) to per-warp patch
            int cb = nf * 8 + tiq * 2;
            sP[(quad    ) * KSTR + cb    ] = __uint_as_float(tf32cvt(p0));
            sP[(quad    ) * KSTR + cb + 1] = __uint_as_float(tf32cvt(p1));
            sP[(quad + 8) * KSTR + cb    ] = __uint_as_float(tf32cvt(p2));
            sP[(quad + 8) * KSTR + cb + 1] = __uint_as_float(tf32cvt(p3));
        }
        rs0 += __shfl_xor_sync(0xffffffffu, rs0, 1);
        rs0 += __shfl_xor_sync(0xffffffffu, rs0, 2);
        rs1 += __shfl_xor_sync(0xffffffffu, rs1, 1);
        rs1 += __shfl_xor_sync(0xffffffffu, rs1, 2);
        l0 = l0 * c0 + rs0;
        l1 = l1 * c1 + rs1;

        // rescale existing O
        #pragma unroll
        for (int nf = 0; nf < 8; nf++) {
            o[nf][0] *= c0; o[nf][1] *= c0;
            o[nf][2] *= c1; o[nf][3] *= c1;
        }
        __syncwarp();

        // ---- O += P @ V : A-frags from sP, B-frags from sV ----
        #pragma unroll
        for (int kc = 0; kc < 8; kc++) {
            int k = kc * 8 + tiq;
            uint32_t a0 = uP[(quad    ) * KSTR + k    ];
            uint32_t a1 = uP[(quad + 8) * KSTR + k    ];
            uint32_t a2 = uP[(quad    ) * KSTR + k + 4];
            uint32_t a3 = uP[(quad + 8) * KSTR + k + 4];
            #pragma unroll
            for (int nf = 0; nf < 8; nf++) {
                uint32_t b0 = uV[(k    ) * KSTR + nf * 8 + quad];
                uint32_t b1 = uV[(k + 4) * KSTR + nf * 8 + quad];
                mma_tf32(o[nf][0], o[nf][1], o[nf][2], o[nf][3],
                         a0, a1, a2, a3, b0, b1);
            }
        }
        __syncwarp();
    }

    // ---- normalize and write out ----
    float il0 = 1.f / l0, il1 = 1.f / l1;
    int r0 = tq0 + wid * 16 + quad;
    #pragma unroll
    for (int nf = 0; nf < 8; nf++) {
        int c = h * DHEAD + nf * 8 + tiq * 2;
        *reinterpret_cast<float2*>(aout + (size_t)r0 * DIMC + c) =
            make_float2(o[nf][0] * il0, o[nf][1] * il0);
        *reinterpret_cast<float2*>(aout + (size_t)(r0 + 8) * DIMC + c) =
            make_float2(o[nf][2] * il1, o[nf][3] * il1);
    }
}

// ============================================================
// launch
// ============================================================
extern "C" void kernel_launch(void* const* d_in, const int* in_sizes, int n_in,
                              void* d_out, int out_size)
{
    const float* x      = (const float*)d_in[0];
    const float* norm_g = (const float*)d_in[1];
    const float* norm_b = (const float*)d_in[2];
    const float* W1     = (const float*)d_in[3];
    const float* b1     = (const float*)d_in[4];
    const float* qn_g   = (const float*)d_in[5];
    const float* qn_b   = (const float*)d_in[6];
    const float* kn_g   = (const float*)d_in[7];
    const float* kn_b   = (const float*)d_in[8];
    const float* Wao    = (const float*)d_in[9];
    const float* bao    = (const float*)d_in[10];
    const float* Wmo    = (const float*)d_in[11];
    const float* bmo    = (const float*)d_in[12];
    const float* W2     = (const float*)d_in[13];
    const float* b2     = (const float*)d_in[14];
    float*       out    = (float*)d_out;

    float *norm, *fused, *attn, *comb, *w1t, *waot, *wmot, *w2t;
    cudaGetSymbolAddress((void**)&norm,  g_norm);
    cudaGetSymbolAddress((void**)&fused, g_fused);
    cudaGetSymbolAddress((void**)&attn,  g_attn);
    cudaGetSymbolAddress((void**)&comb,  g_comb);
    cudaGetSymbolAddress((void**)&w1t,   g_w1t);
    cudaGetSymbolAddress((void**)&waot,  g_waot);
    cudaGetSymbolAddress((void**)&wmot,  g_wmot);
    cudaGetSymbolAddress((void**)&w2t,   g_w2t);

    cudaFuncSetAttribute(mma_gemm, cudaFuncAttributeMaxDynamicSharedMemorySize, GEMM_SMEM);
    cudaFuncSetAttribute(fattn_kernel, cudaFuncAttributeMaxDynamicSharedMemorySize, ATTN_SMEM);

    dim3 tblk(32, 8);
    transpose_kernel<<<dim3(FWP / 32, DIMC / 32), tblk>>>(W1, DIMC, FW, w1t, DIMC, FWP);
    transpose_kernel<<<dim3(DIMC / 32, DIMC / 32), tblk>>>(Wao, DIMC, DIMC, waot, DIMC, DIMC);
    transpose_kernel<<<dim3(DIMC / 32, KHPAD / 32), tblk>>>(Wmo, MLPHID, DIMC, wmot, KHPAD, DIMC);
    transpose_kernel<<<dim3(DIMC / 32, 2 * DIMC / 32), tblk>>>(W2, 2 * DIMC, DIMC, w2t, 2 * DIMC, DIMC);

    // 1) layernorm(x)
    ln_kernel<<<NTOK, 256>>>(x, norm_g, norm_b, norm);

    // 2) fused = norm @ W1 + b1   [4096 x 3840(pad)]
    mma_gemm<<<dim3(FWP / 128, NTOK / 128), 256, GEMM_SMEM>>>(
        norm, DIMC, w1t, DIMC, fused, FWP, b1, FW, nullptr, 0, DIMC);

    // 3) per-head LN on q/k
    qkln_kernel<<<(NTOK * 32) / 8, 256>>>(fused, qn_g, qn_b, kn_g, kn_b);

    // 4) gelu on mlp hidden
    gelu_kernel<<<dim3((MLPHID + 255) / 256, NTOK), 256>>>(fused);

    // 5) flash attention (tensor cores)
    fattn_kernel<<<dim3(NSEQ / 128, NHEADS, 2), 256, ATTN_SMEM>>>(fused, attn);

    // 6) attn_out -> comb[:, :1024]
    mma_gemm<<<dim3(DIMC / 128, NTOK / 128), 256, GEMM_SMEM>>>(
        attn, DIMC, waot, DIMC, comb, 2 * DIMC, bao, DIMC, nullptr, 0, DIMC);

    // 7) mlp_out -> comb[:, 1024:]
    mma_gemm<<<dim3(DIMC / 128, NTOK / 128), 256, GEMM_SMEM>>>(
        fused + 3 * DIMC, FWP, wmot, KHPAD, comb + DIMC, 2 * DIMC,
        bmo, DIMC, nullptr, 0, KHPAD);

    // 8) out = x + comb @ W2 + b2
    mma_gemm<<<dim3(DIMC / 128, NTOK / 128), 256, GEMM_SMEM>>>(
        comb, 2 * DIMC, w2t, 2 * DIMC, out, DIMC, b2, DIMC, x, DIMC, 2 * DIMC);
}

// round 5
// speedup vs baseline: 3.6036x; 1.0500x over previous
#include <cuda_runtime.h>
#include <math.h>
#include <stdint.h>

// ---------------- problem constants ----------------
#define NTOK   4096              // B*N = 2*2048
#define DIMC   1024
#define NHEADS 16
#define DHEAD  64
#define MLPHID 716
#define FW     3788              // 3*DIM + MLP_HID (true width)
#define FWP    3840              // padded to 30*128
#define HIDPAD 768               // MLPHID padded for fold GEMM tiles
#define KHID   736               // K used in apply_m (mult of 32, >= 716)
#define NSEQ   2048
#define LN_EPS 1e-6f

// ---------------- scratch (static device globals) ------
__device__ float g_norm [NTOK * DIMC];        // LN output (tf32-rounded)
__device__ float g_fused[NTOK * FWP];         // qkv | gelu(hidden)
__device__ float g_attn [NTOK * DIMC];        // attention out (tf32-rounded)
__device__ float g_w1t  [FWP  * DIMC];        // W1^T, tf32
__device__ float g_w2t  [DIMC * 2 * DIMC];    // W2^T, tf32
__device__ float g_waor [DIMC * DIMC];        // Wao rounded (row-major)
__device__ float g_wmor [HIDPAD * DIMC];      // Wmo rounded, row-padded
__device__ float g_wfa  [DIMC * DIMC];        // folded attn weight (Bt form)
__device__ float g_wfm  [DIMC * HIDPAD];      // folded mlp weight (Bt form)
__device__ float g_beff [DIMC];               // folded bias

// ================= helpers =================
__device__ __forceinline__ uint32_t tf32cvt(float x) {
    uint32_t u;
    asm("cvt.rna.tf32.f32 %0, %1;" : "=r"(u) : "f"(x));
    return u;
}
__device__ __forceinline__ float tf32r(float x) {
    return __uint_as_float(tf32cvt(x));
}
__device__ __forceinline__ uint32_t smem_u32(const void* p) {
    uint32_t a;
    asm("{ .reg .u64 t; cvta.to.shared.u64 t, %1; cvt.u32.u64 %0, t; }" : "=r"(a) : "l"(p));
    return a;
}
__device__ __forceinline__ void mma_tf32(float& d0, float& d1, float& d2, float& d3,
                                         uint32_t a0, uint32_t a1, uint32_t a2, uint32_t a3,
                                         uint32_t b0, uint32_t b1)
{
    asm volatile(
        "mma.sync.aligned.m16n8k8.row.col.f32.tf32.tf32.f32 "
        "{%0,%1,%2,%3}, {%4,%5,%6,%7}, {%8,%9}, {%0,%1,%2,%3};"
        : "+f"(d0), "+f"(d1), "+f"(d2), "+f"(d3)
        : "r"(a0), "r"(a1), "r"(a2), "r"(a3), "r"(b0), "r"(b1));
}
__device__ __forceinline__ float gelu1(float x) {
    float u = 0.7978845608028654f * (x + 0.044715f * x * x * x);
    return 0.5f * x * (1.f + tanhf(u));
}

// ============================================================
// weight transpose + tf32 round: Wt[n][k] = tf32(W[k][n])
// ============================================================
__global__ void transpose_kernel(const float* __restrict__ W, int K, int N,
                                 float* __restrict__ Wt, int Kpad, int Npad)
{
    __shared__ float t[32][33];
    int n0 = blockIdx.x * 32, k0 = blockIdx.y * 32;
    int tx = threadIdx.x, ty = threadIdx.y;
    #pragma unroll
    for (int i = 0; i < 32; i += 8) {
        int k = k0 + ty + i, n = n0 + tx;
        t[ty + i][tx] = (k < K && n < N) ? tf32r(W[(size_t)k * N + n]) : 0.f;
    }
    __syncthreads();
    #pragma unroll
    for (int i = 0; i < 32; i += 8) {
        int n = n0 + ty + i, k = k0 + tx;
        if (n < Npad && k < Kpad) Wt[(size_t)n * Kpad + k] = t[tx][ty + i];
    }
}

// ============================================================
// round-copy with row padding: out[r][c] = tf32(W[r][c]) (zeros for r>=rows)
// cols = 1024, grid covers rowspad*cols/256
// ============================================================
__global__ void roundcopy_kernel(const float* __restrict__ W, int rows,
                                 float* __restrict__ out)
{
    int idx = blockIdx.x * 256 + threadIdx.x;
    int r = idx >> 10;
    float v = (r < rows) ? tf32r(W[idx - ((idx >> 10) - r) * 0 + 0 * idx]) : 0.f;
    // simpler: recompute index
    v = (r < rows) ? tf32r(W[(size_t)r * DIMC + (idx & 1023)]) : 0.f;
    out[idx] = v;
}

// ============================================================
// folded bias: beff[n] = b2[n] + sum_k bao[k] W2[k][n] + sum_k bmo[k] W2[1024+k][n]
// ============================================================
__global__ void beff_kernel(const float* __restrict__ bao,
                            const float* __restrict__ bmo,
                            const float* __restrict__ b2,
                            const float* __restrict__ W2,
                            float* __restrict__ beff)
{
    int n = blockIdx.x * 256 + threadIdx.x;
    float s = b2[n];
    for (int k = 0; k < DIMC; k++)
        s += bao[k] * W2[(size_t)k * DIMC + n];
    for (int k = 0; k < MLPHID; k++)
        s += bmo[k] * W2[(size_t)(DIMC + k) * DIMC + n];
    beff[n] = s;
}

// ============================================================
// LayerNorm over DIM=1024, tf32-rounded output
// ============================================================
__global__ void ln_kernel(const float* __restrict__ x,
                          const float* __restrict__ g,
                          const float* __restrict__ b,
                          float* __restrict__ out)
{
    int row = blockIdx.x;
    int tid = threadIdx.x;
    const float4 v = reinterpret_cast<const float4*>(x + (size_t)row * DIMC)[tid];

    float s  = v.x + v.y + v.z + v.w;
    float sq = v.x*v.x + v.y*v.y + v.z*v.z + v.w*v.w;
    #pragma unroll
    for (int o = 16; o > 0; o >>= 1) {
        s  += __shfl_xor_sync(0xffffffffu, s,  o);
        sq += __shfl_xor_sync(0xffffffffu, sq, o);
    }
    __shared__ float ws[8], wq[8];
    int warp = tid >> 5, lane = tid & 31;
    if (lane == 0) { ws[warp] = s; wq[warp] = sq; }
    __syncthreads();
    if (warp == 0) {
        float s2  = (lane < 8) ? ws[lane] : 0.f;
        float sq2 = (lane < 8) ? wq[lane] : 0.f;
        #pragma unroll
        for (int o = 4; o > 0; o >>= 1) {
            s2  += __shfl_xor_sync(0xffffffffu, s2,  o);
            sq2 += __shfl_xor_sync(0xffffffffu, sq2, o);
        }
        if (lane == 0) { ws[0] = s2; wq[0] = sq2; }
    }
    __syncthreads();
    float mean = ws[0] * (1.f / DIMC);
    float var  = wq[0] * (1.f / DIMC) - mean * mean;
    float rstd = rsqrtf(var + LN_EPS);

    float4 gg = reinterpret_cast<const float4*>(g)[tid];
    float4 bb = reinterpret_cast<const float4*>(b)[tid];
    float4 o4;
    o4.x = tf32r((v.x - mean) * rstd * gg.x + bb.x);
    o4.y = tf32r((v.y - mean) * rstd * gg.y + bb.y);
    o4.z = tf32r((v.z - mean) * rstd * gg.z + bb.z);
    o4.w = tf32r((v.w - mean) * rstd * gg.w + bb.w);
    reinterpret_cast<float4*>(out + (size_t)row * DIMC)[tid] = o4;
}

// ============================================================
// tf32 mma.sync GEMM with cp.async double-buffered pipeline.
// C[M,N] = A[M,K] @ Bt[N,K]^T (+bias)(+resid)(gelu/round epilogue)
// 128x128 CTA tile, BK=32, 256 thr, 8 warps of 64x32.
// Inputs A, Bt must already be tf32-rounded.
// ============================================================
#define SSTR  36
#define ABUF  (128 * SSTR)
#define BUFSZ (2 * ABUF)
#define GEMM_SMEM (2 * BUFSZ * 4)

__global__ void __launch_bounds__(256, 2)
mma_gemm(const float* __restrict__ A, int lda,
         const float* __restrict__ Bt, int ldb,
         float* __restrict__ C, int ldc,
         const float* __restrict__ bias, int nbias,
         const float* __restrict__ resid, int ldr,
         int K, int gelu_from, int round_all)
{
    extern __shared__ float sm[];
    uint32_t sbase = smem_u32(sm);
    int tid  = threadIdx.x;
    int wid  = tid >> 5, lane = tid & 31;
    int gid2 = lane >> 2, tig = lane & 3;
    int bm = blockIdx.y * 128, bn = blockIdx.x * 128;
    int wm = (wid & 1) * 64, wn = (wid >> 1) * 32;

    float acc[4][4][4];
    #pragma unroll
    for (int i = 0; i < 4; i++)
        #pragma unroll
        for (int j = 0; j < 4; j++)
            #pragma unroll
            for (int r = 0; r < 4; r++) acc[i][j][r] = 0.f;

    int lr = tid >> 3;                // 0..31
    int lc = (tid & 7) * 4;           // 0..28

    auto prefetch = [&](int k0, int b) {
        uint32_t dA = sbase + (uint32_t)b * BUFSZ * 4;
        uint32_t dB = dA + ABUF * 4;
        #pragma unroll
        for (int i = 0; i < 4; i++) {
            int r = i * 32 + lr;
            uint32_t oa = dA + (uint32_t)(r * SSTR + lc) * 4;
            const float* ga = A + (size_t)(bm + r) * lda + k0 + lc;
            asm volatile("cp.async.ca.shared.global [%0], [%1], 16;"
                         :: "r"(oa), "l"(ga) : "memory");
            uint32_t ob = dB + (uint32_t)(r * SSTR + lc) * 4;
            const float* gb = Bt + (size_t)(bn + r) * ldb + k0 + lc;
            asm volatile("cp.async.cg.shared.global [%0], [%1], 16;"
                         :: "r"(ob), "l"(gb) : "memory");
        }
        asm volatile("cp.async.commit_group;" ::: "memory");
    };

    const int nk = K >> 5;
    prefetch(0, 0);

    for (int it = 0; it < nk; it++) {
        if (it + 1 < nk) {
            prefetch((it + 1) << 5, (it + 1) & 1);
            asm volatile("cp.async.wait_group 1;" ::: "memory");
        } else {
            asm volatile("cp.async.wait_group 0;" ::: "memory");
        }
        __syncthreads();

        const uint32_t* sA = reinterpret_cast<const uint32_t*>(sm + (it & 1) * BUFSZ);
        const uint32_t* sB = sA + ABUF;

        #pragma unroll
        for (int kk = 0; kk < 4; kk++) {
            int k8 = kk * 8;
            uint32_t af[4][4], bf[4][2];
            #pragma unroll
            for (int mt = 0; mt < 4; mt++) {
                int row = wm + mt * 16 + gid2;
                af[mt][0] = sA[(row    ) * SSTR + k8 + tig    ];
                af[mt][1] = sA[(row + 8) * SSTR + k8 + tig    ];
                af[mt][2] = sA[(row    ) * SSTR + k8 + tig + 4];
                af[mt][3] = sA[(row + 8) * SSTR + k8 + tig + 4];
            }
            #pragma unroll
            for (int nt = 0; nt < 4; nt++) {
                int col = wn + nt * 8 + gid2;
                bf[nt][0] = sB[col * SSTR + k8 + tig    ];
                bf[nt][1] = sB[col * SSTR + k8 + tig + 4];
            }
            #pragma unroll
            for (int mt = 0; mt < 4; mt++)
                #pragma unroll
                for (int nt = 0; nt < 4; nt++)
                    mma_tf32(acc[mt][nt][0], acc[mt][nt][1],
                             acc[mt][nt][2], acc[mt][nt][3],
                             af[mt][0], af[mt][1], af[mt][2], af[mt][3],
                             bf[nt][0], bf[nt][1]);
        }
        __syncthreads();
    }

    bool do_gelu = (bn >= gelu_from);

    #pragma unroll
    for (int mt = 0; mt < 4; mt++) {
        int r0 = bm + wm + mt * 16 + gid2;
        #pragma unroll
        for (int nt = 0; nt < 4; nt++) {
            int c = bn + wn + nt * 8 + tig * 2;
            float2 v0 = make_float2(acc[mt][nt][0], acc[mt][nt][1]);
            float2 v1 = make_float2(acc[mt][nt][2], acc[mt][nt][3]);
            if (bias) {
                float bx = (c     < nbias) ? bias[c]     : 0.f;
                float by = (c + 1 < nbias) ? bias[c + 1] : 0.f;
                v0.x += bx; v0.y += by;
                v1.x += bx; v1.y += by;
            }
            if (resid) {
                float2 ra = *reinterpret_cast<const float2*>(resid + (size_t)r0 * ldr + c);
                float2 rb = *reinterpret_cast<const float2*>(resid + (size_t)(r0 + 8) * ldr + c);
                v0.x += ra.x; v0.y += ra.y;
                v1.x += rb.x; v1.y += rb.y;
            }
            if (do_gelu) {
                v0.x = tf32r(gelu1(v0.x)); v0.y = tf32r(gelu1(v0.y));
                v1.x = tf32r(gelu1(v1.x)); v1.y = tf32r(gelu1(v1.y));
            } else if (round_all) {
                v0.x = tf32r(v0.x); v0.y = tf32r(v0.y);
                v1.x = tf32r(v1.x); v1.y = tf32r(v1.y);
            }
            *reinterpret_cast<float2*>(C + (size_t)r0 * ldc + c) = v0;
            *reinterpret_cast<float2*>(C + (size_t)(r0 + 8) * ldc + c) = v1;
        }
    }
}

// ============================================================
// Per-head Q/K layernorm over DHEAD=64 (padded fused stride)
// ============================================================
__global__ void qkln_kernel(float* __restrict__ fused,
                            const float* __restrict__ qg, const float* __restrict__ qb,
                            const float* __restrict__ kg, const float* __restrict__ kb)
{
    int gid   = blockIdx.x * 8 + (threadIdx.x >> 5);
    int lane  = threadIdx.x & 31;
    int token = gid >> 5;
    int rem   = gid & 31;
    int qk    = rem >> 4;
    int head  = rem & 15;

    float* p = fused + (size_t)token * FWP + qk * DIMC + head * DHEAD;
    float v0 = p[lane];
    float v1 = p[lane + 32];

    float s = v0 + v1;
    #pragma unroll
    for (int o = 16; o > 0; o >>= 1) s += __shfl_xor_sync(0xffffffffu, s, o);
    float mean = s * (1.f / 64.f);

    float d0 = v0 - mean, d1 = v1 - mean;
    float sq = d0 * d0 + d1 * d1;
    #pragma unroll
    for (int o = 16; o > 0; o >>= 1) sq += __shfl_xor_sync(0xffffffffu, sq, o);
    float rstd = rsqrtf(sq * (1.f / 64.f) + LN_EPS);

    const float* g = qk ? kg : qg;
    const float* b = qk ? kb : qb;
    p[lane]      = d0 * rstd * g[lane]      + b[lane];
    p[lane + 32] = d1 * rstd * g[lane + 32] + b[lane + 32];
}

// ============================================================
// Flash attention with tf32 mma.sync (round-4 design, rounded output)
// ============================================================
#define KSTR 68
#define ATTN_SMEM ((2 * 64 * KSTR + 8 * 16 * KSTR) * 4)

__global__ void __launch_bounds__(256, 2)
fattn_kernel(const float* __restrict__ fused, float* __restrict__ aout)
{
    extern __shared__ float sm[];
    float* sK = sm;
    float* sV = sm + 64 * KSTR;

    int tid  = threadIdx.x;
    int wid  = tid >> 5, lane = tid & 31;
    int quad = lane >> 2, tiq = lane & 3;
    int h  = blockIdx.y;
    int bb = blockIdx.z;
    int q0 = blockIdx.x * 128;
    int tq0 = bb * NSEQ + q0;
    int kvb = bb * NSEQ;

    float* sP = sm + 2 * 64 * KSTR + wid * 16 * KSTR;

    {
        #pragma unroll
        for (int i = 0; i < 8; i++) {
            int idx = i * 256 + tid;
            int r = idx >> 4, c4 = (idx & 15) * 4;
            float4 v = *reinterpret_cast<const float4*>(
                fused + (size_t)(tq0 + r) * FWP + h * DHEAD + c4);
            uint4 u;
            u.x = tf32cvt(v.x * 0.125f); u.y = tf32cvt(v.y * 0.125f);
            u.z = tf32cvt(v.z * 0.125f); u.w = tf32cvt(v.w * 0.125f);
            *reinterpret_cast<uint4*>(sm + r * KSTR + c4) = u;
        }
    }
    __syncthreads();

    uint32_t qf[8][4];
    {
        const uint32_t* sQ = reinterpret_cast<const uint32_t*>(sm);
        int r0 = wid * 16 + quad;
        #pragma unroll
        for (int kc = 0; kc < 8; kc++) {
            int c = kc * 8 + tiq;
            qf[kc][0] = sQ[(r0    ) * KSTR + c    ];
            qf[kc][1] = sQ[(r0 + 8) * KSTR + c    ];
            qf[kc][2] = sQ[(r0    ) * KSTR + c + 4];
            qf[kc][3] = sQ[(r0 + 8) * KSTR + c + 4];
        }
    }

    float o[8][4];
    #pragma unroll
    for (int i = 0; i < 8; i++)
        #pragma unroll
        for (int j = 0; j < 4; j++) o[i][j] = 0.f;
    float m0 = -1e30f, m1 = -1e30f, l0 = 0.f, l1 = 0.f;

    const uint32_t* uK = reinterpret_cast<const uint32_t*>(sK);
    const uint32_t* uV = reinterpret_cast<const uint32_t*>(sV);
    const uint32_t* uP = reinterpret_cast<const uint32_t*>(sP);

    for (int kt = 0; kt < NSEQ; kt += 64) {
        __syncthreads();
        #pragma unroll
        for (int i = 0; i < 4; i++) {
            int idx = i * 256 + tid;
            int r = idx >> 4, c4 = (idx & 15) * 4;
            const float* base = fused + (size_t)(kvb + kt + r) * FWP + h * DHEAD + c4;
            float4 kv = *reinterpret_cast<const float4*>(base + DIMC);
            uint4 uk;
            uk.x = tf32cvt(kv.x); uk.y = tf32cvt(kv.y);
            uk.z = tf32cvt(kv.z); uk.w = tf32cvt(kv.w);
            *reinterpret_cast<uint4*>(sK + r * KSTR + c4) = uk;
            float4 vv = *reinterpret_cast<const float4*>(base + 2 * DIMC);
            uint4 uv;
            uv.x = tf32cvt(vv.x); uv.y = tf32cvt(vv.y);
            uv.z = tf32cvt(vv.z); uv.w = tf32cvt(vv.w);
            *reinterpret_cast<uint4*>(sV + r * KSTR + c4) = uv;
        }
        __syncthreads();

        float sc[8][4];
        #pragma unroll
        for (int i = 0; i < 8; i++)
            #pragma unroll
            for (int j = 0; j < 4; j++) sc[i][j] = 0.f;

        #pragma unroll
        for (int kc = 0; kc < 8; kc++) {
            int k8 = kc * 8 + tiq;
            #pragma unroll
            for (int nf = 0; nf < 8; nf++) {
                uint32_t b0 = uK[(nf * 8 + quad) * KSTR + k8    ];
                uint32_t b1 = uK[(nf * 8 + quad) * KSTR + k8 + 4];
                mma_tf32(sc[nf][0], sc[nf][1], sc[nf][2], sc[nf][3],
                         qf[kc][0], qf[kc][1], qf[kc][2], qf[kc][3], b0, b1);
            }
        }

        float rm0 = -1e30f, rm1 = -1e30f;
        #pragma unroll
        for (int nf = 0; nf < 8; nf++) {
            rm0 = fmaxf(rm0, fmaxf(sc[nf][0], sc[nf][1]));
            rm1 = fmaxf(rm1, fmaxf(sc[nf][2], sc[nf][3]));
        }
        rm0 = fmaxf(rm0, __shfl_xor_sync(0xffffffffu, rm0, 1));
        rm0 = fmaxf(rm0, __shfl_xor_sync(0xffffffffu, rm0, 2));
        rm1 = fmaxf(rm1, __shfl_xor_sync(0xffffffffu, rm1, 1));
        rm1 = fmaxf(rm1, __shfl_xor_sync(0xffffffffu, rm1, 2));

        float mn0 = fmaxf(m0, rm0), mn1 = fmaxf(m1, rm1);
        float c0 = __expf(m0 - mn0), c1 = __expf(m1 - mn1);
        m0 = mn0; m1 = mn1;

        float rs0 = 0.f, rs1 = 0.f;
        #pragma unroll
        for (int nf = 0; nf < 8; nf++) {
            float p0 = __expf(sc[nf][0] - m0);
            float p1 = __expf(sc[nf][1] - m0);
            float p2 = __expf(sc[nf][2] - m1);
            float p3 = __expf(sc[nf][3] - m1);
            rs0 += p0 + p1; rs1 += p2 + p3;
            int cb = nf * 8 + tiq * 2;
            sP[(quad    ) * KSTR + cb    ] = __uint_as_float(tf32cvt(p0));
            sP[(quad    ) * KSTR + cb + 1] = __uint_as_float(tf32cvt(p1));
            sP[(quad + 8) * KSTR + cb    ] = __uint_as_float(tf32cvt(p2));
            sP[(quad + 8) * KSTR + cb + 1] = __uint_as_float(tf32cvt(p3));
        }
        rs0 += __shfl_xor_sync(0xffffffffu, rs0, 1);
        rs0 += __shfl_xor_sync(0xffffffffu, rs0, 2);
        rs1 += __shfl_xor_sync(0xffffffffu, rs1, 1);
        rs1 += __shfl_xor_sync(0xffffffffu, rs1, 2);
        l0 = l0 * c0 + rs0;
        l1 = l1 * c1 + rs1;

        #pragma unroll
        for (int nf = 0; nf < 8; nf++) {
            o[nf][0] *= c0; o[nf][1] *= c0;
            o[nf][2] *= c1; o[nf][3] *= c1;
        }
        __syncwarp();

        #pragma unroll
        for (int kc = 0; kc < 8; kc++) {
            int k = kc * 8 + tiq;
            uint32_t a0 = uP[(quad    ) * KSTR + k    ];
            uint32_t a1 = uP[(quad + 8) * KSTR + k    ];
            uint32_t a2 = uP[(quad    ) * KSTR + k + 4];
            uint32_t a3 = uP[(quad + 8) * KSTR + k + 4];
            #pragma unroll
            for (int nf = 0; nf < 8; nf++) {
                uint32_t b0 = uV[(k    ) * KSTR + nf * 8 + quad];
                uint32_t b1 = uV[(k + 4) * KSTR + nf * 8 + quad];
                mma_tf32(o[nf][0], o[nf][1], o[nf][2], o[nf][3],
                         a0, a1, a2, a3, b0, b1);
            }
        }
        __syncwarp();
    }

    float il0 = 1.f / l0, il1 = 1.f / l1;
    int r0 = tq0 + wid * 16 + quad;
    #pragma unroll
    for (int nf = 0; nf < 8; nf++) {
        int c = h * DHEAD + nf * 8 + tiq * 2;
        *reinterpret_cast<float2*>(aout + (size_t)r0 * DIMC + c) =
            make_float2(tf32r(o[nf][0] * il0), tf32r(o[nf][1] * il0));
        *reinterpret_cast<float2*>(aout + (size_t)(r0 + 8) * DIMC + c) =
            make_float2(tf32r(o[nf][2] * il1), tf32r(o[nf][3] * il1));
    }
}

// ============================================================
// launch
// ============================================================
extern "C" void kernel_launch(void* const* d_in, const int* in_sizes, int n_in,
                              void* d_out, int out_size)
{
    const float* x      = (const float*)d_in[0];
    const float* norm_g = (const float*)d_in[1];
    const float* norm_b = (const float*)d_in[2];
    const float* W1     = (const float*)d_in[3];
    const float* b1     = (const float*)d_in[4];
    const float* qn_g   = (const float*)d_in[5];
    const float* qn_b   = (const float*)d_in[6];
    const float* kn_g   = (const float*)d_in[7];
    const float* kn_b   = (const float*)d_in[8];
    const float* Wao    = (const float*)d_in[9];
    const float* bao    = (const float*)d_in[10];
    const float* Wmo    = (const float*)d_in[11];
    const float* bmo    = (const float*)d_in[12];
    const float* W2     = (const float*)d_in[13];
    const float* b2     = (const float*)d_in[14];
    float*       out    = (float*)d_out;

    float *norm, *fused, *attn, *w1t, *w2t, *waor, *wmor, *wfa, *wfm, *beff;
    cudaGetSymbolAddress((void**)&norm,  g_norm);
    cudaGetSymbolAddress((void**)&fused, g_fused);
    cudaGetSymbolAddress((void**)&attn,  g_attn);
    cudaGetSymbolAddress((void**)&w1t,   g_w1t);
    cudaGetSymbolAddress((void**)&w2t,   g_w2t);
    cudaGetSymbolAddress((void**)&waor,  g_waor);
    cudaGetSymbolAddress((void**)&wmor,  g_wmor);
    cudaGetSymbolAddress((void**)&wfa,   g_wfa);
    cudaGetSymbolAddress((void**)&wfm,   g_wfm);
    cudaGetSymbolAddress((void**)&beff,  g_beff);

    cudaFuncSetAttribute(mma_gemm, cudaFuncAttributeMaxDynamicSharedMemorySize, GEMM_SMEM);
    cudaFuncSetAttribute(fattn_kernel, cudaFuncAttributeMaxDynamicSharedMemorySize, ATTN_SMEM);

    const int NOGELU = 1 << 30;
    dim3 tblk(32, 8);

    // weight prep
    transpose_kernel<<<dim3(FWP / 32, DIMC / 32), tblk>>>(W1, DIMC, FW, w1t, DIMC, FWP);
    transpose_kernel<<<dim3(DIMC / 32, 2 * DIMC / 32), tblk>>>(W2, 2 * DIMC, DIMC, w2t, 2 * DIMC, DIMC);
    roundcopy_kernel<<<(DIMC * DIMC) / 256, 256>>>(Wao, DIMC, waor);
    roundcopy_kernel<<<(HIDPAD * DIMC) / 256, 256>>>(Wmo, MLPHID, wmor);
    beff_kernel<<<DIMC / 256, 256>>>(bao, bmo, b2, W2, beff);

    // weight folds: wfa[n][i] = sum_k Wao[i][k] W2[k][n] ; wfm[n][kh] = sum_c Wmo[kh][c] W2[1024+c][n]
    mma_gemm<<<dim3(DIMC / 128, DIMC / 128), 256, GEMM_SMEM>>>(
        w2t, 2 * DIMC, waor, DIMC, wfa, DIMC,
        nullptr, 0, nullptr, 0, DIMC, NOGELU, 1);
    mma_gemm<<<dim3(HIDPAD / 128, DIMC / 128), 256, GEMM_SMEM>>>(
        w2t + DIMC, 2 * DIMC, wmor, DIMC, wfm, HIDPAD,
        nullptr, 0, nullptr, 0, DIMC, NOGELU, 1);

    // 1) layernorm(x) (tf32-rounded)
    ln_kernel<<<NTOK, 256>>>(x, norm_g, norm_b, norm);

    // 2) fused = norm @ W1 + b1, gelu applied+rounded on cols >= 3072
    mma_gemm<<<dim3(FWP / 128, NTOK / 128), 256, GEMM_SMEM>>>(
        norm, DIMC, w1t, DIMC, fused, FWP,
        b1, FW, nullptr, 0, DIMC, 3 * DIMC, 0);

    // 3) per-head LN on q/k
    qkln_kernel<<<(NTOK * 32) / 8, 256>>>(fused, qn_g, qn_b, kn_g, kn_b);

    // 4) flash attention (tf32-rounded output)
    fattn_kernel<<<dim3(NSEQ / 128, NHEADS, 2), 256, ATTN_SMEM>>>(fused, attn);

    // 5) out = x + attn @ wfa^T + beff
    mma_gemm<<<dim3(DIMC / 128, NTOK / 128), 256, GEMM_SMEM>>>(
        attn, DIMC, wfa, DIMC, out, DIMC,
        beff, DIMC, x, DIMC, DIMC, NOGELU, 0);

    // 6) out += gelu_hidden @ wfm^T
    mma_gemm<<<dim3(DIMC / 128, NTOK / 128), 256, GEMM_SMEM>>>(
        fused + 3 * DIMC, FWP, wfm, HIDPAD, out, DIMC,
        nullptr, 0, out, DIMC, KHID, NOGELU, 0);
}

// round 6
// speedup vs baseline: 3.8475x; 1.0677x over previous
#include <cuda_runtime.h>
#include <math.h>
#include <stdint.h>

// ---------------- problem constants ----------------
#define NTOK   4096              // B*N = 2*2048
#define DIMC   1024
#define NHEADS 16
#define DHEAD  64
#define MLPHID 716
#define FW     3788              // 3*DIM + MLP_HID (true width)
#define FWP    3840              // padded to 30*128
#define HIDPAD 768               // Wmo rows padded
#define KHID   736               // K used in apply segment 2
#define NSEQ   2048
#define LN_EPS 1e-6f
#define NSLICE 16

// ---------------- scratch (static device globals) ------
__device__ float g_norm [NTOK * DIMC];
__device__ float g_fused[NTOK * FWP];
__device__ float g_attn [NTOK * DIMC];
__device__ float g_w1t  [FWP  * DIMC];
__device__ float g_w2t  [DIMC * 2 * DIMC];
__device__ float g_waor [DIMC * DIMC];
__device__ float g_wmor [HIDPAD * DIMC];
__device__ float g_wfa  [DIMC * DIMC];
__device__ float g_wfm  [DIMC * HIDPAD];
__device__ float g_beff [DIMC];
__device__ float g_beffp[NSLICE * DIMC];

// ================= helpers =================
__device__ __forceinline__ uint32_t tf32cvt(float x) {
    uint32_t u;
    asm("cvt.rna.tf32.f32 %0, %1;" : "=r"(u) : "f"(x));
    return u;
}
__device__ __forceinline__ float tf32r(float x) {
    return __uint_as_float(tf32cvt(x));
}
__device__ __forceinline__ uint32_t smem_u32(const void* p) {
    uint32_t a;
    asm("{ .reg .u64 t; cvta.to.shared.u64 t, %1; cvt.u32.u64 %0, t; }" : "=r"(a) : "l"(p));
    return a;
}
__device__ __forceinline__ void mma_tf32(float& d0, float& d1, float& d2, float& d3,
                                         uint32_t a0, uint32_t a1, uint32_t a2, uint32_t a3,
                                         uint32_t b0, uint32_t b1)
{
    asm volatile(
        "mma.sync.aligned.m16n8k8.row.col.f32.tf32.tf32.f32 "
        "{%0,%1,%2,%3}, {%4,%5,%6,%7}, {%8,%9}, {%0,%1,%2,%3};"
        : "+f"(d0), "+f"(d1), "+f"(d2), "+f"(d3)
        : "r"(a0), "r"(a1), "r"(a2), "r"(a3), "r"(b0), "r"(b1));
}
__device__ __forceinline__ float gelu1(float x) {
    float u = 0.7978845608028654f * (x + 0.044715f * x * x * x);
    return 0.5f * x * (1.f + tanhf(u));
}
#define CP_CA(dst, src) asm volatile("cp.async.ca.shared.global [%0], [%1], 16;" :: "r"(dst), "l"(src) : "memory")
#define CP_CG(dst, src) asm volatile("cp.async.cg.shared.global [%0], [%1], 16;" :: "r"(dst), "l"(src) : "memory")
#define CP_COMMIT()     asm volatile("cp.async.commit_group;" ::: "memory")
#define CP_WAIT(n)      asm volatile("cp.async.wait_group %0;" :: "n"(n) : "memory")

// ============================================================
// weight transpose + tf32 round
// ============================================================
__global__ void transpose_kernel(const float* __restrict__ W, int K, int N,
                                 float* __restrict__ Wt, int Kpad, int Npad)
{
    __shared__ float t[32][33];
    int n0 = blockIdx.x * 32, k0 = blockIdx.y * 32;
    int tx = threadIdx.x, ty = threadIdx.y;
    #pragma unroll
    for (int i = 0; i < 32; i += 8) {
        int k = k0 + ty + i, n = n0 + tx;
        t[ty + i][tx] = (k < K && n < N) ? tf32r(W[(size_t)k * N + n]) : 0.f;
    }
    __syncthreads();
    #pragma unroll
    for (int i = 0; i < 32; i += 8) {
        int n = n0 + ty + i, k = k0 + tx;
        if (n < Npad && k < Kpad) Wt[(size_t)n * Kpad + k] = t[tx][ty + i];
    }
}

// ============================================================
// round-copy (cols=1024) with zero row padding
// ============================================================
__global__ void roundcopy_kernel(const float* __restrict__ W, int rows,
                                 float* __restrict__ out)
{
    int idx = blockIdx.x * 256 + threadIdx.x;
    int r = idx >> 10, c = idx & 1023;
    out[idx] = (r < rows) ? tf32r(W[(size_t)r * DIMC + c]) : 0.f;
}

// ============================================================
// folded bias, k-sliced partials + reduce
// beff[n] = b2[n] + sum_{k<1024} bao[k] W2[k][n] + sum_{k<1024} bmo[k] W2[1024+k][n]
// ============================================================
__global__ void beff_part(const float* __restrict__ bao,
                          const float* __restrict__ bmo,
                          const float* __restrict__ b2,
                          const float* __restrict__ W2)
{
    int n = blockIdx.x * 256 + threadIdx.x;
    int s = blockIdx.y;
    float acc = (s == 0) ? b2[n] : 0.f;
    int k0 = s * (2048 / NSLICE), k1 = k0 + (2048 / NSLICE);
    for (int k = k0; k < k1; k++) {
        float c = (k < 1024) ? bao[k] : bmo[k - 1024];
        acc += c * W2[(size_t)k * DIMC + n];
    }
    g_beffp[s * DIMC + n] = acc;
}
__global__ void beff_red(float* __restrict__ beff)
{
    int n = blockIdx.x * 256 + threadIdx.x;
    float s = 0.f;
    #pragma unroll
    for (int i = 0; i < NSLICE; i++) s += g_beffp[i * DIMC + n];
    beff[n] = s;
}

// ============================================================
// LayerNorm over DIM=1024, tf32-rounded output
// ============================================================
__global__ void ln_kernel(const float* __restrict__ x,
                          const float* __restrict__ g,
                          const float* __restrict__ b,
                          float* __restrict__ out)
{
    int row = blockIdx.x;
    int tid = threadIdx.x;
    const float4 v = reinterpret_cast<const float4*>(x + (size_t)row * DIMC)[tid];

    float s  = v.x + v.y + v.z + v.w;
    float sq = v.x*v.x + v.y*v.y + v.z*v.z + v.w*v.w;
    #pragma unroll
    for (int o = 16; o > 0; o >>= 1) {
        s  += __shfl_xor_sync(0xffffffffu, s,  o);
        sq += __shfl_xor_sync(0xffffffffu, sq, o);
    }
    __shared__ float ws[8], wq[8];
    int warp = tid >> 5, lane = tid & 31;
    if (lane == 0) { ws[warp] = s; wq[warp] = sq; }
    __syncthreads();
    if (warp == 0) {
        float s2  = (lane < 8) ? ws[lane] : 0.f;
        float sq2 = (lane < 8) ? wq[lane] : 0.f;
        #pragma unroll
        for (int o = 4; o > 0; o >>= 1) {
            s2  += __shfl_xor_sync(0xffffffffu, s2,  o);
            sq2 += __shfl_xor_sync(0xffffffffu, sq2, o);
        }
        if (lane == 0) { ws[0] = s2; wq[0] = sq2; }
    }
    __syncthreads();
    float mean = ws[0] * (1.f / DIMC);
    float var  = wq[0] * (1.f / DIMC) - mean * mean;
    float rstd = rsqrtf(var + LN_EPS);

    float4 gg = reinterpret_cast<const float4*>(g)[tid];
    float4 bb = reinterpret_cast<const float4*>(b)[tid];
    float4 o4;
    o4.x = tf32r((v.x - mean) * rstd * gg.x + bb.x);
    o4.y = tf32r((v.y - mean) * rstd * gg.y + bb.y);
    o4.z = tf32r((v.z - mean) * rstd * gg.z + bb.z);
    o4.w = tf32r((v.w - mean) * rstd * gg.w + bb.w);
    reinterpret_cast<float4*>(out + (size_t)row * DIMC)[tid] = o4;
}

// ============================================================
// tf32 mma.sync GEMM, 3-stage cp.async pipeline, dual K-segment.
// C[M,N] = A[M,K1] @ Bt^T (+ A2[M,K2] @ Bt2^T) (+bias)(+resid)
// ============================================================
#define SSTR  36
#define ABUF  (128 * SSTR)
#define STAGE (2 * ABUF)
#define GEMM_SMEM (3 * STAGE * 4)   // 110592 B

__global__ void __launch_bounds__(256, 2)
mma_gemm(const float* __restrict__ A, int lda,
         const float* __restrict__ Bt, int ldb,
         float* __restrict__ C, int ldc,
         const float* __restrict__ bias, int nbias,
         const float* __restrict__ resid, int ldr,
         int K1, int gelu_from, int round_all,
         const float* __restrict__ A2, int lda2,
         const float* __restrict__ Bt2, int ldb2, int K2)
{
    extern __shared__ float sm[];
    uint32_t sbase = smem_u32(sm);
    int tid  = threadIdx.x;
    int wid  = tid >> 5, lane = tid & 31;
    int gid2 = lane >> 2, tig = lane & 3;
    int bm = blockIdx.y * 128, bn = blockIdx.x * 128;
    int wm = (wid & 1) * 64, wn = (wid >> 1) * 32;

    float acc[4][4][4];
    #pragma unroll
    for (int i = 0; i < 4; i++)
        #pragma unroll
        for (int j = 0; j < 4; j++)
            #pragma unroll
            for (int r = 0; r < 4; r++) acc[i][j][r] = 0.f;

    int lr = tid >> 3;
    int lc = (tid & 7) * 4;

    const int nk1 = K1 >> 5;
    const int nk  = nk1 + (K2 >> 5);

    auto prefetch = [&](int it, int st) {
        const float* Ab; const float* Bb; int la, lb, k0;
        if (it < nk1) { Ab = A;  Bb = Bt;  la = lda;  lb = ldb;  k0 = it << 5; }
        else          { Ab = A2; Bb = Bt2; la = lda2; lb = ldb2; k0 = (it - nk1) << 5; }
        uint32_t dA = sbase + (uint32_t)st * STAGE * 4;
        uint32_t dB = dA + ABUF * 4;
        #pragma unroll
        for (int i = 0; i < 4; i++) {
            int r = i * 32 + lr;
            CP_CA(dA + (uint32_t)(r * SSTR + lc) * 4, Ab + (size_t)(bm + r) * la + k0 + lc);
            CP_CG(dB + (uint32_t)(r * SSTR + lc) * 4, Bb + (size_t)(bn + r) * lb + k0 + lc);
        }
        CP_COMMIT();
    };

    prefetch(0, 0);
    if (nk > 1) prefetch(1, 1);

    for (int it = 0; it < nk; it++) {
        int st = it % 3;
        if (it + 2 < nk) { prefetch(it + 2, (it + 2) % 3); CP_WAIT(2); }
        else if (it + 1 < nk) { CP_WAIT(1); }
        else { CP_WAIT(0); }
        __syncthreads();

        const uint32_t* sA = reinterpret_cast<const uint32_t*>(sm + st * STAGE);
        const uint32_t* sB = sA + ABUF;

        #pragma unroll
        for (int kk = 0; kk < 4; kk++) {
            int k8 = kk * 8;
            uint32_t af[4][4], bf[4][2];
            #pragma unroll
            for (int mt = 0; mt < 4; mt++) {
                int row = wm + mt * 16 + gid2;
                af[mt][0] = sA[(row    ) * SSTR + k8 + tig    ];
                af[mt][1] = sA[(row + 8) * SSTR + k8 + tig    ];
                af[mt][2] = sA[(row    ) * SSTR + k8 + tig + 4];
                af[mt][3] = sA[(row + 8) * SSTR + k8 + tig + 4];
            }
            #pragma unroll
            for (int nt = 0; nt < 4; nt++) {
                int col = wn + nt * 8 + gid2;
                bf[nt][0] = sB[col * SSTR + k8 + tig    ];
                bf[nt][1] = sB[col * SSTR + k8 + tig + 4];
            }
            #pragma unroll
            for (int mt = 0; mt < 4; mt++)
                #pragma unroll
                for (int nt = 0; nt < 4; nt++)
                    mma_tf32(acc[mt][nt][0], acc[mt][nt][1],
                             acc[mt][nt][2], acc[mt][nt][3],
                             af[mt][0], af[mt][1], af[mt][2], af[mt][3],
                             bf[nt][0], bf[nt][1]);
        }
        __syncthreads();
    }

    bool do_gelu = (bn >= gelu_from);

    #pragma unroll
    for (int mt = 0; mt < 4; mt++) {
        int r0 = bm + wm + mt * 16 + gid2;
        #pragma unroll
        for (int nt = 0; nt < 4; nt++) {
            int c = bn + wn + nt * 8 + tig * 2;
            float2 v0 = make_float2(acc[mt][nt][0], acc[mt][nt][1]);
            float2 v1 = make_float2(acc[mt][nt][2], acc[mt][nt][3]);
            if (bias) {
                float bx = (c     < nbias) ? bias[c]     : 0.f;
                float by = (c + 1 < nbias) ? bias[c + 1] : 0.f;
                v0.x += bx; v0.y += by;
                v1.x += bx; v1.y += by;
            }
            if (resid) {
                float2 ra = *reinterpret_cast<const float2*>(resid + (size_t)r0 * ldr + c);
                float2 rb = *reinterpret_cast<const float2*>(resid + (size_t)(r0 + 8) * ldr + c);
                v0.x += ra.x; v0.y += ra.y;
                v1.x += rb.x; v1.y += rb.y;
            }
            if (do_gelu) {
                v0.x = tf32r(gelu1(v0.x)); v0.y = tf32r(gelu1(v0.y));
                v1.x = tf32r(gelu1(v1.x)); v1.y = tf32r(gelu1(v1.y));
            } else if (round_all) {
                v0.x = tf32r(v0.x); v0.y = tf32r(v0.y);
                v1.x = tf32r(v1.x); v1.y = tf32r(v1.y);
            }
            *reinterpret_cast<float2*>(C + (size_t)r0 * ldc + c) = v0;
            *reinterpret_cast<float2*>(C + (size_t)(r0 + 8) * ldc + c) = v1;
        }
    }
}

// ============================================================
// Per-head Q/K layernorm; q rows get *0.125 (attention scale folded in)
// ============================================================
__global__ void qkln_kernel(float* __restrict__ fused,
                            const float* __restrict__ qg, const float* __restrict__ qb,
                            const float* __restrict__ kg, const float* __restrict__ kb)
{
    int gid   = blockIdx.x * 8 + (threadIdx.x >> 5);
    int lane  = threadIdx.x & 31;
    int token = gid >> 5;
    int rem   = gid & 31;
    int qk    = rem >> 4;
    int head  = rem & 15;

    float* p = fused + (size_t)token * FWP + qk * DIMC + head * DHEAD;
    float v0 = p[lane];
    float v1 = p[lane + 32];

    float s = v0 + v1;
    #pragma unroll
    for (int o = 16; o > 0; o >>= 1) s += __shfl_xor_sync(0xffffffffu, s, o);
    float mean = s * (1.f / 64.f);

    float d0 = v0 - mean, d1 = v1 - mean;
    float sq = d0 * d0 + d1 * d1;
    #pragma unroll
    for (int o = 16; o > 0; o >>= 1) sq += __shfl_xor_sync(0xffffffffu, sq, o);
    float rstd = rsqrtf(sq * (1.f / 64.f) + LN_EPS);

    const float* g = qk ? kg : qg;
    const float* b = qk ? kb : qb;
    float sc = qk ? 1.f : 0.125f;
    p[lane]      = (d0 * rstd * g[lane]      + b[lane])      * sc;
    p[lane + 32] = (d1 * rstd * g[lane + 32] + b[lane + 32]) * sc;
}

// ============================================================
// Flash attention, tf32 mma, cp.async double-buffered K/V.
// Raw f32 operands (HW truncates to tf32 — error invisible here).
// Q SMEM region reused as per-warp P patch after fragment extraction.
// ============================================================
#define KSTR 68
#define QELEMS (128 * KSTR)           // 8704 floats
#define KVTILE (64 * KSTR)            // 4352 floats
#define ATTN_SMEM ((QELEMS + 4 * KVTILE) * 4)   // 104448 B

__global__ void __launch_bounds__(256, 2)
fattn_kernel(const float* __restrict__ fused, float* __restrict__ aout)
{
    extern __shared__ float sm[];
    uint32_t sbase = smem_u32(sm);

    int tid  = threadIdx.x;
    int wid  = tid >> 5, lane = tid & 31;
    int quad = lane >> 2, tiq = lane & 3;
    int h  = blockIdx.y;
    int bb = blockIdx.z;
    int q0 = blockIdx.x * 128;
    int tq0 = bb * NSEQ + q0;
    int kvb = bb * NSEQ;

    auto prefetch_kv = [&](int kt, int buf) {
        uint32_t dK = sbase + (uint32_t)(QELEMS + buf * 2 * KVTILE) * 4;
        uint32_t dV = dK + KVTILE * 4;
        #pragma unroll
        for (int i = 0; i < 4; i++) {
            int idx = i * 256 + tid;
            int r = idx >> 4, c4 = (idx & 15) * 4;
            const float* base = fused + (size_t)(kvb + kt + r) * FWP + h * DHEAD + c4;
            uint32_t off = (uint32_t)(r * KSTR + c4) * 4;
            CP_CG(dK + off, base + DIMC);
            CP_CG(dV + off, base + 2 * DIMC);
        }
        CP_COMMIT();
    };

    // Q tile (128x64) + first K/V tile, one group
    #pragma unroll
    for (int i = 0; i < 8; i++) {
        int idx = i * 256 + tid;
        int r = idx >> 4, c4 = (idx & 15) * 4;
        CP_CA(sbase + (uint32_t)(r * KSTR + c4) * 4,
              fused + (size_t)(tq0 + r) * FWP + h * DHEAD + c4);
    }
    prefetch_kv(0, 0);
    CP_WAIT(0);
    __syncthreads();

    // persistent Q fragments (raw f32 bits)
    uint32_t qf[8][4];
    {
        const uint32_t* sQ = reinterpret_cast<const uint32_t*>(sm);
        int r0 = wid * 16 + quad;
        #pragma unroll
        for (int kc = 0; kc < 8; kc++) {
            int c = kc * 8 + tiq;
            qf[kc][0] = sQ[(r0    ) * KSTR + c    ];
            qf[kc][1] = sQ[(r0 + 8) * KSTR + c    ];
            qf[kc][2] = sQ[(r0    ) * KSTR + c + 4];
            qf[kc][3] = sQ[(r0 + 8) * KSTR + c + 4];
        }
    }
    // per-warp P patch reuses this warp's own Q rows
    float* sP = sm + wid * 16 * KSTR;
    const uint32_t* uP = reinterpret_cast<const uint32_t*>(sP);

    float o[8][4];
    #pragma unroll
    for (int i = 0; i < 8; i++)
        #pragma unroll
        for (int j = 0; j < 4; j++) o[i][j] = 0.f;
    float m0 = -1e30f, m1 = -1e30f, l0 = 0.f, l1 = 0.f;

    for (int t = 0; t < NSEQ / 64; t++) {
        int b = t & 1;
        if (t + 1 < NSEQ / 64) prefetch_kv((t + 1) * 64, b ^ 1);

        const uint32_t* uK = reinterpret_cast<const uint32_t*>(sm + QELEMS + b * 2 * KVTILE);
        const uint32_t* uV = uK + KVTILE;

        float sc[8][4];
        #pragma unroll
        for (int i = 0; i < 8; i++)
            #pragma unroll
            for (int j = 0; j < 4; j++) sc[i][j] = 0.f;

        #pragma unroll
        for (int kc = 0; kc < 8; kc++) {
            int k8 = kc * 8 + tiq;
            #pragma unroll
            for (int nf = 0; nf < 8; nf++) {
                uint32_t b0 = uK[(nf * 8 + quad) * KSTR + k8    ];
                uint32_t b1 = uK[(nf * 8 + quad) * KSTR + k8 + 4];
                mma_tf32(sc[nf][0], sc[nf][1], sc[nf][2], sc[nf][3],
                         qf[kc][0], qf[kc][1], qf[kc][2], qf[kc][3], b0, b1);
            }
        }

        float rm0 = -1e30f, rm1 = -1e30f;
        #pragma unroll
        for (int nf = 0; nf < 8; nf++) {
            rm0 = fmaxf(rm0, fmaxf(sc[nf][0], sc[nf][1]));
            rm1 = fmaxf(rm1, fmaxf(sc[nf][2], sc[nf][3]));
        }
        rm0 = fmaxf(rm0, __shfl_xor_sync(0xffffffffu, rm0, 1));
        rm0 = fmaxf(rm0, __shfl_xor_sync(0xffffffffu, rm0, 2));
        rm1 = fmaxf(rm1, __shfl_xor_sync(0xffffffffu, rm1, 1));
        rm1 = fmaxf(rm1, __shfl_xor_sync(0xffffffffu, rm1, 2));

        float mn0 = fmaxf(m0, rm0), mn1 = fmaxf(m1, rm1);
        float c0 = __expf(m0 - mn0), c1 = __expf(m1 - mn1);
        m0 = mn0; m1 = mn1;

        float rs0 = 0.f, rs1 = 0.f;
        #pragma unroll
        for (int nf = 0; nf < 8; nf++) {
            float p0 = __expf(sc[nf][0] - m0);
            float p1 = __expf(sc[nf][1] - m0);
            float p2 = __expf(sc[nf][2] - m1);
            float p3 = __expf(sc[nf][3] - m1);
            rs0 += p0 + p1; rs1 += p2 + p3;
            int cb = nf * 8 + tiq * 2;
            sP[(quad    ) * KSTR + cb    ] = p0;
            sP[(quad    ) * KSTR + cb + 1] = p1;
            sP[(quad + 8) * KSTR + cb    ] = p2;
            sP[(quad + 8) * KSTR + cb + 1] = p3;
        }
        rs0 += __shfl_xor_sync(0xffffffffu, rs0, 1);
        rs0 += __shfl_xor_sync(0xffffffffu, rs0, 2);
        rs1 += __shfl_xor_sync(0xffffffffu, rs1, 1);
        rs1 += __shfl_xor_sync(0xffffffffu, rs1, 2);
        l0 = l0 * c0 + rs0;
        l1 = l1 * c1 + rs1;

        #pragma unroll
        for (int nf = 0; nf < 8; nf++) {
            o[nf][0] *= c0; o[nf][1] *= c0;
            o[nf][2] *= c1; o[nf][3] *= c1;
        }
        __syncwarp();

        #pragma unroll
        for (int kc = 0; kc < 8; kc++) {
            int k = kc * 8 + tiq;
            uint32_t a0 = uP[(quad    ) * KSTR + k    ];
            uint32_t a1 = uP[(quad + 8) * KSTR + k    ];
            uint32_t a2 = uP[(quad    ) * KSTR + k + 4];
            uint32_t a3 = uP[(quad + 8) * KSTR + k + 4];
            #pragma unroll
            for (int nf = 0; nf < 8; nf++) {
                uint32_t b0 = uV[(k    ) * KSTR + nf * 8 + quad];
                uint32_t b1 = uV[(k + 4) * KSTR + nf * 8 + quad];
                mma_tf32(o[nf][0], o[nf][1], o[nf][2], o[nf][3],
                         a0, a1, a2, a3, b0, b1);
            }
        }
        __syncwarp();

        if (t + 1 < NSEQ / 64) { CP_WAIT(0); }
        __syncthreads();
    }

    float il0 = 1.f / l0, il1 = 1.f / l1;
    int r0 = tq0 + wid * 16 + quad;
    #pragma unroll
    for (int nf = 0; nf < 8; nf++) {
        int c = h * DHEAD + nf * 8 + tiq * 2;
        *reinterpret_cast<float2*>(aout + (size_t)r0 * DIMC + c) =
            make_float2(o[nf][0] * il0, o[nf][1] * il0);
        *reinterpret_cast<float2*>(aout + (size_t)(r0 + 8) * DIMC + c) =
            make_float2(o[nf][2] * il1, o[nf][3] * il1);
    }
}

// ============================================================
// launch
// ============================================================
extern "C" void kernel_launch(void* const* d_in, const int* in_sizes, int n_in,
                              void* d_out, int out_size)
{
    const float* x      = (const float*)d_in[0];
    const float* norm_g = (const float*)d_in[1];
    const float* norm_b = (const float*)d_in[2];
    const float* W1     = (const float*)d_in[3];
    const float* b1     = (const float*)d_in[4];
    const float* qn_g   = (const float*)d_in[5];
    const float* qn_b   = (const float*)d_in[6];
    const float* kn_g   = (const float*)d_in[7];
    const float* kn_b   = (const float*)d_in[8];
    const float* Wao    = (const float*)d_in[9];
    const float* bao    = (const float*)d_in[10];
    const float* Wmo    = (const float*)d_in[11];
    const float* bmo    = (const float*)d_in[12];
    const float* W2     = (const float*)d_in[13];
    const float* b2     = (const float*)d_in[14];
    float*       out    = (float*)d_out;

    float *norm, *fused, *attn, *w1t, *w2t, *waor, *wmor, *wfa, *wfm, *beff;
    cudaGetSymbolAddress((void**)&norm,  g_norm);
    cudaGetSymbolAddress((void**)&fused, g_fused);
    cudaGetSymbolAddress((void**)&attn,  g_attn);
    cudaGetSymbolAddress((void**)&w1t,   g_w1t);
    cudaGetSymbolAddress((void**)&w2t,   g_w2t);
    cudaGetSymbolAddress((void**)&waor,  g_waor);
    cudaGetSymbolAddress((void**)&wmor,  g_wmor);
    cudaGetSymbolAddress((void**)&wfa,   g_wfa);
    cudaGetSymbolAddress((void**)&wfm,   g_wfm);
    cudaGetSymbolAddress((void**)&beff,  g_beff);

    cudaFuncSetAttribute(mma_gemm, cudaFuncAttributeMaxDynamicSharedMemorySize, GEMM_SMEM);
    cudaFuncSetAttribute(fattn_kernel, cudaFuncAttributeMaxDynamicSharedMemorySize, ATTN_SMEM);

    const int NOGELU = 1 << 30;
    dim3 tblk(32, 8);

    // weight prep
    transpose_kernel<<<dim3(FWP / 32, DIMC / 32), tblk>>>(W1, DIMC, FW, w1t, DIMC, FWP);
    transpose_kernel<<<dim3(DIMC / 32, 2 * DIMC / 32), tblk>>>(W2, 2 * DIMC, DIMC, w2t, 2 * DIMC, DIMC);
    roundcopy_kernel<<<(DIMC * DIMC) / 256, 256>>>(Wao, DIMC, waor);
    roundcopy_kernel<<<(HIDPAD * DIMC) / 256, 256>>>(Wmo, MLPHID, wmor);
    beff_part<<<dim3(DIMC / 256, NSLICE), 256>>>(bao, bmo, b2, W2);
    beff_red<<<DIMC / 256, 256>>>(beff);

    // weight folds
    mma_gemm<<<dim3(DIMC / 128, DIMC / 128), 256, GEMM_SMEM>>>(
        w2t, 2 * DIMC, waor, DIMC, wfa, DIMC,
        nullptr, 0, nullptr, 0, DIMC, NOGELU, 1,
        nullptr, 0, nullptr, 0, 0);
    mma_gemm<<<dim3(HIDPAD / 128, DIMC / 128), 256, GEMM_SMEM>>>(
        w2t + DIMC, 2 * DIMC, wmor, DIMC, wfm, HIDPAD,
        nullptr, 0, nullptr, 0, DIMC, NOGELU, 1,
        nullptr, 0, nullptr, 0, 0);

    // 1) layernorm(x)
    ln_kernel<<<NTOK, 256>>>(x, norm_g, norm_b, norm);

    // 2) fused = norm @ W1 + b1, gelu on cols >= 3072
    mma_gemm<<<dim3(FWP / 128, NTOK / 128), 256, GEMM_SMEM>>>(
        norm, DIMC, w1t, DIMC, fused, FWP,
        b1, FW, nullptr, 0, DIMC, 3 * DIMC, 0,
        nullptr, 0, nullptr, 0, 0);

    // 3) per-head LN on q/k (q scaled by 0.125)
    qkln_kernel<<<(NTOK * 32) / 8, 256>>>(fused, qn_g, qn_b, kn_g, kn_b);

    // 4) flash attention
    fattn_kernel<<<dim3(NSEQ / 128, NHEADS, 2), 256, ATTN_SMEM>>>(fused, attn);

    // 5) out = x + attn @ wfa^T + gelu_hidden @ wfm^T + beff  (merged)
    mma_gemm<<<dim3(DIMC / 128, NTOK / 128), 256, GEMM_SMEM>>>(
        attn, DIMC, wfa, DIMC, out, DIMC,
        beff, DIMC, x, DIMC, DIMC, NOGELU, 0,
        fused + 3 * DIMC, FWP, wfm, HIDPAD, KHID);
}

// round 7
// speedup vs baseline: 7.1300x; 1.8531x over previous
#include <cuda_runtime.h>
#include <cuda_fp16.h>
#include <math.h>
#include <stdint.h>

// ---------------- problem constants ----------------
#define NTOK   4096              // B*N = 2*2048
#define DIMC   1024
#define NHEADS 16
#define DHEAD  64
#define MLPHID 716
#define FW     3788              // 3*DIM + MLP_HID (true width)
#define FWP    3840              // padded to 30*128
#define HIDPAD 768               // Wmo rows padded; K2 of apply
#define NSEQ   2048
#define LN_EPS 1e-6f
#define NSLICE 16

// ---------------- scratch (static device globals) ------
__device__ __half g_norm [NTOK * DIMC];
__device__ __half g_fused[NTOK * FWP];
__device__ __half g_vt   [2 * NHEADS * DHEAD * NSEQ];   // V transposed [b][h][d][n]
__device__ __half g_attn [NTOK * DIMC];
__device__ __half g_w1t  [FWP  * DIMC];
__device__ __half g_w2t  [DIMC * 2 * DIMC];
__device__ __half g_waor [DIMC * DIMC];
__device__ __half g_wmor [HIDPAD * DIMC];
__device__ __half g_wfa  [DIMC * DIMC];
__device__ __half g_wfm  [DIMC * HIDPAD];
__device__ float  g_beff [DIMC];
__device__ float  g_beffp[NSLICE * DIMC];

// ================= helpers =================
__device__ __forceinline__ uint32_t smem_u32(const void* p) {
    uint32_t a;
    asm("{ .reg .u64 t; cvta.to.shared.u64 t, %1; cvt.u32.u64 %0, t; }" : "=r"(a) : "l"(p));
    return a;
}
__device__ __forceinline__ void mma_f16(float& d0, float& d1, float& d2, float& d3,
                                        uint32_t a0, uint32_t a1, uint32_t a2, uint32_t a3,
                                        uint32_t b0, uint32_t b1)
{
    asm volatile(
        "mma.sync.aligned.m16n8k16.row.col.f32.f16.f16.f32 "
        "{%0,%1,%2,%3}, {%4,%5,%6,%7}, {%8,%9}, {%0,%1,%2,%3};"
        : "+f"(d0), "+f"(d1), "+f"(d2), "+f"(d3)
        : "r"(a0), "r"(a1), "r"(a2), "r"(a3), "r"(b0), "r"(b1));
}
__device__ __forceinline__ float gelu1(float x) {
    float u = 0.7978845608028654f * (x + 0.044715f * x * x * x);
    return 0.5f * x * (1.f + tanhf(u));
}
__device__ __forceinline__ uint32_t h2pack(float a, float b) {
    __half2 h = __floats2half2_rn(a, b);
    return *reinterpret_cast<uint32_t*>(&h);
}
#define CP_CA(dst, src) asm volatile("cp.async.ca.shared.global [%0], [%1], 16;" :: "r"(dst), "l"(src) : "memory")
#define CP_CG(dst, src) asm volatile("cp.async.cg.shared.global [%0], [%1], 16;" :: "r"(dst), "l"(src) : "memory")
#define CP_COMMIT()     asm volatile("cp.async.commit_group;" ::: "memory")
#define CP_WAIT(n)      asm volatile("cp.async.wait_group %0;" :: "n"(n) : "memory")

// ============================================================
// weight transpose to half: Wt[n][k] = h(W[k][n])
// ============================================================
__global__ void transpose_kernel(const float* __restrict__ W, int K, int N,
                                 __half* __restrict__ Wt, int Kpad, int Npad)
{
    __shared__ float t[32][33];
    int n0 = blockIdx.x * 32, k0 = blockIdx.y * 32;
    int tx = threadIdx.x, ty = threadIdx.y;
    #pragma unroll
    for (int i = 0; i < 32; i += 8) {
        int k = k0 + ty + i, n = n0 + tx;
        t[ty + i][tx] = (k < K && n < N) ? W[(size_t)k * N + n] : 0.f;
    }
    __syncthreads();
    #pragma unroll
    for (int i = 0; i < 32; i += 8) {
        int n = n0 + ty + i, k = k0 + tx;
        if (n < Npad && k < Kpad) Wt[(size_t)n * Kpad + k] = __float2half(t[tx][ty + i]);
    }
}

// ============================================================
// round-copy to half (cols=1024) with zero row padding
// ============================================================
__global__ void roundcopy_kernel(const float* __restrict__ W, int rows,
                                 __half* __restrict__ out)
{
    int idx = blockIdx.x * 256 + threadIdx.x;
    int r = idx >> 10, c = idx & 1023;
    out[idx] = (r < rows) ? __float2half(W[(size_t)r * DIMC + c]) : __float2half(0.f);
}

// ============================================================
// folded bias (exact fp32), k-sliced partials + reduce
// ============================================================
__global__ void beff_part(const float* __restrict__ bao,
                          const float* __restrict__ bmo,
                          const float* __restrict__ b2,
                          const float* __restrict__ W2)
{
    int n = blockIdx.x * 256 + threadIdx.x;
    int s = blockIdx.y;
    float acc = (s == 0) ? b2[n] : 0.f;
    int k0 = s * (2048 / NSLICE), k1 = k0 + (2048 / NSLICE);
    for (int k = k0; k < k1; k++) {
        float c = (k < 1024) ? bao[k] : bmo[k - 1024];
        acc += c * W2[(size_t)k * DIMC + n];
    }
    g_beffp[s * DIMC + n] = acc;
}
__global__ void beff_red(float* __restrict__ beff)
{
    int n = blockIdx.x * 256 + threadIdx.x;
    float s = 0.f;
    #pragma unroll
    for (int i = 0; i < NSLICE; i++) s += g_beffp[i * DIMC + n];
    beff[n] = s;
}

// ============================================================
// LayerNorm over DIM=1024, half output
// ============================================================
__global__ void ln_kernel(const float* __restrict__ x,
                          const float* __restrict__ g,
                          const float* __restrict__ b,
                          __half* __restrict__ out)
{
    int row = blockIdx.x;
    int tid = threadIdx.x;
    const float4 v = reinterpret_cast<const float4*>(x + (size_t)row * DIMC)[tid];

    float s  = v.x + v.y + v.z + v.w;
    float sq = v.x*v.x + v.y*v.y + v.z*v.z + v.w*v.w;
    #pragma unroll
    for (int o = 16; o > 0; o >>= 1) {
        s  += __shfl_xor_sync(0xffffffffu, s,  o);
        sq += __shfl_xor_sync(0xffffffffu, sq, o);
    }
    __shared__ float ws[8], wq[8];
    int warp = tid >> 5, lane = tid & 31;
    if (lane == 0) { ws[warp] = s; wq[warp] = sq; }
    __syncthreads();
    if (warp == 0) {
        float s2  = (lane < 8) ? ws[lane] : 0.f;
        float sq2 = (lane < 8) ? wq[lane] : 0.f;
        #pragma unroll
        for (int o = 4; o > 0; o >>= 1) {
            s2  += __shfl_xor_sync(0xffffffffu, s2,  o);
            sq2 += __shfl_xor_sync(0xffffffffu, sq2, o);
        }
        if (lane == 0) { ws[0] = s2; wq[0] = sq2; }
    }
    __syncthreads();
    float mean = ws[0] * (1.f / DIMC);
    float var  = wq[0] * (1.f / DIMC) - mean * mean;
    float rstd = rsqrtf(var + LN_EPS);

    float4 gg = reinterpret_cast<const float4*>(g)[tid];
    float4 bb = reinterpret_cast<const float4*>(b)[tid];
    uint2 o2;
    o2.x = h2pack((v.x - mean) * rstd * gg.x + bb.x,
                  (v.y - mean) * rstd * gg.y + bb.y);
    o2.y = h2pack((v.z - mean) * rstd * gg.z + bb.z,
                  (v.w - mean) * rstd * gg.w + bb.w);
    reinterpret_cast<uint2*>(out + (size_t)row * DIMC)[tid] = o2;
}

// ============================================================
// fp16 mma.sync GEMM, 3-stage cp.async pipeline, dual K-segment.
// All dims in HALVES. Word stride 36 -> conflict-free fragment LDS.
// mode 0: C half plain   mode 1: GEMM1 (qk half / V->g_vt transposed / gelu)
// mode 2: C float + bias + resid
// ============================================================
#define SSTRW 36
#define ABUFW (128 * SSTRW)
#define STAGEW (2 * ABUFW)
#define GEMM_SMEM (3 * STAGEW * 4)   // 110592 B

__global__ void __launch_bounds__(256, 2)
mma_gemm(const __half* __restrict__ A, int lda,
         const __half* __restrict__ Bt, int ldb, int K1,
         const __half* __restrict__ A2, int lda2,
         const __half* __restrict__ Bt2, int ldb2, int K2,
         __half* __restrict__ Ch, int ldch,
         float* __restrict__ Cf, int ldcf,
         const float* __restrict__ bias, int nbias,
         const float* __restrict__ resid, int ldr,
         int mode)
{
    extern __shared__ uint32_t smw[];
    uint32_t sbase = smem_u32(smw);
    int tid  = threadIdx.x;
    int wid  = tid >> 5, lane = tid & 31;
    int quad = lane >> 2, tig = lane & 3;
    int bm = blockIdx.y * 128, bn = blockIdx.x * 128;
    int wm = (wid & 1) * 64, wn = (wid >> 1) * 32;

    float acc[4][4][4];
    #pragma unroll
    for (int i = 0; i < 4; i++)
        #pragma unroll
        for (int j = 0; j < 4; j++)
            #pragma unroll
            for (int r = 0; r < 4; r++) acc[i][j][r] = 0.f;

    int lr = tid >> 3;                // 0..31
    int lcw = (tid & 7) * 4;          // word offset 0..28

    const int nk1 = K1 >> 6;
    const int nk  = nk1 + (K2 >> 6);

    auto prefetch = [&](int it, int st) {
        const __half* Ab; const __half* Bb; int la, lb, k0;
        if (it < nk1) { Ab = A;  Bb = Bt;  la = lda;  lb = ldb;  k0 = it << 6; }
        else          { Ab = A2; Bb = Bt2; la = lda2; lb = ldb2; k0 = (it - nk1) << 6; }
        uint32_t dA = sbase + (uint32_t)st * STAGEW * 4;
        uint32_t dB = dA + ABUFW * 4;
        #pragma unroll
        for (int i = 0; i < 4; i++) {
            int r = i * 32 + lr;
            CP_CG(dA + (uint32_t)(r * SSTRW + lcw) * 4, Ab + (size_t)(bm + r) * la + k0 + lcw * 2);
            CP_CG(dB + (uint32_t)(r * SSTRW + lcw) * 4, Bb + (size_t)(bn + r) * lb + k0 + lcw * 2);
        }
        CP_COMMIT();
    };

    prefetch(0, 0);
    if (nk > 1) prefetch(1, 1);

    for (int it = 0; it < nk; it++) {
        int st = it % 3;
        if (it + 2 < nk) { prefetch(it + 2, (it + 2) % 3); CP_WAIT(2); }
        else if (it + 1 < nk) { CP_WAIT(1); }
        else { CP_WAIT(0); }
        __syncthreads();

        const uint32_t* sA = smw + st * STAGEW;
        const uint32_t* sB = sA + ABUFW;

        #pragma unroll
        for (int kk = 0; kk < 4; kk++) {
            int k8 = kk * 8;
            uint32_t af[4][4], bf[4][2];
            #pragma unroll
            for (int mt = 0; mt < 4; mt++) {
                int row = wm + mt * 16 + quad;
                af[mt][0] = sA[(row    ) * SSTRW + k8 + tig    ];
                af[mt][1] = sA[(row + 8) * SSTRW + k8 + tig    ];
                af[mt][2] = sA[(row    ) * SSTRW + k8 + tig + 4];
                af[mt][3] = sA[(row + 8) * SSTRW + k8 + tig + 4];
            }
            #pragma unroll
            for (int nt = 0; nt < 4; nt++) {
                int col = wn + nt * 8 + quad;
                bf[nt][0] = sB[col * SSTRW + k8 + tig    ];
                bf[nt][1] = sB[col * SSTRW + k8 + tig + 4];
            }
            #pragma unroll
            for (int mt = 0; mt < 4; mt++)
                #pragma unroll
                for (int nt = 0; nt < 4; nt++)
                    mma_f16(acc[mt][nt][0], acc[mt][nt][1],
                            acc[mt][nt][2], acc[mt][nt][3],
                            af[mt][0], af[mt][1], af[mt][2], af[mt][3],
                            bf[nt][0], bf[nt][1]);
        }
        __syncthreads();
    }

    // region for mode 1 (per-CTA uniform: boundaries are multiples of 128)
    int region = (mode != 1) ? 0 : ((bn < 2 * DIMC) ? 0 : (bn < 3 * DIMC ? 1 : 2));

    #pragma unroll
    for (int mt = 0; mt < 4; mt++) {
        int r0 = bm + wm + mt * 16 + quad;
        #pragma unroll
        for (int nt = 0; nt < 4; nt++) {
            int c = bn + wn + nt * 8 + tig * 2;
            float2 v0 = make_float2(acc[mt][nt][0], acc[mt][nt][1]);
            float2 v1 = make_float2(acc[mt][nt][2], acc[mt][nt][3]);
            if (bias) {
                float bx = (c     < nbias) ? bias[c]     : 0.f;
                float by = (c + 1 < nbias) ? bias[c + 1] : 0.f;
                v0.x += bx; v0.y += by;
                v1.x += bx; v1.y += by;
            }
            if (mode == 2) {
                float2 ra = *reinterpret_cast<const float2*>(resid + (size_t)r0 * ldr + c);
                float2 rb = *reinterpret_cast<const float2*>(resid + (size_t)(r0 + 8) * ldr + c);
                v0.x += ra.x; v0.y += ra.y;
                v1.x += rb.x; v1.y += rb.y;
                *reinterpret_cast<float2*>(Cf + (size_t)r0 * ldcf + c) = v0;
                *reinterpret_cast<float2*>(Cf + (size_t)(r0 + 8) * ldcf + c) = v1;
            } else if (mode == 1 && region == 1) {
                // V -> g_vt transposed: vt[((bb*16+h)*64+d)*2048 + n]
                int d = c - 2 * DIMC;
                int hh = d >> 6, dd = d & 63;
                int bbk = r0 >> 11, nn = r0 & 2047;
                size_t base = ((size_t)(bbk * NHEADS + hh) * DHEAD);
                g_vt[(base + dd    ) * NSEQ + nn    ] = __float2half(v0.x);
                g_vt[(base + dd + 1) * NSEQ + nn    ] = __float2half(v0.y);
                g_vt[(base + dd    ) * NSEQ + nn + 8] = __float2half(v1.x);
                g_vt[(base + dd + 1) * NSEQ + nn + 8] = __float2half(v1.y);
            } else {
                if (mode == 1 && region == 2) {
                    v0.x = gelu1(v0.x); v0.y = gelu1(v0.y);
                    v1.x = gelu1(v1.x); v1.y = gelu1(v1.y);
                }
                *reinterpret_cast<uint32_t*>(Ch + (size_t)r0 * ldch + c) = h2pack(v0.x, v0.y);
                *reinterpret_cast<uint32_t*>(Ch + (size_t)(r0 + 8) * ldch + c) = h2pack(v1.x, v1.y);
            }
        }
    }
}

// ============================================================
// Per-head Q/K layernorm on half data; q rows scaled by 0.125
// ============================================================
__global__ void qkln_kernel(__half* __restrict__ fused,
                            const float* __restrict__ qg, const float* __restrict__ qb,
                            const float* __restrict__ kg, const float* __restrict__ kb)
{
    int gid   = blockIdx.x * 8 + (threadIdx.x >> 5);
    int lane  = threadIdx.x & 31;
    int token = gid >> 5;
    int rem   = gid & 31;
    int qk    = rem >> 4;
    int head  = rem & 15;

    __half* p = fused + (size_t)token * FWP + qk * DIMC + head * DHEAD;
    float v0 = __half2float(p[lane]);
    float v1 = __half2float(p[lane + 32]);

    float s = v0 + v1;
    #pragma unroll
    for (int o = 16; o > 0; o >>= 1) s += __shfl_xor_sync(0xffffffffu, s, o);
    float mean = s * (1.f / 64.f);

    float d0 = v0 - mean, d1 = v1 - mean;
    float sq = d0 * d0 + d1 * d1;
    #pragma unroll
    for (int o = 16; o > 0; o >>= 1) sq += __shfl_xor_sync(0xffffffffu, sq, o);
    float rstd = rsqrtf(sq * (1.f / 64.f) + LN_EPS);

    const float* g = qk ? kg : qg;
    const float* b = qk ? kb : qb;
    float sc = qk ? 1.f : 0.125f;
    p[lane]      = __float2half((d0 * rstd * g[lane]      + b[lane])      * sc);
    p[lane + 32] = __float2half((d1 * rstd * g[lane + 32] + b[lane + 32]) * sc);
}

// ============================================================
// Flash attention, fp16 m16n8k16, cp.async double-buffered K/Vt.
// Q persistent (16 regs); V pre-transposed in g_vt; P patch in Q rows.
// ============================================================
#define KSTRW 36                        // word stride (72 halves)
#define QWORDS (128 * KSTRW)            // 4608 words
#define KVWORDS (64 * KSTRW)            // 2304 words per matrix
#define ATTN_SMEM ((QWORDS + 4 * KVWORDS) * 4)   // 55296 B

__global__ void __launch_bounds__(256, 2)
fattn_kernel(const __half* __restrict__ fused, __half* __restrict__ aout)
{
    extern __shared__ uint32_t smw[];
    uint32_t sbase = smem_u32(smw);

    int tid  = threadIdx.x;
    int wid  = tid >> 5, lane = tid & 31;
    int quad = lane >> 2, tig = lane & 3;
    int h  = blockIdx.y;
    int bb = blockIdx.z;
    int q0 = blockIdx.x * 128;
    int tq0 = bb * NSEQ + q0;
    int kvb = bb * NSEQ;
    const __half* vtb = g_vt + (size_t)(bb * NHEADS + h) * DHEAD * NSEQ;

    auto prefetch_kv = [&](int kt, int buf) {
        uint32_t dK = sbase + (uint32_t)(QWORDS + buf * 2 * KVWORDS) * 4;
        uint32_t dV = dK + KVWORDS * 4;
        #pragma unroll
        for (int i = 0; i < 2; i++) {
            int idx = i * 256 + tid;          // 0..511
            int r = idx >> 3, ch = (idx & 7) * 8;   // row, half offset
            CP_CG(dK + (uint32_t)(r * KSTRW + ch / 2) * 4,
                  fused + (size_t)(kvb + kt + r) * FWP + DIMC + h * DHEAD + ch);
            CP_CG(dV + (uint32_t)(r * KSTRW + ch / 2) * 4,
                  vtb + (size_t)r * NSEQ + kt + ch);
        }
        CP_COMMIT();
    };

    // Q tile (128 x 64 halves)
    #pragma unroll
    for (int i = 0; i < 4; i++) {
        int idx = i * 256 + tid;              // 0..1023
        int r = idx >> 3, ch = (idx & 7) * 8;
        CP_CA(sbase + (uint32_t)(r * KSTRW + ch / 2) * 4,
              fused + (size_t)(tq0 + r) * FWP + h * DHEAD + ch);
    }
    prefetch_kv(0, 0);
    CP_WAIT(0);
    __syncthreads();

    // persistent Q fragments: 4 k16 steps x 4 regs
    uint32_t qf[4][4];
    {
        int r0 = wid * 16 + quad;
        #pragma unroll
        for (int kc = 0; kc < 4; kc++) {
            qf[kc][0] = smw[(r0    ) * KSTRW + kc * 8 + tig    ];
            qf[kc][1] = smw[(r0 + 8) * KSTRW + kc * 8 + tig    ];
            qf[kc][2] = smw[(r0    ) * KSTRW + kc * 8 + tig + 4];
            qf[kc][3] = smw[(r0 + 8) * KSTRW + kc * 8 + tig + 4];
        }
    }
    // per-warp P patch reuses this warp's Q rows
    uint32_t* sP = smw + wid * 16 * KSTRW;

    float o[8][4];
    #pragma unroll
    for (int i = 0; i < 8; i++)
        #pragma unroll
        for (int j = 0; j < 4; j++) o[i][j] = 0.f;
    float m0 = -1e30f, m1 = -1e30f, l0 = 0.f, l1 = 0.f;

    for (int t = 0; t < NSEQ / 64; t++) {
        int b = t & 1;
        if (t + 1 < NSEQ / 64) prefetch_kv((t + 1) * 64, b ^ 1);

        const uint32_t* uK = smw + QWORDS + b * 2 * KVWORDS;
        const uint32_t* uV = uK + KVWORDS;

        float sc[8][4];
        #pragma unroll
        for (int i = 0; i < 8; i++)
            #pragma unroll
            for (int j = 0; j < 4; j++) sc[i][j] = 0.f;

        #pragma unroll
        for (int kc = 0; kc < 4; kc++) {
            int k8 = kc * 8 + tig;
            #pragma unroll
            for (int nf = 0; nf < 8; nf++) {
                uint32_t b0 = uK[(nf * 8 + quad) * KSTRW + k8    ];
                uint32_t b1 = uK[(nf * 8 + quad) * KSTRW + k8 + 4];
                mma_f16(sc[nf][0], sc[nf][1], sc[nf][2], sc[nf][3],
                        qf[kc][0], qf[kc][1], qf[kc][2], qf[kc][3], b0, b1);
            }
        }

        float rm0 = -1e30f, rm1 = -1e30f;
        #pragma unroll
        for (int nf = 0; nf < 8; nf++) {
            rm0 = fmaxf(rm0, fmaxf(sc[nf][0], sc[nf][1]));
            rm1 = fmaxf(rm1, fmaxf(sc[nf][2], sc[nf][3]));
        }
        rm0 = fmaxf(rm0, __shfl_xor_sync(0xffffffffu, rm0, 1));
        rm0 = fmaxf(rm0, __shfl_xor_sync(0xffffffffu, rm0, 2));
        rm1 = fmaxf(rm1, __shfl_xor_sync(0xffffffffu, rm1, 1));
        rm1 = fmaxf(rm1, __shfl_xor_sync(0xffffffffu, rm1, 2));

        float mn0 = fmaxf(m0, rm0), mn1 = fmaxf(m1, rm1);
        float c0 = __expf(m0 - mn0), c1 = __expf(m1 - mn1);
        m0 = mn0; m1 = mn1;

        float rs0 = 0.f, rs1 = 0.f;
        #pragma unroll
        for (int nf = 0; nf < 8; nf++) {
            float p0 = __expf(sc[nf][0] - m0);
            float p1 = __expf(sc[nf][1] - m0);
            float p2 = __expf(sc[nf][2] - m1);
            float p3 = __expf(sc[nf][3] - m1);
            rs0 += p0 + p1; rs1 += p2 + p3;
            // P store: half2 of adjacent keys at word quad*36 + nf*4 + tig
            sP[(quad    ) * KSTRW + nf * 4 + tig] = h2pack(p0, p1);
            sP[(quad + 8) * KSTRW + nf * 4 + tig] = h2pack(p2, p3);
        }
        rs0 += __shfl_xor_sync(0xffffffffu, rs0, 1);
        rs0 += __shfl_xor_sync(0xffffffffu, rs0, 2);
        rs1 += __shfl_xor_sync(0xffffffffu, rs1, 1);
        rs1 += __shfl_xor_sync(0xffffffffu, rs1, 2);
        l0 = l0 * c0 + rs0;
        l1 = l1 * c1 + rs1;

        #pragma unroll
        for (int nf = 0; nf < 8; nf++) {
            o[nf][0] *= c0; o[nf][1] *= c0;
            o[nf][2] *= c1; o[nf][3] *= c1;
        }
        __syncwarp();

        // O += P @ V  (A from sP, B from transposed V)
        #pragma unroll
        for (int kc = 0; kc < 4; kc++) {
            int k8 = kc * 8 + tig;
            uint32_t a0 = sP[(quad    ) * KSTRW + k8    ];
            uint32_t a1 = sP[(quad + 8) * KSTRW + k8    ];
            uint32_t a2 = sP[(quad    ) * KSTRW + k8 + 4];
            uint32_t a3 = sP[(quad + 8) * KSTRW + k8 + 4];
            #pragma unroll
            for (int nf = 0; nf < 8; nf++) {
                uint32_t b0 = uV[(nf * 8 + quad) * KSTRW + k8    ];
                uint32_t b1 = uV[(nf * 8 + quad) * KSTRW + k8 + 4];
                mma_f16(o[nf][0], o[nf][1], o[nf][2], o[nf][3],
                        a0, a1, a2, a3, b0, b1);
            }
        }
        __syncwarp();

        if (t + 1 < NSEQ / 64) { CP_WAIT(0); }
        __syncthreads();
    }

    float il0 = 1.f / l0, il1 = 1.f / l1;
    int r0 = tq0 + wid * 16 + quad;
    #pragma unroll
    for (int nf = 0; nf < 8; nf++) {
        int c = h * DHEAD + nf * 8 + tig * 2;
        *reinterpret_cast<uint32_t*>(aout + (size_t)r0 * DIMC + c) =
            h2pack(o[nf][0] * il0, o[nf][1] * il0);
        *reinterpret_cast<uint32_t*>(aout + (size_t)(r0 + 8) * DIMC + c) =
            h2pack(o[nf][2] * il1, o[nf][3] * il1);
    }
}

// ============================================================
// launch
// ============================================================
extern "C" void kernel_launch(void* const* d_in, const int* in_sizes, int n_in,
                              void* d_out, int out_size)
{
    const float* x      = (const float*)d_in[0];
    const float* norm_g = (const float*)d_in[1];
    const float* norm_b = (const float*)d_in[2];
    const float* W1     = (const float*)d_in[3];
    const float* b1     = (const float*)d_in[4];
    const float* qn_g   = (const float*)d_in[5];
    const float* qn_b   = (const float*)d_in[6];
    const float* kn_g   = (const float*)d_in[7];
    const float* kn_b   = (const float*)d_in[8];
    const float* Wao    = (const float*)d_in[9];
    const float* bao    = (const float*)d_in[10];
    const float* Wmo    = (const float*)d_in[11];
    const float* bmo    = (const float*)d_in[12];
    const float* W2     = (const float*)d_in[13];
    const float* b2     = (const float*)d_in[14];
    float*       out    = (float*)d_out;

    __half *norm, *fused, *attn, *w1t, *w2t, *waor, *wmor, *wfa, *wfm;
    float *beff;
    cudaGetSymbolAddress((void**)&norm,  g_norm);
    cudaGetSymbolAddress((void**)&fused, g_fused);
    cudaGetSymbolAddress((void**)&attn,  g_attn);
    cudaGetSymbolAddress((void**)&w1t,   g_w1t);
    cudaGetSymbolAddress((void**)&w2t,   g_w2t);
    cudaGetSymbolAddress((void**)&waor,  g_waor);
    cudaGetSymbolAddress((void**)&wmor,  g_wmor);
    cudaGetSymbolAddress((void**)&wfa,   g_wfa);
    cudaGetSymbolAddress((void**)&wfm,   g_wfm);
    cudaGetSymbolAddress((void**)&beff,  g_beff);

    cudaFuncSetAttribute(mma_gemm, cudaFuncAttributeMaxDynamicSharedMemorySize, GEMM_SMEM);
    cudaFuncSetAttribute(fattn_kernel, cudaFuncAttributeMaxDynamicSharedMemorySize, ATTN_SMEM);

    dim3 tblk(32, 8);

    // weight prep (half)
    transpose_kernel<<<dim3(FWP / 32, DIMC / 32), tblk>>>(W1, DIMC, FW, w1t, DIMC, FWP);
    transpose_kernel<<<dim3(DIMC / 32, 2 * DIMC / 32), tblk>>>(W2, 2 * DIMC, DIMC, w2t, 2 * DIMC, DIMC);
    roundcopy_kernel<<<(DIMC * DIMC) / 256, 256>>>(Wao, DIMC, waor);
    roundcopy_kernel<<<(HIDPAD * DIMC) / 256, 256>>>(Wmo, MLPHID, wmor);
    beff_part<<<dim3(DIMC / 256, NSLICE), 256>>>(bao, bmo, b2, W2);
    beff_red<<<DIMC / 256, 256>>>(beff);

    // weight folds (mode 0)
    mma_gemm<<<dim3(DIMC / 128, DIMC / 128), 256, GEMM_SMEM>>>(
        w2t, 2 * DIMC, waor, DIMC, DIMC,
        nullptr, 0, nullptr, 0, 0,
        wfa, DIMC, nullptr, 0, nullptr, 0, nullptr, 0, 0);
    mma_gemm<<<dim3(HIDPAD / 128, DIMC / 128), 256, GEMM_SMEM>>>(
        w2t + DIMC, 2 * DIMC, wmor, DIMC, DIMC,
        nullptr, 0, nullptr, 0, 0,
        wfm, HIDPAD, nullptr, 0, nullptr, 0, nullptr, 0, 0);

    // 1) layernorm(x) -> half
    ln_kernel<<<NTOK, 256>>>(x, norm_g, norm_b, norm);

    // 2) fused = norm @ W1 + b1; qk->fused, V->g_vt transposed, mlp->gelu->fused
    mma_gemm<<<dim3(FWP / 128, NTOK / 128), 256, GEMM_SMEM>>>(
        norm, DIMC, w1t, DIMC, DIMC,
        nullptr, 0, nullptr, 0, 0,
        fused, FWP, nullptr, 0, b1, FW, nullptr, 0, 1);

    // 3) per-head LN on q/k (q scaled by 0.125)
    qkln_kernel<<<(NTOK * 32) / 8, 256>>>(fused, qn_g, qn_b, kn_g, kn_b);

    // 4) flash attention (fp16)
    fattn_kernel<<<dim3(NSEQ / 128, NHEADS, 2), 256, ATTN_SMEM>>>(fused, attn);

    // 5) out = x + attn @ wfa^T + gelu_hidden @ wfm^T + beff  (merged, mode 2)
    mma_gemm<<<dim3(DIMC / 128, NTOK / 128), 256, GEMM_SMEM>>>(
        attn, DIMC, wfa, DIMC, DIMC,
        fused + 3 * DIMC, FWP, wfm, HIDPAD, HIDPAD,
        nullptr, 0, out, DIMC, beff, DIMC, x, DIMC, 2);
}

// round 8
// speedup vs baseline: 7.6429x; 1.0719x over previous
#include <cuda_runtime.h>
#include <cuda_fp16.h>
#include <math.h>
#include <stdint.h>

// ---------------- problem constants ----------------
#define NTOK   4096              // B*N = 2*2048
#define DIMC   1024
#define NHEADS 16
#define DHEAD  64
#define MLPHID 716
#define FW     3788              // 3*DIM + MLP_HID (true width)
#define FWP    3840              // padded to 30*128
#define HIDPAD 768               // Wmo rows padded; K2 of apply
#define NSEQ   2048
#define LN_EPS 1e-6f
#define NSLICE 16

// ---------------- scratch (static device globals) ------
__device__ __half g_norm [NTOK * DIMC];
__device__ __half g_fused[NTOK * FWP];
__device__ __half g_vt   [2 * NHEADS * DHEAD * NSEQ];   // V transposed [b][h][d][n]
__device__ __half g_attn [NTOK * DIMC];
__device__ __half g_w1t  [FWP  * DIMC];
__device__ __half g_w2t  [DIMC * 2 * DIMC];
__device__ __half g_waor [DIMC * DIMC];
__device__ __half g_wmor [HIDPAD * DIMC];
__device__ __half g_wfa  [DIMC * DIMC];
__device__ __half g_wfm  [DIMC * HIDPAD];
__device__ float  g_beff [DIMC];
__device__ float  g_beffp[NSLICE * DIMC];

// ================= helpers =================
__device__ __forceinline__ uint32_t smem_u32(const void* p) {
    uint32_t a;
    asm("{ .reg .u64 t; cvta.to.shared.u64 t, %1; cvt.u32.u64 %0, t; }" : "=r"(a) : "l"(p));
    return a;
}
__device__ __forceinline__ void mma_f16(float& d0, float& d1, float& d2, float& d3,
                                        uint32_t a0, uint32_t a1, uint32_t a2, uint32_t a3,
                                        uint32_t b0, uint32_t b1)
{
    asm volatile(
        "mma.sync.aligned.m16n8k16.row.col.f32.f16.f16.f32 "
        "{%0,%1,%2,%3}, {%4,%5,%6,%7}, {%8,%9}, {%0,%1,%2,%3};"
        : "+f"(d0), "+f"(d1), "+f"(d2), "+f"(d3)
        : "r"(a0), "r"(a1), "r"(a2), "r"(a3), "r"(b0), "r"(b1));
}
__device__ __forceinline__ void ldsm4(uint32_t& r0, uint32_t& r1, uint32_t& r2, uint32_t& r3,
                                      uint32_t addr)
{
    asm volatile("ldmatrix.sync.aligned.m8n8.x4.shared.b16 {%0,%1,%2,%3}, [%4];"
                 : "=r"(r0), "=r"(r1), "=r"(r2), "=r"(r3) : "r"(addr));
}
__device__ __forceinline__ void stsm4(uint32_t addr, uint32_t r0, uint32_t r1,
                                      uint32_t r2, uint32_t r3)
{
    asm volatile("stmatrix.sync.aligned.m8n8.x4.shared.b16 [%0], {%1,%2,%3,%4};"
                 :: "r"(addr), "r"(r0), "r"(r1), "r"(r2), "r"(r3) : "memory");
}
__device__ __forceinline__ float gelu1(float x) {
    float u = 0.7978845608028654f * (x + 0.044715f * x * x * x);
    return 0.5f * x * (1.f + tanhf(u));
}
__device__ __forceinline__ uint32_t h2pack(float a, float b) {
    __half2 h = __floats2half2_rn(a, b);
    return *reinterpret_cast<uint32_t*>(&h);
}
#define CP_CA(dst, src) asm volatile("cp.async.ca.shared.global [%0], [%1], 16;" :: "r"(dst), "l"(src) : "memory")
#define CP_CG(dst, src) asm volatile("cp.async.cg.shared.global [%0], [%1], 16;" :: "r"(dst), "l"(src) : "memory")
#define CP_COMMIT()     asm volatile("cp.async.commit_group;" ::: "memory")
#define CP_WAIT(n)      asm volatile("cp.async.wait_group %0;" :: "n"(n) : "memory")

// ============================================================
// merged prep: W1^T, W2^T, Wao copy, Wmo copy(pad), beff partials
// all as one launch; 256 threads per CTA
// blocks: [0,3840) W1t | [3840,5888) W2t | [5888,9984) Wao |
//         [9984,13056) Wmo | [13056,13120) beff_part
// ============================================================
__global__ void prep_kernel(const float* __restrict__ W1,
                            const float* __restrict__ W2,
                            const float* __restrict__ Wao,
                            const float* __restrict__ Wmo,
                            const float* __restrict__ bao,
                            const float* __restrict__ bmo,
                            const float* __restrict__ b2)
{
    __shared__ float t[32][33];
    int bid = blockIdx.x, tid = threadIdx.x;
    int tx = tid & 31, ty = tid >> 5;

    if (bid < 3840) {                       // W1 [1024 x 3788] -> w1t [3840][1024]
        int bx = bid % (FWP / 32), by = bid / (FWP / 32);
        int n0 = bx * 32, k0 = by * 32;
        #pragma unroll
        for (int i = 0; i < 32; i += 8) {
            int n = n0 + tx;
            t[ty + i][tx] = (n < FW) ? W1[(size_t)(k0 + ty + i) * FW + n] : 0.f;
        }
        __syncthreads();
        #pragma unroll
        for (int i = 0; i < 32; i += 8)
            g_w1t[(size_t)(n0 + ty + i) * DIMC + k0 + tx] = __float2half(t[tx][ty + i]);
    } else if (bid < 5888) {                // W2 [2048 x 1024] -> w2t [1024][2048]
        int b = bid - 3840;
        int bx = b % 32, by = b / 32;
        int n0 = bx * 32, k0 = by * 32;
        #pragma unroll
        for (int i = 0; i < 32; i += 8)
            t[ty + i][tx] = W2[(size_t)(k0 + ty + i) * DIMC + n0 + tx];
        __syncthreads();
        #pragma unroll
        for (int i = 0; i < 32; i += 8)
            g_w2t[(size_t)(n0 + ty + i) * 2 * DIMC + k0 + tx] = __float2half(t[tx][ty + i]);
    } else if (bid < 9984) {                // Wao copy (1024x1024)
        int idx = (bid - 5888) * 256 + tid;
        g_waor[idx] = __float2half(Wao[idx]);
    } else if (bid < 13056) {               // Wmo copy (716->768 rows x1024)
        int idx = (bid - 9984) * 256 + tid;
        int r = idx >> 10, c = idx & 1023;
        g_wmor[idx] = (r < MLPHID) ? __float2half(Wmo[(size_t)r * DIMC + c])
                                   : __float2half(0.f);
    } else {                                // beff partials
        int b = bid - 13056;                // 0..63
        int n = (b & 3) * 256 + tid;
        int s = b >> 2;
        float acc = (s == 0) ? b2[n] : 0.f;
        int k0 = s * (2048 / NSLICE), k1 = k0 + (2048 / NSLICE);
        for (int k = k0; k < k1; k++) {
            float c = (k < 1024) ? bao[k] : bmo[k - 1024];
            acc += c * W2[(size_t)k * DIMC + n];
        }
        g_beffp[s * DIMC + n] = acc;
    }
}

__global__ void beff_red(float* __restrict__ beff)
{
    int n = blockIdx.x * 256 + threadIdx.x;
    float s = 0.f;
    #pragma unroll
    for (int i = 0; i < NSLICE; i++) s += g_beffp[i * DIMC + n];
    beff[n] = s;
}

// ============================================================
// LayerNorm over DIM=1024, half output
// ============================================================
__global__ void ln_kernel(const float* __restrict__ x,
                          const float* __restrict__ g,
                          const float* __restrict__ b,
                          __half* __restrict__ out)
{
    int row = blockIdx.x;
    int tid = threadIdx.x;
    const float4 v = reinterpret_cast<const float4*>(x + (size_t)row * DIMC)[tid];

    float s  = v.x + v.y + v.z + v.w;
    float sq = v.x*v.x + v.y*v.y + v.z*v.z + v.w*v.w;
    #pragma unroll
    for (int o = 16; o > 0; o >>= 1) {
        s  += __shfl_xor_sync(0xffffffffu, s,  o);
        sq += __shfl_xor_sync(0xffffffffu, sq, o);
    }
    __shared__ float ws[8], wq[8];
    int warp = tid >> 5, lane = tid & 31;
    if (lane == 0) { ws[warp] = s; wq[warp] = sq; }
    __syncthreads();
    if (warp == 0) {
        float s2  = (lane < 8) ? ws[lane] : 0.f;
        float sq2 = (lane < 8) ? wq[lane] : 0.f;
        #pragma unroll
        for (int o = 4; o > 0; o >>= 1) {
            s2  += __shfl_xor_sync(0xffffffffu, s2,  o);
            sq2 += __shfl_xor_sync(0xffffffffu, sq2, o);
        }
        if (lane == 0) { ws[0] = s2; wq[0] = sq2; }
    }
    __syncthreads();
    float mean = ws[0] * (1.f / DIMC);
    float var  = wq[0] * (1.f / DIMC) - mean * mean;
    float rstd = rsqrtf(var + LN_EPS);

    float4 gg = reinterpret_cast<const float4*>(g)[tid];
    float4 bb = reinterpret_cast<const float4*>(b)[tid];
    uint2 o2;
    o2.x = h2pack((v.x - mean) * rstd * gg.x + bb.x,
                  (v.y - mean) * rstd * gg.y + bb.y);
    o2.y = h2pack((v.z - mean) * rstd * gg.z + bb.z,
                  (v.w - mean) * rstd * gg.w + bb.w);
    reinterpret_cast<uint2*>(out + (size_t)row * DIMC)[tid] = o2;
}

// ============================================================
// fp16 mma.sync GEMM, 3-stage cp.async pipeline, ldmatrix frags.
// mode 0: C half   mode 1: GEMM1 (qk half / V->g_vt / gelu)   mode 2: C float+resid
// ============================================================
#define SSTRW 36
#define ABUFW (128 * SSTRW)
#define STAGEW (2 * ABUFW)
#define GEMM_SMEM (3 * STAGEW * 4)   // 110592 B

__global__ void __launch_bounds__(256, 2)
mma_gemm(const __half* __restrict__ A, int lda,
         const __half* __restrict__ Bt, int ldb, int K1,
         const __half* __restrict__ A2, int lda2,
         const __half* __restrict__ Bt2, int ldb2, int K2,
         __half* __restrict__ Ch, int ldch,
         float* __restrict__ Cf, int ldcf,
         const float* __restrict__ bias, int nbias,
         const float* __restrict__ resid, int ldr,
         int mode)
{
    extern __shared__ uint32_t smw[];
    uint32_t sbase = smem_u32(smw);
    int tid  = threadIdx.x;
    int wid  = tid >> 5, lane = tid & 31;
    int quad = lane >> 2, tig = lane & 3;
    int bm = blockIdx.y * 128, bn = blockIdx.x * 128;
    int wm = (wid & 1) * 64, wn = (wid >> 1) * 32;

    float acc[4][4][4];
    #pragma unroll
    for (int i = 0; i < 4; i++)
        #pragma unroll
        for (int j = 0; j < 4; j++)
            #pragma unroll
            for (int r = 0; r < 4; r++) acc[i][j][r] = 0.f;

    int lr = tid >> 3;
    int lcw = (tid & 7) * 4;

    // ldmatrix lane-relative byte offsets
    int lane15 = lane & 15;
    uint32_t aoff[4];
    #pragma unroll
    for (int mt = 0; mt < 4; mt++)
        aoff[mt] = (uint32_t)((wm + mt * 16 + lane15) * SSTRW) * 4 + (lane >> 4) * 16;
    uint32_t boff0 = (uint32_t)((wn + ((lane >> 4) << 3) + (lane & 7)) * SSTRW) * 4
                   + ((lane >> 3) & 1) * 16;
    uint32_t boff1 = boff0 + 16 * SSTRW * 4;

    const int nk1 = K1 >> 6;
    const int nk  = nk1 + (K2 >> 6);

    auto prefetch = [&](int it, int st) {
        const __half* Ab; const __half* Bb; int la, lb, k0;
        if (it < nk1) { Ab = A;  Bb = Bt;  la = lda;  lb = ldb;  k0 = it << 6; }
        else          { Ab = A2; Bb = Bt2; la = lda2; lb = ldb2; k0 = (it - nk1) << 6; }
        uint32_t dA = sbase + (uint32_t)st * STAGEW * 4;
        uint32_t dB = dA + ABUFW * 4;
        #pragma unroll
        for (int i = 0; i < 4; i++) {
            int r = i * 32 + lr;
            CP_CG(dA + (uint32_t)(r * SSTRW + lcw) * 4, Ab + (size_t)(bm + r) * la + k0 + lcw * 2);
            CP_CG(dB + (uint32_t)(r * SSTRW + lcw) * 4, Bb + (size_t)(bn + r) * lb + k0 + lcw * 2);
        }
        CP_COMMIT();
    };

    prefetch(0, 0);
    if (nk > 1) prefetch(1, 1);

    for (int it = 0; it < nk; it++) {
        int st = it % 3;
        if (it + 2 < nk) { prefetch(it + 2, (it + 2) % 3); CP_WAIT(2); }
        else if (it + 1 < nk) { CP_WAIT(1); }
        else { CP_WAIT(0); }
        __syncthreads();

        uint32_t stA = sbase + (uint32_t)st * STAGEW * 4;
        uint32_t stB = stA + ABUFW * 4;

        #pragma unroll
        for (int kk = 0; kk < 4; kk++) {
            uint32_t af[4][4], bf[4][2];
            #pragma unroll
            for (int mt = 0; mt < 4; mt++)
                ldsm4(af[mt][0], af[mt][1], af[mt][2], af[mt][3],
                      stA + aoff[mt] + kk * 32);
            ldsm4(bf[0][0], bf[0][1], bf[1][0], bf[1][1], stB + boff0 + kk * 32);
            ldsm4(bf[2][0], bf[2][1], bf[3][0], bf[3][1], stB + boff1 + kk * 32);
            #pragma unroll
            for (int mt = 0; mt < 4; mt++)
                #pragma unroll
                for (int nt = 0; nt < 4; nt++)
                    mma_f16(acc[mt][nt][0], acc[mt][nt][1],
                            acc[mt][nt][2], acc[mt][nt][3],
                            af[mt][0], af[mt][1], af[mt][2], af[mt][3],
                            bf[nt][0], bf[nt][1]);
        }
        __syncthreads();
    }

    int region = (mode != 1) ? 0 : ((bn < 2 * DIMC) ? 0 : (bn < 3 * DIMC ? 1 : 2));

    #pragma unroll
    for (int mt = 0; mt < 4; mt++) {
        int r0 = bm + wm + mt * 16 + quad;
        #pragma unroll
        for (int nt = 0; nt < 4; nt++) {
            int c = bn + wn + nt * 8 + tig * 2;
            float2 v0 = make_float2(acc[mt][nt][0], acc[mt][nt][1]);
            float2 v1 = make_float2(acc[mt][nt][2], acc[mt][nt][3]);
            if (bias) {
                float bx = (c     < nbias) ? bias[c]     : 0.f;
                float by = (c + 1 < nbias) ? bias[c + 1] : 0.f;
                v0.x += bx; v0.y += by;
                v1.x += bx; v1.y += by;
            }
            if (mode == 2) {
                float2 ra = *reinterpret_cast<const float2*>(resid + (size_t)r0 * ldr + c);
                float2 rb = *reinterpret_cast<const float2*>(resid + (size_t)(r0 + 8) * ldr + c);
                v0.x += ra.x; v0.y += ra.y;
                v1.x += rb.x; v1.y += rb.y;
                *reinterpret_cast<float2*>(Cf + (size_t)r0 * ldcf + c) = v0;
                *reinterpret_cast<float2*>(Cf + (size_t)(r0 + 8) * ldcf + c) = v1;
            } else if (mode == 1 && region == 1) {
                int d = c - 2 * DIMC;
                int hh = d >> 6, dd = d & 63;
                int bbk = r0 >> 11, nn = r0 & 2047;
                size_t base = ((size_t)(bbk * NHEADS + hh) * DHEAD);
                g_vt[(base + dd    ) * NSEQ + nn    ] = __float2half(v0.x);
                g_vt[(base + dd + 1) * NSEQ + nn    ] = __float2half(v0.y);
                g_vt[(base + dd    ) * NSEQ + nn + 8] = __float2half(v1.x);
                g_vt[(base + dd + 1) * NSEQ + nn + 8] = __float2half(v1.y);
            } else {
                if (mode == 1 && region == 2) {
                    v0.x = gelu1(v0.x); v0.y = gelu1(v0.y);
                    v1.x = gelu1(v1.x); v1.y = gelu1(v1.y);
                }
                *reinterpret_cast<uint32_t*>(Ch + (size_t)r0 * ldch + c) = h2pack(v0.x, v0.y);
                *reinterpret_cast<uint32_t*>(Ch + (size_t)(r0 + 8) * ldch + c) = h2pack(v1.x, v1.y);
            }
        }
    }
}

// ============================================================
// Per-head Q/K layernorm on half data; q rows scaled by 0.125
// ============================================================
__global__ void qkln_kernel(__half* __restrict__ fused,
                            const float* __restrict__ qg, const float* __restrict__ qb,
                            const float* __restrict__ kg, const float* __restrict__ kb)
{
    int gid   = blockIdx.x * 8 + (threadIdx.x >> 5);
    int lane  = threadIdx.x & 31;
    int token = gid >> 5;
    int rem   = gid & 31;
    int qk    = rem >> 4;
    int head  = rem & 15;

    __half* p = fused + (size_t)token * FWP + qk * DIMC + head * DHEAD;
    float v0 = __half2float(p[lane]);
    float v1 = __half2float(p[lane + 32]);

    float s = v0 + v1;
    #pragma unroll
    for (int o = 16; o > 0; o >>= 1) s += __shfl_xor_sync(0xffffffffu, s, o);
    float mean = s * (1.f / 64.f);

    float d0 = v0 - mean, d1 = v1 - mean;
    float sq = d0 * d0 + d1 * d1;
    #pragma unroll
    for (int o = 16; o > 0; o >>= 1) sq += __shfl_xor_sync(0xffffffffu, sq, o);
    float rstd = rsqrtf(sq * (1.f / 64.f) + LN_EPS);

    const float* g = qk ? kg : qg;
    const float* b = qk ? kb : qb;
    float sc = qk ? 1.f : 0.125f;
    p[lane]      = __float2half((d0 * rstd * g[lane]      + b[lane])      * sc);
    p[lane + 32] = __float2half((d1 * rstd * g[lane + 32] + b[lane + 32]) * sc);
}

// ============================================================
// Flash attention, fp16 m16n8k16, ldmatrix/stmatrix fragments.
// ============================================================
#define KSTRW 36
#define QWORDS (128 * KSTRW)
#define KVWORDS (64 * KSTRW)
#define ATTN_SMEM ((QWORDS + 4 * KVWORDS) * 4)   // 55296 B

__global__ void __launch_bounds__(256, 2)
fattn_kernel(const __half* __restrict__ fused, __half* __restrict__ aout)
{
    extern __shared__ uint32_t smw[];
    uint32_t sbase = smem_u32(smw);

    int tid  = threadIdx.x;
    int wid  = tid >> 5, lane = tid & 31;
    int quad = lane >> 2, tig = lane & 3;
    int lane15 = lane & 15;
    int h  = blockIdx.y;
    int bb = blockIdx.z;
    int q0 = blockIdx.x * 128;
    int tq0 = bb * NSEQ + q0;
    int kvb = bb * NSEQ;
    const __half* vtb = g_vt + (size_t)(bb * NHEADS + h) * DHEAD * NSEQ;

    auto prefetch_kv = [&](int kt, int buf) {
        uint32_t dK = sbase + (uint32_t)(QWORDS + buf * 2 * KVWORDS) * 4;
        uint32_t dV = dK + KVWORDS * 4;
        #pragma unroll
        for (int i = 0; i < 2; i++) {
            int idx = i * 256 + tid;
            int r = idx >> 3, ch = (idx & 7) * 8;
            CP_CG(dK + (uint32_t)(r * KSTRW + ch / 2) * 4,
                  fused + (size_t)(kvb + kt + r) * FWP + DIMC + h * DHEAD + ch);
            CP_CG(dV + (uint32_t)(r * KSTRW + ch / 2) * 4,
                  vtb + (size_t)r * NSEQ + kt + ch);
        }
        CP_COMMIT();
    };

    #pragma unroll
    for (int i = 0; i < 4; i++) {
        int idx = i * 256 + tid;
        int r = idx >> 3, ch = (idx & 7) * 8;
        CP_CA(sbase + (uint32_t)(r * KSTRW + ch / 2) * 4,
              fused + (size_t)(tq0 + r) * FWP + h * DHEAD + ch);
    }
    prefetch_kv(0, 0);
    CP_WAIT(0);
    __syncthreads();

    // A-operand ldmatrix offset pattern (16-row patch)
    uint32_t aPat = (uint32_t)(lane15 * KSTRW) * 4 + (lane >> 4) * 16;
    // B-operand ldmatrix pattern (16 n-rows, klo/khi)
    uint32_t bPat = (uint32_t)((((lane >> 4) << 3) + (lane & 7)) * KSTRW) * 4
                  + ((lane >> 3) & 1) * 16;
    // stmatrix pattern for P
    uint32_t sPat = (uint32_t)(((((lane >> 3) & 1) << 3) + (lane & 7)) * KSTRW) * 4
                  + (lane >> 4) * 16;

    // persistent Q fragments
    uint32_t qf[4][4];
    {
        uint32_t qbase = sbase + (uint32_t)(wid * 16 * KSTRW) * 4 + aPat;
        #pragma unroll
        for (int kc = 0; kc < 4; kc++)
            ldsm4(qf[kc][0], qf[kc][1], qf[kc][2], qf[kc][3], qbase + kc * 32);
    }
    uint32_t pBase = sbase + (uint32_t)(wid * 16 * KSTRW) * 4;   // per-warp P patch

    float o[8][4];
    #pragma unroll
    for (int i = 0; i < 8; i++)
        #pragma unroll
        for (int j = 0; j < 4; j++) o[i][j] = 0.f;
    float m0 = -1e30f, m1 = -1e30f, l0 = 0.f, l1 = 0.f;

    for (int t = 0; t < NSEQ / 64; t++) {
        int b = t & 1;
        if (t + 1 < NSEQ / 64) prefetch_kv((t + 1) * 64, b ^ 1);

        uint32_t kBase = sbase + (uint32_t)(QWORDS + b * 2 * KVWORDS) * 4;
        uint32_t vBase = kBase + KVWORDS * 4;

        float sc[8][4];
        #pragma unroll
        for (int i = 0; i < 8; i++)
            #pragma unroll
            for (int j = 0; j < 4; j++) sc[i][j] = 0.f;

        #pragma unroll
        for (int kc = 0; kc < 4; kc++) {
            #pragma unroll
            for (int np = 0; np < 4; np++) {
                uint32_t b00, b01, b10, b11;
                ldsm4(b00, b01, b10, b11,
                      kBase + (uint32_t)(np * 16 * KSTRW) * 4 + bPat + kc * 32);
                mma_f16(sc[2*np][0], sc[2*np][1], sc[2*np][2], sc[2*np][3],
                        qf[kc][0], qf[kc][1], qf[kc][2], qf[kc][3], b00, b01);
                mma_f16(sc[2*np+1][0], sc[2*np+1][1], sc[2*np+1][2], sc[2*np+1][3],
                        qf[kc][0], qf[kc][1], qf[kc][2], qf[kc][3], b10, b11);
            }
        }

        float rm0 = -1e30f, rm1 = -1e30f;
        #pragma unroll
        for (int nf = 0; nf < 8; nf++) {
            rm0 = fmaxf(rm0, fmaxf(sc[nf][0], sc[nf][1]));
            rm1 = fmaxf(rm1, fmaxf(sc[nf][2], sc[nf][3]));
        }
        rm0 = fmaxf(rm0, __shfl_xor_sync(0xffffffffu, rm0, 1));
        rm0 = fmaxf(rm0, __shfl_xor_sync(0xffffffffu, rm0, 2));
        rm1 = fmaxf(rm1, __shfl_xor_sync(0xffffffffu, rm1, 1));
        rm1 = fmaxf(rm1, __shfl_xor_sync(0xffffffffu, rm1, 2));

        float mn0 = fmaxf(m0, rm0), mn1 = fmaxf(m1, rm1);
        float c0 = __expf(m0 - mn0), c1 = __expf(m1 - mn1);
        m0 = mn0; m1 = mn1;

        float rs0 = 0.f, rs1 = 0.f;
        uint32_t hl0[8], hl1[8];
        #pragma unroll
        for (int nf = 0; nf < 8; nf++) {
            float p0 = __expf(sc[nf][0] - m0);
            float p1 = __expf(sc[nf][1] - m0);
            float p2 = __expf(sc[nf][2] - m1);
            float p3 = __expf(sc[nf][3] - m1);
            rs0 += p0 + p1; rs1 += p2 + p3;
            hl0[nf] = h2pack(p0, p1);
            hl1[nf] = h2pack(p2, p3);
        }
        #pragma unroll
        for (int np = 0; np < 4; np++)
            stsm4(pBase + sPat + np * 32,
                  hl0[2*np], hl1[2*np], hl0[2*np+1], hl1[2*np+1]);

        rs0 += __shfl_xor_sync(0xffffffffu, rs0, 1);
        rs0 += __shfl_xor_sync(0xffffffffu, rs0, 2);
        rs1 += __shfl_xor_sync(0xffffffffu, rs1, 1);
        rs1 += __shfl_xor_sync(0xffffffffu, rs1, 2);
        l0 = l0 * c0 + rs0;
        l1 = l1 * c1 + rs1;

        #pragma unroll
        for (int nf = 0; nf < 8; nf++) {
            o[nf][0] *= c0; o[nf][1] *= c0;
            o[nf][2] *= c1; o[nf][3] *= c1;
        }
        __syncwarp();

        #pragma unroll
        for (int kc = 0; kc < 4; kc++) {
            uint32_t a0, a1, a2, a3;
            ldsm4(a0, a1, a2, a3, pBase + aPat + kc * 32);
            #pragma unroll
            for (int np = 0; np < 4; np++) {
                uint32_t b00, b01, b10, b11;
                ldsm4(b00, b01, b10, b11,
                      vBase + (uint32_t)(np * 16 * KSTRW) * 4 + bPat + kc * 32);
                mma_f16(o[2*np][0], o[2*np][1], o[2*np][2], o[2*np][3],
                        a0, a1, a2, a3, b00, b01);
                mma_f16(o[2*np+1][0], o[2*np+1][1], o[2*np+1][2], o[2*np+1][3],
                        a0, a1, a2, a3, b10, b11);
            }
        }
        __syncwarp();

        if (t + 1 < NSEQ / 64) { CP_WAIT(0); }
        __syncthreads();
    }

    float il0 = 1.f / l0, il1 = 1.f / l1;
    int r0 = tq0 + wid * 16 + quad;
    #pragma unroll
    for (int nf = 0; nf < 8; nf++) {
        int c = h * DHEAD + nf * 8 + tig * 2;
        *reinterpret_cast<uint32_t*>(aout + (size_t)r0 * DIMC + c) =
            h2pack(o[nf][0] * il0, o[nf][1] * il0);
        *reinterpret_cast<uint32_t*>(aout + (size_t)(r0 + 8) * DIMC + c) =
            h2pack(o[nf][2] * il1, o[nf][3] * il1);
    }
}

// ============================================================
// launch
// ============================================================
extern "C" void kernel_launch(void* const* d_in, const int* in_sizes, int n_in,
                              void* d_out, int out_size)
{
    const float* x      = (const float*)d_in[0];
    const float* norm_g = (const float*)d_in[1];
    const float* norm_b = (const float*)d_in[2];
    const float* W1     = (const float*)d_in[3];
    const float* b1     = (const float*)d_in[4];
    const float* qn_g   = (const float*)d_in[5];
    const float* qn_b   = (const float*)d_in[6];
    const float* kn_g   = (const float*)d_in[7];
    const float* kn_b   = (const float*)d_in[8];
    const float* Wao    = (const float*)d_in[9];
    const float* bao    = (const float*)d_in[10];
    const float* Wmo    = (const float*)d_in[11];
    const float* bmo    = (const float*)d_in[12];
    const float* W2     = (const float*)d_in[13];
    const float* b2     = (const float*)d_in[14];
    float*       out    = (float*)d_out;

    __half *norm, *fused, *attn, *w1t, *w2t, *waor, *wmor, *wfa, *wfm;
    float *beff;
    cudaGetSymbolAddress((void**)&norm,  g_norm);
    cudaGetSymbolAddress((void**)&fused, g_fused);
    cudaGetSymbolAddress((void**)&attn,  g_attn);
    cudaGetSymbolAddress((void**)&w1t,   g_w1t);
    cudaGetSymbolAddress((void**)&w2t,   g_w2t);
    cudaGetSymbolAddress((void**)&waor,  g_waor);
    cudaGetSymbolAddress((void**)&wmor,  g_wmor);
    cudaGetSymbolAddress((void**)&wfa,   g_wfa);
    cudaGetSymbolAddress((void**)&wfm,   g_wfm);
    cudaGetSymbolAddress((void**)&beff,  g_beff);

    cudaFuncSetAttribute(mma_gemm, cudaFuncAttributeMaxDynamicSharedMemorySize, GEMM_SMEM);
    cudaFuncSetAttribute(fattn_kernel, cudaFuncAttributeMaxDynamicSharedMemorySize, ATTN_SMEM);

    // merged weight prep
    prep_kernel<<<13120, 256>>>(W1, W2, Wao, Wmo, bao, bmo, b2);
    beff_red<<<DIMC / 256, 256>>>(beff);

    // weight folds (mode 0)
    mma_gemm<<<dim3(DIMC / 128, DIMC / 128), 256, GEMM_SMEM>>>(
        w2t, 2 * DIMC, waor, DIMC, DIMC,
        nullptr, 0, nullptr, 0, 0,
        wfa, DIMC, nullptr, 0, nullptr, 0, nullptr, 0, 0);
    mma_gemm<<<dim3(HIDPAD / 128, DIMC / 128), 256, GEMM_SMEM>>>(
        w2t + DIMC, 2 * DIMC, wmor, DIMC, DIMC,
        nullptr, 0, nullptr, 0, 0,
        wfm, HIDPAD, nullptr, 0, nullptr, 0, nullptr, 0, 0);

    // 1) layernorm(x) -> half
    ln_kernel<<<NTOK, 256>>>(x, norm_g, norm_b, norm);

    // 2) fused = norm @ W1 + b1; qk->fused, V->g_vt transposed, mlp->gelu->fused
    mma_gemm<<<dim3(FWP / 128, NTOK / 128), 256, GEMM_SMEM>>>(
        norm, DIMC, w1t, DIMC, DIMC,
        nullptr, 0, nullptr, 0, 0,
        fused, FWP, nullptr, 0, b1, FW, nullptr, 0, 1);

    // 3) per-head LN on q/k (q scaled by 0.125)
    qkln_kernel<<<(NTOK * 32) / 8, 256>>>(fused, qn_g, qn_b, kn_g, kn_b);

    // 4) flash attention (fp16, ldmatrix)
    fattn_kernel<<<dim3(NSEQ / 128, NHEADS, 2), 256, ATTN_SMEM>>>(fused, attn);

    // 5) out = x + attn @ wfa^T + gelu_hidden @ wfm^T + beff  (merged, mode 2)
    mma_gemm<<<dim3(DIMC / 128, NTOK / 128), 256, GEMM_SMEM>>>(
        attn, DIMC, wfa, DIMC, DIMC,
        fused + 3 * DIMC, FWP, wfm, HIDPAD, HIDPAD,
        nullptr, 0, out, DIMC, beff, DIMC, x, DIMC, 2);
}

// round 9
// speedup vs baseline: 8.3450x; 1.0919x over previous
#include <cuda_runtime.h>
#include <cuda_fp16.h>
#include <math.h>
#include <stdint.h>

// ---------------- problem constants ----------------
#define NTOK   4096              // B*N = 2*2048
#define DIMC   1024
#define NHEADS 16
#define DHEAD  64
#define MLPHID 716
#define FW     3788              // 3*DIM + MLP_HID (true width)
#define FWP    3840              // padded to 30*128
#define HIDPAD 768               // Wmo rows padded; K2 of apply
#define NSEQ   2048
#define LN_EPS 1e-6f
#define NSLICE 16

// ---------------- scratch (static device globals) ------
__device__ __half g_norm [NTOK * DIMC];
__device__ __half g_fused[NTOK * FWP];
__device__ __half g_vt   [2 * NHEADS * DHEAD * NSEQ];   // V transposed [b][h][d][n]
__device__ __half g_attn [NTOK * DIMC];
__device__ __half g_w1t  [FWP  * DIMC];
__device__ __half g_w2t  [DIMC * 2 * DIMC];
__device__ __half g_waor [DIMC * DIMC];
__device__ __half g_wmor [HIDPAD * DIMC];
__device__ __half g_wfa  [DIMC * DIMC];
__device__ __half g_wfm  [DIMC * HIDPAD];
__device__ float  g_beff [DIMC];
__device__ float  g_beffp[NSLICE * DIMC];

// ================= helpers =================
__device__ __forceinline__ uint32_t smem_u32(const void* p) {
    uint32_t a;
    asm("{ .reg .u64 t; cvta.to.shared.u64 t, %1; cvt.u32.u64 %0, t; }" : "=r"(a) : "l"(p));
    return a;
}
__device__ __forceinline__ void mma_f16(float& d0, float& d1, float& d2, float& d3,
                                        uint32_t a0, uint32_t a1, uint32_t a2, uint32_t a3,
                                        uint32_t b0, uint32_t b1)
{
    asm volatile(
        "mma.sync.aligned.m16n8k16.row.col.f32.f16.f16.f32 "
        "{%0,%1,%2,%3}, {%4,%5,%6,%7}, {%8,%9}, {%0,%1,%2,%3};"
        : "+f"(d0), "+f"(d1), "+f"(d2), "+f"(d3)
        : "r"(a0), "r"(a1), "r"(a2), "r"(a3), "r"(b0), "r"(b1));
}
__device__ __forceinline__ void ldsm4(uint32_t& r0, uint32_t& r1, uint32_t& r2, uint32_t& r3,
                                      uint32_t addr)
{
    asm volatile("ldmatrix.sync.aligned.m8n8.x4.shared.b16 {%0,%1,%2,%3}, [%4];"
                 : "=r"(r0), "=r"(r1), "=r"(r2), "=r"(r3) : "r"(addr));
}
__device__ __forceinline__ void stsm4(uint32_t addr, uint32_t r0, uint32_t r1,
                                      uint32_t r2, uint32_t r3)
{
    asm volatile("stmatrix.sync.aligned.m8n8.x4.shared.b16 [%0], {%1,%2,%3,%4};"
                 :: "r"(addr), "r"(r0), "r"(r1), "r"(r2), "r"(r3) : "memory");
}
__device__ __forceinline__ float gelu1(float x) {
    float u = 0.7978845608028654f * (x + 0.044715f * x * x * x);
    return 0.5f * x * (1.f + tanhf(u));
}
__device__ __forceinline__ uint32_t h2pack(float a, float b) {
    __half2 h = __floats2half2_rn(a, b);
    return *reinterpret_cast<uint32_t*>(&h);
}
#define CP_CA(dst, src) asm volatile("cp.async.ca.shared.global [%0], [%1], 16;" :: "r"(dst), "l"(src) : "memory")
#define CP_CG(dst, src) asm volatile("cp.async.cg.shared.global [%0], [%1], 16;" :: "r"(dst), "l"(src) : "memory")
#define CP_COMMIT()     asm volatile("cp.async.commit_group;" ::: "memory")
#define CP_WAIT(n)      asm volatile("cp.async.wait_group %0;" :: "n"(n) : "memory")

// ============================================================
// merged prep: W1^T, W2^T, Wao copy, Wmo copy(pad), beff partials
// blocks: [0,3840) W1t | [3840,5888) W2t | [5888,9984) Wao |
//         [9984,13056) Wmo | [13056,13120) beff_part
// ============================================================
__global__ void prep_kernel(const float* __restrict__ W1,
                            const float* __restrict__ W2,
                            const float* __restrict__ Wao,
                            const float* __restrict__ Wmo,
                            const float* __restrict__ bao,
                            const float* __restrict__ bmo,
                            const float* __restrict__ b2)
{
    __shared__ float t[32][33];
    int bid = blockIdx.x, tid = threadIdx.x;
    int tx = tid & 31, ty = tid >> 5;

    if (bid < 3840) {
        int bx = bid % (FWP / 32), by = bid / (FWP / 32);
        int n0 = bx * 32, k0 = by * 32;
        #pragma unroll
        for (int i = 0; i < 32; i += 8) {
            int n = n0 + tx;
            t[ty + i][tx] = (n < FW) ? W1[(size_t)(k0 + ty + i) * FW + n] : 0.f;
        }
        __syncthreads();
        #pragma unroll
        for (int i = 0; i < 32; i += 8)
            g_w1t[(size_t)(n0 + ty + i) * DIMC + k0 + tx] = __float2half(t[tx][ty + i]);
    } else if (bid < 5888) {
        int b = bid - 3840;
        int bx = b % 32, by = b / 32;
        int n0 = bx * 32, k0 = by * 32;
        #pragma unroll
        for (int i = 0; i < 32; i += 8)
            t[ty + i][tx] = W2[(size_t)(k0 + ty + i) * DIMC + n0 + tx];
        __syncthreads();
        #pragma unroll
        for (int i = 0; i < 32; i += 8)
            g_w2t[(size_t)(n0 + ty + i) * 2 * DIMC + k0 + tx] = __float2half(t[tx][ty + i]);
    } else if (bid < 9984) {
        int idx = (bid - 5888) * 256 + tid;
        g_waor[idx] = __float2half(Wao[idx]);
    } else if (bid < 13056) {
        int idx = (bid - 9984) * 256 + tid;
        int r = idx >> 10, c = idx & 1023;
        g_wmor[idx] = (r < MLPHID) ? __float2half(Wmo[(size_t)r * DIMC + c])
                                   : __float2half(0.f);
    } else {
        int b = bid - 13056;
        int n = (b & 3) * 256 + tid;
        int s = b >> 2;
        float acc = (s == 0) ? b2[n] : 0.f;
        int k0 = s * (2048 / NSLICE), k1 = k0 + (2048 / NSLICE);
        for (int k = k0; k < k1; k++) {
            float c = (k < 1024) ? bao[k] : bmo[k - 1024];
            acc += c * W2[(size_t)k * DIMC + n];
        }
        g_beffp[s * DIMC + n] = acc;
    }
}

// ============================================================
// merged fold launch: BOTH weight folds + beff reduce, one wave.
// blocks [0,64): wfa = w2t(:, :1024-K) x waor ;  [64,112): wfm ; [112,116): beff
// ============================================================
#define SSTRW 36
#define ABUFW (128 * SSTRW)
#define STAGEW (2 * ABUFW)
#define GEMM_SMEM (3 * STAGEW * 4)   // 110592 B

__global__ void __launch_bounds__(256, 2)
fold_kernel()
{
    extern __shared__ uint32_t smw[];
    int bid = blockIdx.x, tid = threadIdx.x;

    if (bid >= 112) {                      // beff reduce
        int n = (bid - 112) * 256 + tid;
        float s = 0.f;
        #pragma unroll
        for (int i = 0; i < NSLICE; i++) s += g_beffp[i * DIMC + n];
        g_beff[n] = s;
        return;
    }

    const __half* A; const __half* Bt; __half* C;
    int lda, ldb, ldc, bm, bn;
    if (bid < 64) {        // wfa[1024][1024] = w2t[:, :? ] rows x waor rows
        A = g_w2t;  lda = 2 * DIMC; Bt = g_waor; ldb = DIMC;
        C = g_wfa;  ldc = DIMC;
        bn = (bid & 7) * 128; bm = (bid >> 3) * 128;
    } else {               // wfm[1024][768]
        int b = bid - 64;
        A = g_w2t + DIMC; lda = 2 * DIMC; Bt = g_wmor; ldb = DIMC;
        C = g_wfm; ldc = HIDPAD;
        bn = (b % 6) * 128; bm = (b / 6) * 128;
    }

    uint32_t sbase = smem_u32(smw);
    int wid = tid >> 5, lane = tid & 31;
    int quad = lane >> 2, tig = lane & 3;
    int wm = (wid & 1) * 64, wn = (wid >> 1) * 32;
    int lr = tid >> 3, lcw = (tid & 7) * 4;
    int lane15 = lane & 15;

    float acc[4][4][4];
    #pragma unroll
    for (int i = 0; i < 4; i++)
        #pragma unroll
        for (int j = 0; j < 4; j++)
            #pragma unroll
            for (int r = 0; r < 4; r++) acc[i][j][r] = 0.f;

    uint32_t aoff[4];
    #pragma unroll
    for (int mt = 0; mt < 4; mt++)
        aoff[mt] = (uint32_t)((wm + mt * 16 + lane15) * SSTRW) * 4 + (lane >> 4) * 16;
    uint32_t boff0 = (uint32_t)((wn + ((lane >> 4) << 3) + (lane & 7)) * SSTRW) * 4
                   + ((lane >> 3) & 1) * 16;
    uint32_t boff1 = boff0 + 16 * SSTRW * 4;

    const int nk = DIMC >> 6;     // 16

    auto prefetch = [&](int it, int st) {
        int k0 = it << 6;
        uint32_t dA = sbase + (uint32_t)st * STAGEW * 4;
        uint32_t dB = dA + ABUFW * 4;
        #pragma unroll
        for (int i = 0; i < 4; i++) {
            int r = i * 32 + lr;
            CP_CG(dA + (uint32_t)(r * SSTRW + lcw) * 4, A + (size_t)(bm + r) * lda + k0 + lcw * 2);
            CP_CG(dB + (uint32_t)(r * SSTRW + lcw) * 4, Bt + (size_t)(bn + r) * ldb + k0 + lcw * 2);
        }
        CP_COMMIT();
    };

    prefetch(0, 0);
    prefetch(1, 1);

    for (int it = 0; it < nk; it++) {
        int st = it % 3;
        if (it + 2 < nk) { prefetch(it + 2, (it + 2) % 3); CP_WAIT(2); }
        else if (it + 1 < nk) { CP_WAIT(1); }
        else { CP_WAIT(0); }
        __syncthreads();

        uint32_t stA = sbase + (uint32_t)st * STAGEW * 4;
        uint32_t stB = stA + ABUFW * 4;
        #pragma unroll
        for (int kk = 0; kk < 4; kk++) {
            uint32_t af[4][4], bf[4][2];
            #pragma unroll
            for (int mt = 0; mt < 4; mt++)
                ldsm4(af[mt][0], af[mt][1], af[mt][2], af[mt][3],
                      stA + aoff[mt] + kk * 32);
            ldsm4(bf[0][0], bf[0][1], bf[1][0], bf[1][1], stB + boff0 + kk * 32);
            ldsm4(bf[2][0], bf[2][1], bf[3][0], bf[3][1], stB + boff1 + kk * 32);
            #pragma unroll
            for (int mt = 0; mt < 4; mt++)
                #pragma unroll
                for (int nt = 0; nt < 4; nt++)
                    mma_f16(acc[mt][nt][0], acc[mt][nt][1],
                            acc[mt][nt][2], acc[mt][nt][3],
                            af[mt][0], af[mt][1], af[mt][2], af[mt][3],
                            bf[nt][0], bf[nt][1]);
        }
        __syncthreads();
    }

    #pragma unroll
    for (int mt = 0; mt < 4; mt++) {
        int r0 = bm + wm + mt * 16 + quad;
        #pragma unroll
        for (int nt = 0; nt < 4; nt++) {
            int c = bn + wn + nt * 8 + tig * 2;
            *reinterpret_cast<uint32_t*>(C + (size_t)r0 * ldc + c) =
                h2pack(acc[mt][nt][0], acc[mt][nt][1]);
            *reinterpret_cast<uint32_t*>(C + (size_t)(r0 + 8) * ldc + c) =
                h2pack(acc[mt][nt][2], acc[mt][nt][3]);
        }
    }
}

// ============================================================
// LayerNorm over DIM=1024, half output
// ============================================================
__global__ void ln_kernel(const float* __restrict__ x,
                          const float* __restrict__ g,
                          const float* __restrict__ b,
                          __half* __restrict__ out)
{
    int row = blockIdx.x;
    int tid = threadIdx.x;
    const float4 v = reinterpret_cast<const float4*>(x + (size_t)row * DIMC)[tid];

    float s  = v.x + v.y + v.z + v.w;
    float sq = v.x*v.x + v.y*v.y + v.z*v.z + v.w*v.w;
    #pragma unroll
    for (int o = 16; o > 0; o >>= 1) {
        s  += __shfl_xor_sync(0xffffffffu, s,  o);
        sq += __shfl_xor_sync(0xffffffffu, sq, o);
    }
    __shared__ float ws[8], wq[8];
    int warp = tid >> 5, lane = tid & 31;
    if (lane == 0) { ws[warp] = s; wq[warp] = sq; }
    __syncthreads();
    if (warp == 0) {
        float s2  = (lane < 8) ? ws[lane] : 0.f;
        float sq2 = (lane < 8) ? wq[lane] : 0.f;
        #pragma unroll
        for (int o = 4; o > 0; o >>= 1) {
            s2  += __shfl_xor_sync(0xffffffffu, s2,  o);
            sq2 += __shfl_xor_sync(0xffffffffu, sq2, o);
        }
        if (lane == 0) { ws[0] = s2; wq[0] = sq2; }
    }
    __syncthreads();
    float mean = ws[0] * (1.f / DIMC);
    float var  = wq[0] * (1.f / DIMC) - mean * mean;
    float rstd = rsqrtf(var + LN_EPS);

    float4 gg = reinterpret_cast<const float4*>(g)[tid];
    float4 bb = reinterpret_cast<const float4*>(b)[tid];
    uint2 o2;
    o2.x = h2pack((v.x - mean) * rstd * gg.x + bb.x,
                  (v.y - mean) * rstd * gg.y + bb.y);
    o2.y = h2pack((v.z - mean) * rstd * gg.z + bb.z,
                  (v.w - mean) * rstd * gg.w + bb.w);
    reinterpret_cast<uint2*>(out + (size_t)row * DIMC)[tid] = o2;
}

// ============================================================
// fp16 mma.sync GEMM, 3-stage cp.async pipeline, ldmatrix frags.
// mode 1: GEMM1 — region 0 (qk): FUSED per-head LN (+0.125 q scale)
//                 region 1: V->g_vt transposed   region 2: gelu
// mode 2: C float + bias + resid (apply)
// ============================================================
__global__ void __launch_bounds__(256, 2)
mma_gemm(const __half* __restrict__ A, int lda,
         const __half* __restrict__ Bt, int ldb, int K1,
         const __half* __restrict__ A2, int lda2,
         const __half* __restrict__ Bt2, int ldb2, int K2,
         __half* __restrict__ Ch, int ldch,
         float* __restrict__ Cf, int ldcf,
         const float* __restrict__ bias, int nbias,
         const float* __restrict__ resid, int ldr,
         const float* __restrict__ qg, const float* __restrict__ qb,
         const float* __restrict__ kg, const float* __restrict__ kb,
         int mode)
{
    extern __shared__ uint32_t smw[];
    uint32_t sbase = smem_u32(smw);
    int tid  = threadIdx.x;
    int wid  = tid >> 5, lane = tid & 31;
    int quad = lane >> 2, tig = lane & 3;
    int bm = blockIdx.y * 128, bn = blockIdx.x * 128;
    int wm = (wid & 1) * 64, wn = (wid >> 1) * 32;

    float acc[4][4][4];
    #pragma unroll
    for (int i = 0; i < 4; i++)
        #pragma unroll
        for (int j = 0; j < 4; j++)
            #pragma unroll
            for (int r = 0; r < 4; r++) acc[i][j][r] = 0.f;

    int lr = tid >> 3;
    int lcw = (tid & 7) * 4;

    int lane15 = lane & 15;
    uint32_t aoff[4];
    #pragma unroll
    for (int mt = 0; mt < 4; mt++)
        aoff[mt] = (uint32_t)((wm + mt * 16 + lane15) * SSTRW) * 4 + (lane >> 4) * 16;
    uint32_t boff0 = (uint32_t)((wn + ((lane >> 4) << 3) + (lane & 7)) * SSTRW) * 4
                   + ((lane >> 3) & 1) * 16;
    uint32_t boff1 = boff0 + 16 * SSTRW * 4;

    const int nk1 = K1 >> 6;
    const int nk  = nk1 + (K2 >> 6);

    auto prefetch = [&](int it, int st) {
        const __half* Ab; const __half* Bb; int la, lb, k0;
        if (it < nk1) { Ab = A;  Bb = Bt;  la = lda;  lb = ldb;  k0 = it << 6; }
        else          { Ab = A2; Bb = Bt2; la = lda2; lb = ldb2; k0 = (it - nk1) << 6; }
        uint32_t dA = sbase + (uint32_t)st * STAGEW * 4;
        uint32_t dB = dA + ABUFW * 4;
        #pragma unroll
        for (int i = 0; i < 4; i++) {
            int r = i * 32 + lr;
            CP_CG(dA + (uint32_t)(r * SSTRW + lcw) * 4, Ab + (size_t)(bm + r) * la + k0 + lcw * 2);
            CP_CG(dB + (uint32_t)(r * SSTRW + lcw) * 4, Bb + (size_t)(bn + r) * lb + k0 + lcw * 2);
        }
        CP_COMMIT();
    };

    prefetch(0, 0);
    if (nk > 1) prefetch(1, 1);

    for (int it = 0; it < nk; it++) {
        int st = it % 3;
        if (it + 2 < nk) { prefetch(it + 2, (it + 2) % 3); CP_WAIT(2); }
        else if (it + 1 < nk) { CP_WAIT(1); }
        else { CP_WAIT(0); }
        __syncthreads();

        uint32_t stA = sbase + (uint32_t)st * STAGEW * 4;
        uint32_t stB = stA + ABUFW * 4;

        #pragma unroll
        for (int kk = 0; kk < 4; kk++) {
            uint32_t af[4][4], bf[4][2];
            #pragma unroll
            for (int mt = 0; mt < 4; mt++)
                ldsm4(af[mt][0], af[mt][1], af[mt][2], af[mt][3],
                      stA + aoff[mt] + kk * 32);
            ldsm4(bf[0][0], bf[0][1], bf[1][0], bf[1][1], stB + boff0 + kk * 32);
            ldsm4(bf[2][0], bf[2][1], bf[3][0], bf[3][1], stB + boff1 + kk * 32);
            #pragma unroll
            for (int mt = 0; mt < 4; mt++)
                #pragma unroll
                for (int nt = 0; nt < 4; nt++)
                    mma_f16(acc[mt][nt][0], acc[mt][nt][1],
                            acc[mt][nt][2], acc[mt][nt][3],
                            af[mt][0], af[mt][1], af[mt][2], af[mt][3],
                            bf[nt][0], bf[nt][1]);
        }
        __syncthreads();
    }

    int region = (mode != 1) ? -1 : ((bn < 2 * DIMC) ? 0 : (bn < 3 * DIMC ? 1 : 2));

    if (region == 0) {
        // ---------- fused per-head QK layernorm ----------
        float* ssum = reinterpret_cast<float*>(smw);       // [128][4]
        float* ssq  = ssum + 128 * 4;                      // [128][4]
        int ch = wn >> 5;

        #pragma unroll
        for (int mt = 0; mt < 4; mt++) {
            float slo = 0.f, sqlo = 0.f, shi = 0.f, sqhi = 0.f;
            #pragma unroll
            for (int nt = 0; nt < 4; nt++) {
                int c = bn + wn + nt * 8 + tig * 2;
                float b0 = bias[c], b1v = bias[c + 1];
                acc[mt][nt][0] += b0; acc[mt][nt][1] += b1v;
                acc[mt][nt][2] += b0; acc[mt][nt][3] += b1v;
                slo  += acc[mt][nt][0] + acc[mt][nt][1];
                sqlo += acc[mt][nt][0] * acc[mt][nt][0] + acc[mt][nt][1] * acc[mt][nt][1];
                shi  += acc[mt][nt][2] + acc[mt][nt][3];
                sqhi += acc[mt][nt][2] * acc[mt][nt][2] + acc[mt][nt][3] * acc[mt][nt][3];
            }
            slo  += __shfl_xor_sync(0xffffffffu, slo, 1);
            slo  += __shfl_xor_sync(0xffffffffu, slo, 2);
            sqlo += __shfl_xor_sync(0xffffffffu, sqlo, 1);
            sqlo += __shfl_xor_sync(0xffffffffu, sqlo, 2);
            shi  += __shfl_xor_sync(0xffffffffu, shi, 1);
            shi  += __shfl_xor_sync(0xffffffffu, shi, 2);
            sqhi += __shfl_xor_sync(0xffffffffu, sqhi, 1);
            sqhi += __shfl_xor_sync(0xffffffffu, sqhi, 2);
            if (tig == 0) {
                int rl = wm + mt * 16 + quad;
                ssum[rl * 4 + ch] = slo;        ssq[rl * 4 + ch] = sqlo;
                ssum[(rl + 8) * 4 + ch] = shi;  ssq[(rl + 8) * 4 + ch] = sqhi;
            }
        }
        __syncthreads();

        int hb = (wn >> 6) << 1;                 // head-half base (0 or 2)
        bool isq = (bn < DIMC);
        const float* gv = isq ? qg : kg;
        const float* bv = isq ? qb : kb;
        float qsc = isq ? 0.125f : 1.f;

        #pragma unroll
        for (int mt = 0; mt < 4; mt++) {
            int rl = wm + mt * 16 + quad;
            float mlo = (ssum[rl * 4 + hb] + ssum[rl * 4 + hb + 1]) * (1.f / 64.f);
            float vlo = (ssq[rl * 4 + hb] + ssq[rl * 4 + hb + 1]) * (1.f / 64.f) - mlo * mlo;
            float rlo = rsqrtf(vlo + LN_EPS);
            float mhi = (ssum[(rl + 8) * 4 + hb] + ssum[(rl + 8) * 4 + hb + 1]) * (1.f / 64.f);
            float vhi = (ssq[(rl + 8) * 4 + hb] + ssq[(rl + 8) * 4 + hb + 1]) * (1.f / 64.f) - mhi * mhi;
            float rhi = rsqrtf(vhi + LN_EPS);
            int r0 = bm + rl;
            #pragma unroll
            for (int nt = 0; nt < 4; nt++) {
                int c = bn + wn + nt * 8 + tig * 2;
                int d = c & 63;
                float g0 = gv[d], g1 = gv[d + 1];
                float e0 = bv[d], e1 = bv[d + 1];
                float o0 = ((acc[mt][nt][0] - mlo) * rlo * g0 + e0) * qsc;
                float o1 = ((acc[mt][nt][1] - mlo) * rlo * g1 + e1) * qsc;
                float o2 = ((acc[mt][nt][2] - mhi) * rhi * g0 + e0) * qsc;
                float o3 = ((acc[mt][nt][3] - mhi) * rhi * g1 + e1) * qsc;
                *reinterpret_cast<uint32_t*>(Ch + (size_t)r0 * ldch + c) = h2pack(o0, o1);
                *reinterpret_cast<uint32_t*>(Ch + (size_t)(r0 + 8) * ldch + c) = h2pack(o2, o3);
            }
        }
        return;
    }

    #pragma unroll
    for (int mt = 0; mt < 4; mt++) {
        int r0 = bm + wm + mt * 16 + quad;
        #pragma unroll
        for (int nt = 0; nt < 4; nt++) {
            int c = bn + wn + nt * 8 + tig * 2;
            float2 v0 = make_float2(acc[mt][nt][0], acc[mt][nt][1]);
            float2 v1 = make_float2(acc[mt][nt][2], acc[mt][nt][3]);
            if (bias) {
                float bx = (c     < nbias) ? bias[c]     : 0.f;
                float by = (c + 1 < nbias) ? bias[c + 1] : 0.f;
                v0.x += bx; v0.y += by;
                v1.x += bx; v1.y += by;
            }
            if (mode == 2) {
                float2 ra = *reinterpret_cast<const float2*>(resid + (size_t)r0 * ldr + c);
                float2 rb = *reinterpret_cast<const float2*>(resid + (size_t)(r0 + 8) * ldr + c);
                v0.x += ra.x; v0.y += ra.y;
                v1.x += rb.x; v1.y += rb.y;
                *reinterpret_cast<float2*>(Cf + (size_t)r0 * ldcf + c) = v0;
                *reinterpret_cast<float2*>(Cf + (size_t)(r0 + 8) * ldcf + c) = v1;
            } else if (region == 1) {
                int d = c - 2 * DIMC;
                int hh = d >> 6, dd = d & 63;
                int bbk = r0 >> 11, nn = r0 & 2047;
                size_t base = ((size_t)(bbk * NHEADS + hh) * DHEAD);
                g_vt[(base + dd    ) * NSEQ + nn    ] = __float2half(v0.x);
                g_vt[(base + dd + 1) * NSEQ + nn    ] = __float2half(v0.y);
                g_vt[(base + dd    ) * NSEQ + nn + 8] = __float2half(v1.x);
                g_vt[(base + dd + 1) * NSEQ + nn + 8] = __float2half(v1.y);
            } else {
                if (region == 2) {
                    v0.x = gelu1(v0.x); v0.y = gelu1(v0.y);
                    v1.x = gelu1(v1.x); v1.y = gelu1(v1.y);
                }
                *reinterpret_cast<uint32_t*>(Ch + (size_t)r0 * ldch + c) = h2pack(v0.x, v0.y);
                *reinterpret_cast<uint32_t*>(Ch + (size_t)(r0 + 8) * ldch + c) = h2pack(v1.x, v1.y);
            }
        }
    }
}

// ============================================================
// Flash attention, fp16 m16n8k16, ldmatrix/stmatrix fragments.
// ============================================================
#define KSTRW 36
#define QWORDS (128 * KSTRW)
#define KVWORDS (64 * KSTRW)
#define ATTN_SMEM ((QWORDS + 4 * KVWORDS) * 4)   // 55296 B

__global__ void __launch_bounds__(256, 2)
fattn_kernel(const __half* __restrict__ fused, __half* __restrict__ aout)
{
    extern __shared__ uint32_t smw[];
    uint32_t sbase = smem_u32(smw);

    int tid  = threadIdx.x;
    int wid  = tid >> 5, lane = tid & 31;
    int quad = lane >> 2, tig = lane & 3;
    int lane15 = lane & 15;
    int h  = blockIdx.y;
    int bb = blockIdx.z;
    int q0 = blockIdx.x * 128;
    int tq0 = bb * NSEQ + q0;
    int kvb = bb * NSEQ;
    const __half* vtb = g_vt + (size_t)(bb * NHEADS + h) * DHEAD * NSEQ;

    auto prefetch_kv = [&](int kt, int buf) {
        uint32_t dK = sbase + (uint32_t)(QWORDS + buf * 2 * KVWORDS) * 4;
        uint32_t dV = dK + KVWORDS * 4;
        #pragma unroll
        for (int i = 0; i < 2; i++) {
            int idx = i * 256 + tid;
            int r = idx >> 3, chh = (idx & 7) * 8;
            CP_CG(dK + (uint32_t)(r * KSTRW + chh / 2) * 4,
                  fused + (size_t)(kvb + kt + r) * FWP + DIMC + h * DHEAD + chh);
            CP_CG(dV + (uint32_t)(r * KSTRW + chh / 2) * 4,
                  vtb + (size_t)r * NSEQ + kt + chh);
        }
        CP_COMMIT();
    };

    #pragma unroll
    for (int i = 0; i < 4; i++) {
        int idx = i * 256 + tid;
        int r = idx >> 3, chh = (idx & 7) * 8;
        CP_CA(sbase + (uint32_t)(r * KSTRW + chh / 2) * 4,
              fused + (size_t)(tq0 + r) * FWP + h * DHEAD + chh);
    }
    prefetch_kv(0, 0);
    CP_WAIT(0);
    __syncthreads();

    uint32_t aPat = (uint32_t)(lane15 * KSTRW) * 4 + (lane >> 4) * 16;
    uint32_t bPat = (uint32_t)((((lane >> 4) << 3) + (lane & 7)) * KSTRW) * 4
                  + ((lane >> 3) & 1) * 16;
    uint32_t sPat = (uint32_t)(((((lane >> 3) & 1) << 3) + (lane & 7)) * KSTRW) * 4
                  + (lane >> 4) * 16;

    uint32_t qf[4][4];
    {
        uint32_t qbase = sbase + (uint32_t)(wid * 16 * KSTRW) * 4 + aPat;
        #pragma unroll
        for (int kc = 0; kc < 4; kc++)
            ldsm4(qf[kc][0], qf[kc][1], qf[kc][2], qf[kc][3], qbase + kc * 32);
    }
    uint32_t pBase = sbase + (uint32_t)(wid * 16 * KSTRW) * 4;

    float o[8][4];
    #pragma unroll
    for (int i = 0; i < 8; i++)
        #pragma unroll
        for (int j = 0; j < 4; j++) o[i][j] = 0.f;
    float m0 = -1e30f, m1 = -1e30f, l0 = 0.f, l1 = 0.f;

    for (int t = 0; t < NSEQ / 64; t++) {
        int b = t & 1;
        if (t + 1 < NSEQ / 64) prefetch_kv((t + 1) * 64, b ^ 1);

        uint32_t kBase = sbase + (uint32_t)(QWORDS + b * 2 * KVWORDS) * 4;
        uint32_t vBase = kBase + KVWORDS * 4;

        float sc[8][4];
        #pragma unroll
        for (int i = 0; i < 8; i++)
            #pragma unroll
            for (int j = 0; j < 4; j++) sc[i][j] = 0.f;

        #pragma unroll
        for (int kc = 0; kc < 4; kc++) {
            #pragma unroll
            for (int np = 0; np < 4; np++) {
                uint32_t b00, b01, b10, b11;
                ldsm4(b00, b01, b10, b11,
                      kBase + (uint32_t)(np * 16 * KSTRW) * 4 + bPat + kc * 32);
                mma_f16(sc[2*np][0], sc[2*np][1], sc[2*np][2], sc[2*np][3],
                        qf[kc][0], qf[kc][1], qf[kc][2], qf[kc][3], b00, b01);
                mma_f16(sc[2*np+1][0], sc[2*np+1][1], sc[2*np+1][2], sc[2*np+1][3],
                        qf[kc][0], qf[kc][1], qf[kc][2], qf[kc][3], b10, b11);
            }
        }

        float rm0 = -1e30f, rm1 = -1e30f;
        #pragma unroll
        for (int nf = 0; nf < 8; nf++) {
            rm0 = fmaxf(rm0, fmaxf(sc[nf][0], sc[nf][1]));
            rm1 = fmaxf(rm1, fmaxf(sc[nf][2], sc[nf][3]));
        }
        rm0 = fmaxf(rm0, __shfl_xor_sync(0xffffffffu, rm0, 1));
        rm0 = fmaxf(rm0, __shfl_xor_sync(0xffffffffu, rm0, 2));
        rm1 = fmaxf(rm1, __shfl_xor_sync(0xffffffffu, rm1, 1));
        rm1 = fmaxf(rm1, __shfl_xor_sync(0xffffffffu, rm1, 2));

        float mn0 = fmaxf(m0, rm0), mn1 = fmaxf(m1, rm1);
        float c0 = __expf(m0 - mn0), c1 = __expf(m1 - mn1);
        m0 = mn0; m1 = mn1;

        float rs0 = 0.f, rs1 = 0.f;
        uint32_t hl0[8], hl1[8];
        #pragma unroll
        for (int nf = 0; nf < 8; nf++) {
            float p0 = __expf(sc[nf][0] - m0);
            float p1 = __expf(sc[nf][1] - m0);
            float p2 = __expf(sc[nf][2] - m1);
            float p3 = __expf(sc[nf][3] - m1);
            rs0 += p0 + p1; rs1 += p2 + p3;
            hl0[nf] = h2pack(p0, p1);
            hl1[nf] = h2pack(p2, p3);
        }
        #pragma unroll
        for (int np = 0; np < 4; np++)
            stsm4(pBase + sPat + np * 32,
                  hl0[2*np], hl1[2*np], hl0[2*np+1], hl1[2*np+1]);

        rs0 += __shfl_xor_sync(0xffffffffu, rs0, 1);
        rs0 += __shfl_xor_sync(0xffffffffu, rs0, 2);
        rs1 += __shfl_xor_sync(0xffffffffu, rs1, 1);
        rs1 += __shfl_xor_sync(0xffffffffu, rs1, 2);
        l0 = l0 * c0 + rs0;
        l1 = l1 * c1 + rs1;

        #pragma unroll
        for (int nf = 0; nf < 8; nf++) {
            o[nf][0] *= c0; o[nf][1] *= c0;
            o[nf][2] *= c1; o[nf][3] *= c1;
        }
        __syncwarp();

        #pragma unroll
        for (int kc = 0; kc < 4; kc++) {
            uint32_t a0, a1, a2, a3;
            ldsm4(a0, a1, a2, a3, pBase + aPat + kc * 32);
            #pragma unroll
            for (int np = 0; np < 4; np++) {
                uint32_t b00, b01, b10, b11;
                ldsm4(b00, b01, b10, b11,
                      vBase + (uint32_t)(np * 16 * KSTRW) * 4 + bPat + kc * 32);
                mma_f16(o[2*np][0], o[2*np][1], o[2*np][2], o[2*np][3],
                        a0, a1, a2, a3, b00, b01);
                mma_f16(o[2*np+1][0], o[2*np+1][1], o[2*np+1][2], o[2*np+1][3],
                        a0, a1, a2, a3, b10, b11);
            }
        }
        __syncwarp();

        if (t + 1 < NSEQ / 64) { CP_WAIT(0); }
        __syncthreads();
    }

    float il0 = 1.f / l0, il1 = 1.f / l1;
    int r0 = tq0 + wid * 16 + quad;
    #pragma unroll
    for (int nf = 0; nf < 8; nf++) {
        int c = h * DHEAD + nf * 8 + tig * 2;
        *reinterpret_cast<uint32_t*>(aout + (size_t)r0 * DIMC + c) =
            h2pack(o[nf][0] * il0, o[nf][1] * il0);
        *reinterpret_cast<uint32_t*>(aout + (size_t)(r0 + 8) * DIMC + c) =
            h2pack(o[nf][2] * il1, o[nf][3] * il1);
    }
}

// ============================================================
// launch
// ============================================================
extern "C" void kernel_launch(void* const* d_in, const int* in_sizes, int n_in,
                              void* d_out, int out_size)
{
    const float* x      = (const float*)d_in[0];
    const float* norm_g = (const float*)d_in[1];
    const float* norm_b = (const float*)d_in[2];
    const float* W1     = (const float*)d_in[3];
    const float* b1     = (const float*)d_in[4];
    const float* qn_g   = (const float*)d_in[5];
    const float* qn_b   = (const float*)d_in[6];
    const float* kn_g   = (const float*)d_in[7];
    const float* kn_b   = (const float*)d_in[8];
    const float* Wao    = (const float*)d_in[9];
    const float* bao    = (const float*)d_in[10];
    const float* Wmo    = (const float*)d_in[11];
    const float* bmo    = (const float*)d_in[12];
    const float* W2     = (const float*)d_in[13];
    const float* b2     = (const float*)d_in[14];
    float*       out    = (float*)d_out;

    __half *norm, *fused, *attn, *w1t, *wfa, *wfm;
    float *beff;
    cudaGetSymbolAddress((void**)&norm,  g_norm);
    cudaGetSymbolAddress((void**)&fused, g_fused);
    cudaGetSymbolAddress((void**)&attn,  g_attn);
    cudaGetSymbolAddress((void**)&w1t,   g_w1t);
    cudaGetSymbolAddress((void**)&wfa,   g_wfa);
    cudaGetSymbolAddress((void**)&wfm,   g_wfm);
    cudaGetSymbolAddress((void**)&beff,  g_beff);

    cudaFuncSetAttribute(mma_gemm, cudaFuncAttributeMaxDynamicSharedMemorySize, GEMM_SMEM);
    cudaFuncSetAttribute(fold_kernel, cudaFuncAttributeMaxDynamicSharedMemorySize, GEMM_SMEM);
    cudaFuncSetAttribute(fattn_kernel, cudaFuncAttributeMaxDynamicSharedMemorySize, ATTN_SMEM);

    // merged weight prep, then merged folds + beff reduce (single wave)
    prep_kernel<<<13120, 256>>>(W1, W2, Wao, Wmo, bao, bmo, b2);
    fold_kernel<<<116, 256, GEMM_SMEM>>>();

    // 1) layernorm(x) -> half
    ln_kernel<<<NTOK, 256>>>(x, norm_g, norm_b, norm);

    // 2) fused = norm @ W1 + b1; qk->LN'd fused, V->g_vt transposed, mlp->gelu
    mma_gemm<<<dim3(FWP / 128, NTOK / 128), 256, GEMM_SMEM>>>(
        norm, DIMC, w1t, DIMC, DIMC,
        nullptr, 0, nullptr, 0, 0,
        fused, FWP, nullptr, 0, b1, FW, nullptr, 0,
        qn_g, qn_b, kn_g, kn_b, 1);

    // 3) flash attention (fp16, ldmatrix)
    fattn_kernel<<<dim3(NSEQ / 128, NHEADS, 2), 256, ATTN_SMEM>>>(fused, attn);

    // 4) out = x + attn @ wfa^T + gelu_hidden @ wfm^T + beff  (merged, mode 2)
    mma_gemm<<<dim3(DIMC / 128, NTOK / 128), 256, GEMM_SMEM>>>(
        attn, DIMC, wfa, DIMC, DIMC,
        fused + 3 * DIMC, FWP, wfm, HIDPAD, HIDPAD,
        nullptr, 0, out, DIMC, beff, DIMC, x, DIMC,
        nullptr, nullptr, nullptr, nullptr, 2);
}

// round 10
// speedup vs baseline: 9.1157x; 1.0924x over previous
#include <cuda_runtime.h>
#include <cuda_fp16.h>
#include <math.h>
#include <stdint.h>

// ---------------- problem constants ----------------
#define NTOK   4096              // B*N = 2*2048
#define DIMC   1024
#define NHEADS 16
#define DHEAD  64
#define MLPHID 716
#define FW     3788              // 3*DIM + MLP_HID (true width)
#define FWP    3840              // padded to 30*128
#define HIDPAD 768               // Wmo rows padded; K2 of apply
#define NSEQ   2048
#define LN_EPS 1e-6f
#define NSLICE 16

// ---------------- scratch (static device globals) ------
__device__ __half g_norm [NTOK * DIMC];
__device__ __half g_fused[NTOK * FWP];
__device__ __half g_vt   [2 * NHEADS * DHEAD * NSEQ];   // V transposed [b][h][d][n]
__device__ __half g_attn [NTOK * DIMC];
__device__ __half g_w1t  [FWP  * DIMC];
__device__ __half g_w2t  [DIMC * 2 * DIMC];
__device__ __half g_waor [DIMC * DIMC];
__device__ __half g_wmor [HIDPAD * DIMC];
__device__ __half g_wfa  [DIMC * DIMC];
__device__ __half g_wfm  [DIMC * HIDPAD];
__device__ float  g_beff [DIMC];
__device__ float  g_beffp[NSLICE * DIMC];

// ================= helpers =================
__device__ __forceinline__ uint32_t smem_u32(const void* p) {
    uint32_t a;
    asm("{ .reg .u64 t; cvta.to.shared.u64 t, %1; cvt.u32.u64 %0, t; }" : "=r"(a) : "l"(p));
    return a;
}
__device__ __forceinline__ void mma_f16(float& d0, float& d1, float& d2, float& d3,
                                        uint32_t a0, uint32_t a1, uint32_t a2, uint32_t a3,
                                        uint32_t b0, uint32_t b1)
{
    asm volatile(
        "mma.sync.aligned.m16n8k16.row.col.f32.f16.f16.f32 "
        "{%0,%1,%2,%3}, {%4,%5,%6,%7}, {%8,%9}, {%0,%1,%2,%3};"
        : "+f"(d0), "+f"(d1), "+f"(d2), "+f"(d3)
        : "r"(a0), "r"(a1), "r"(a2), "r"(a3), "r"(b0), "r"(b1));
}
__device__ __forceinline__ void ldsm4(uint32_t& r0, uint32_t& r1, uint32_t& r2, uint32_t& r3,
                                      uint32_t addr)
{
    asm volatile("ldmatrix.sync.aligned.m8n8.x4.shared.b16 {%0,%1,%2,%3}, [%4];"
                 : "=r"(r0), "=r"(r1), "=r"(r2), "=r"(r3) : "r"(addr));
}
__device__ __forceinline__ void stsm4(uint32_t addr, uint32_t r0, uint32_t r1,
                                      uint32_t r2, uint32_t r3)
{
    asm volatile("stmatrix.sync.aligned.m8n8.x4.shared.b16 [%0], {%1,%2,%3,%4};"
                 :: "r"(addr), "r"(r0), "r"(r1), "r"(r2), "r"(r3) : "memory");
}
__device__ __forceinline__ float gelu1(float x) {
    float u = 0.7978845608028654f * (x + 0.044715f * x * x * x);
    return 0.5f * x * (1.f + tanhf(u));
}
__device__ __forceinline__ uint32_t h2pack(float a, float b) {
    __half2 h = __floats2half2_rn(a, b);
    return *reinterpret_cast<uint32_t*>(&h);
}
#define CP_CA(dst, src) asm volatile("cp.async.ca.shared.global [%0], [%1], 16;" :: "r"(dst), "l"(src) : "memory")
#define CP_CG(dst, src) asm volatile("cp.async.cg.shared.global [%0], [%1], 16;" :: "r"(dst), "l"(src) : "memory")
#define CP_COMMIT()     asm volatile("cp.async.commit_group;" ::: "memory")
#define CP_WAIT(n)      asm volatile("cp.async.wait_group %0;" :: "n"(n) : "memory")

// ============================================================
// prep_w1: W1 [1024 x 3788] -> w1t [3840][1024] (half), 3840 blocks
// ============================================================
__global__ void prep_w1_kernel(const float* __restrict__ W1)
{
    __shared__ float t[32][33];
    int bid = blockIdx.x, tid = threadIdx.x;
    int tx = tid & 31, ty = tid >> 5;
    int bx = bid % (FWP / 32), by = bid / (FWP / 32);
    int n0 = bx * 32, k0 = by * 32;
    #pragma unroll
    for (int i = 0; i < 32; i += 8) {
        int n = n0 + tx;
        t[ty + i][tx] = (n < FW) ? W1[(size_t)(k0 + ty + i) * FW + n] : 0.f;
    }
    __syncthreads();
    #pragma unroll
    for (int i = 0; i < 32; i += 8)
        g_w1t[(size_t)(n0 + ty + i) * DIMC + k0 + tx] = __float2half(t[tx][ty + i]);
}

// ============================================================
// prep_rest: W2^T, Wao copy, Wmo copy(pad), beff partials — 9280 blocks
// [0,2048) W2t | [2048,6144) Wao | [6144,9216) Wmo | [9216,9280) beff
// ============================================================
__global__ void prep_rest_kernel(const float* __restrict__ W2,
                                 const float* __restrict__ Wao,
                                 const float* __restrict__ Wmo,
                                 const float* __restrict__ bao,
                                 const float* __restrict__ bmo,
                                 const float* __restrict__ b2)
{
    __shared__ float t[32][33];
    int bid = blockIdx.x, tid = threadIdx.x;
    int tx = tid & 31, ty = tid >> 5;

    if (bid < 2048) {
        int bx = bid % 32, by = bid / 32;
        int n0 = bx * 32, k0 = by * 32;
        #pragma unroll
        for (int i = 0; i < 32; i += 8)
            t[ty + i][tx] = W2[(size_t)(k0 + ty + i) * DIMC + n0 + tx];
        __syncthreads();
        #pragma unroll
        for (int i = 0; i < 32; i += 8)
            g_w2t[(size_t)(n0 + ty + i) * 2 * DIMC + k0 + tx] = __float2half(t[tx][ty + i]);
    } else if (bid < 6144) {
        int idx = (bid - 2048) * 256 + tid;
        g_waor[idx] = __float2half(Wao[idx]);
    } else if (bid < 9216) {
        int idx = (bid - 6144) * 256 + tid;
        int r = idx >> 10, c = idx & 1023;
        g_wmor[idx] = (r < MLPHID) ? __float2half(Wmo[(size_t)r * DIMC + c])
                                   : __float2half(0.f);
    } else {
        int b = bid - 9216;
        int n = (b & 3) * 256 + tid;
        int s = b >> 2;
        float acc = (s == 0) ? b2[n] : 0.f;
        int k0 = s * (2048 / NSLICE), k1 = k0 + (2048 / NSLICE);
        for (int k = k0; k < k1; k++) {
            float c = (k < 1024) ? bao[k] : bmo[k - 1024];
            acc += c * W2[(size_t)k * DIMC + n];
        }
        g_beffp[s * DIMC + n] = acc;
    }
}

// ============================================================
// merged fold launch: BOTH weight folds + beff reduce, one wave.
// blocks [0,64): wfa ; [64,112): wfm ; [112,116): beff reduce
// ============================================================
#define SSTRW 36
#define ABUFW (128 * SSTRW)
#define STAGEW (2 * ABUFW)
#define GEMM_SMEM (3 * STAGEW * 4)   // 110592 B

__global__ void __launch_bounds__(256, 2)
fold_kernel()
{
    extern __shared__ uint32_t smw[];
    int bid = blockIdx.x, tid = threadIdx.x;

    if (bid >= 112) {
        int n = (bid - 112) * 256 + tid;
        float s = 0.f;
        #pragma unroll
        for (int i = 0; i < NSLICE; i++) s += g_beffp[i * DIMC + n];
        g_beff[n] = s;
        return;
    }

    const __half* A; const __half* Bt; __half* C;
    int lda, ldb, ldc, bm, bn;
    if (bid < 64) {
        A = g_w2t;  lda = 2 * DIMC; Bt = g_waor; ldb = DIMC;
        C = g_wfa;  ldc = DIMC;
        bn = (bid & 7) * 128; bm = (bid >> 3) * 128;
    } else {
        int b = bid - 64;
        A = g_w2t + DIMC; lda = 2 * DIMC; Bt = g_wmor; ldb = DIMC;
        C = g_wfm; ldc = HIDPAD;
        bn = (b % 6) * 128; bm = (b / 6) * 128;
    }

    uint32_t sbase = smem_u32(smw);
    int wid = tid >> 5, lane = tid & 31;
    int quad = lane >> 2, tig = lane & 3;
    int wm = (wid & 1) * 64, wn = (wid >> 1) * 32;
    int lr = tid >> 3, lcw = (tid & 7) * 4;
    int lane15 = lane & 15;

    float acc[4][4][4];
    #pragma unroll
    for (int i = 0; i < 4; i++)
        #pragma unroll
        for (int j = 0; j < 4; j++)
            #pragma unroll
            for (int r = 0; r < 4; r++) acc[i][j][r] = 0.f;

    uint32_t aoff[4];
    #pragma unroll
    for (int mt = 0; mt < 4; mt++)
        aoff[mt] = (uint32_t)((wm + mt * 16 + lane15) * SSTRW) * 4 + (lane >> 4) * 16;
    uint32_t boff0 = (uint32_t)((wn + ((lane >> 4) << 3) + (lane & 7)) * SSTRW) * 4
                   + ((lane >> 3) & 1) * 16;
    uint32_t boff1 = boff0 + 16 * SSTRW * 4;

    const int nk = DIMC >> 6;     // 16

    auto prefetch = [&](int it, int st) {
        int k0 = it << 6;
        uint32_t dA = sbase + (uint32_t)st * STAGEW * 4;
        uint32_t dB = dA + ABUFW * 4;
        #pragma unroll
        for (int i = 0; i < 4; i++) {
            int r = i * 32 + lr;
            CP_CG(dA + (uint32_t)(r * SSTRW + lcw) * 4, A + (size_t)(bm + r) * lda + k0 + lcw * 2);
            CP_CG(dB + (uint32_t)(r * SSTRW + lcw) * 4, Bt + (size_t)(bn + r) * ldb + k0 + lcw * 2);
        }
        CP_COMMIT();
    };

    prefetch(0, 0);
    prefetch(1, 1);

    for (int it = 0; it < nk; it++) {
        if (it == nk - 1) { CP_WAIT(0); } else { CP_WAIT(1); }
        __syncthreads();

        uint32_t stA = sbase + (uint32_t)(it % 3) * STAGEW * 4;
        uint32_t stB = stA + ABUFW * 4;
        #pragma unroll
        for (int kk = 0; kk < 4; kk++) {
            uint32_t af[4][4], bf[4][2];
            #pragma unroll
            for (int mt = 0; mt < 4; mt++)
                ldsm4(af[mt][0], af[mt][1], af[mt][2], af[mt][3],
                      stA + aoff[mt] + kk * 32);
            ldsm4(bf[0][0], bf[0][1], bf[1][0], bf[1][1], stB + boff0 + kk * 32);
            ldsm4(bf[2][0], bf[2][1], bf[3][0], bf[3][1], stB + boff1 + kk * 32);
            #pragma unroll
            for (int mt = 0; mt < 4; mt++)
                #pragma unroll
                for (int nt = 0; nt < 4; nt++)
                    mma_f16(acc[mt][nt][0], acc[mt][nt][1],
                            acc[mt][nt][2], acc[mt][nt][3],
                            af[mt][0], af[mt][1], af[mt][2], af[mt][3],
                            bf[nt][0], bf[nt][1]);
        }
        if (it + 2 < nk) prefetch(it + 2, (it + 2) % 3);
    }

    #pragma unroll
    for (int mt = 0; mt < 4; mt++) {
        int r0 = bm + wm + mt * 16 + quad;
        #pragma unroll
        for (int nt = 0; nt < 4; nt++) {
            int c = bn + wn + nt * 8 + tig * 2;
            *reinterpret_cast<uint32_t*>(C + (size_t)r0 * ldc + c) =
                h2pack(acc[mt][nt][0], acc[mt][nt][1]);
            *reinterpret_cast<uint32_t*>(C + (size_t)(r0 + 8) * ldc + c) =
                h2pack(acc[mt][nt][2], acc[mt][nt][3]);
        }
    }
}

// ============================================================
// LayerNorm over DIM=1024, half output
// ============================================================
__global__ void ln_kernel(const float* __restrict__ x,
                          const float* __restrict__ g,
                          const float* __restrict__ b,
                          __half* __restrict__ out)
{
    int row = blockIdx.x;
    int tid = threadIdx.x;
    const float4 v = reinterpret_cast<const float4*>(x + (size_t)row * DIMC)[tid];

    float s  = v.x + v.y + v.z + v.w;
    float sq = v.x*v.x + v.y*v.y + v.z*v.z + v.w*v.w;
    #pragma unroll
    for (int o = 16; o > 0; o >>= 1) {
        s  += __shfl_xor_sync(0xffffffffu, s,  o);
        sq += __shfl_xor_sync(0xffffffffu, sq, o);
    }
    __shared__ float ws[8], wq[8];
    int warp = tid >> 5, lane = tid & 31;
    if (lane == 0) { ws[warp] = s; wq[warp] = sq; }
    __syncthreads();
    if (warp == 0) {
        float s2  = (lane < 8) ? ws[lane] : 0.f;
        float sq2 = (lane < 8) ? wq[lane] : 0.f;
        #pragma unroll
        for (int o = 4; o > 0; o >>= 1) {
            s2  += __shfl_xor_sync(0xffffffffu, s2,  o);
            sq2 += __shfl_xor_sync(0xffffffffu, sq2, o);
        }
        if (lane == 0) { ws[0] = s2; wq[0] = sq2; }
    }
    __syncthreads();
    float mean = ws[0] * (1.f / DIMC);
    float var  = wq[0] * (1.f / DIMC) - mean * mean;
    float rstd = rsqrtf(var + LN_EPS);

    float4 gg = reinterpret_cast<const float4*>(g)[tid];
    float4 bb = reinterpret_cast<const float4*>(b)[tid];
    uint2 o2;
    o2.x = h2pack((v.x - mean) * rstd * gg.x + bb.x,
                  (v.y - mean) * rstd * gg.y + bb.y);
    o2.y = h2pack((v.z - mean) * rstd * gg.z + bb.z,
                  (v.w - mean) * rstd * gg.w + bb.w);
    reinterpret_cast<uint2*>(out + (size_t)row * DIMC)[tid] = o2;
}

// ============================================================
// fp16 mma.sync GEMM, 3-stage cp.async pipeline, ldmatrix frags.
// Single __syncthreads per K-iteration (prefetch post-compute).
// mode 1: GEMM1 — region 0 (qk): FUSED per-head LN (+0.125 q scale)
//                 region 1: V->g_vt transposed   region 2: gelu
// mode 2: C float + bias + resid (apply)
// ============================================================
__global__ void __launch_bounds__(256, 2)
mma_gemm(const __half* __restrict__ A, int lda,
         const __half* __restrict__ Bt, int ldb, int K1,
         const __half* __restrict__ A2, int lda2,
         const __half* __restrict__ Bt2, int ldb2, int K2,
         __half* __restrict__ Ch, int ldch,
         float* __restrict__ Cf, int ldcf,
         const float* __restrict__ bias, int nbias,
         const float* __restrict__ resid, int ldr,
         const float* __restrict__ qg, const float* __restrict__ qb,
         const float* __restrict__ kg, const float* __restrict__ kb,
         int mode)
{
    extern __shared__ uint32_t smw[];
    uint32_t sbase = smem_u32(smw);
    int tid  = threadIdx.x;
    int wid  = tid >> 5, lane = tid & 31;
    int quad = lane >> 2, tig = lane & 3;
    int bm = blockIdx.y * 128, bn = blockIdx.x * 128;
    int wm = (wid & 1) * 64, wn = (wid >> 1) * 32;

    float acc[4][4][4];
    #pragma unroll
    for (int i = 0; i < 4; i++)
        #pragma unroll
        for (int j = 0; j < 4; j++)
            #pragma unroll
            for (int r = 0; r < 4; r++) acc[i][j][r] = 0.f;

    int lr = tid >> 3;
    int lcw = (tid & 7) * 4;

    int lane15 = lane & 15;
    uint32_t aoff[4];
    #pragma unroll
    for (int mt = 0; mt < 4; mt++)
        aoff[mt] = (uint32_t)((wm + mt * 16 + lane15) * SSTRW) * 4 + (lane >> 4) * 16;
    uint32_t boff0 = (uint32_t)((wn + ((lane >> 4) << 3) + (lane & 7)) * SSTRW) * 4
                   + ((lane >> 3) & 1) * 16;
    uint32_t boff1 = boff0 + 16 * SSTRW * 4;

    const int nk1 = K1 >> 6;
    const int nk  = nk1 + (K2 >> 6);

    auto prefetch = [&](int it, int st) {
        const __half* Ab; const __half* Bb; int la, lb, k0;
        if (it < nk1) { Ab = A;  Bb = Bt;  la = lda;  lb = ldb;  k0 = it << 6; }
        else          { Ab = A2; Bb = Bt2; la = lda2; lb = ldb2; k0 = (it - nk1) << 6; }
        uint32_t dA = sbase + (uint32_t)st * STAGEW * 4;
        uint32_t dB = dA + ABUFW * 4;
        #pragma unroll
        for (int i = 0; i < 4; i++) {
            int r = i * 32 + lr;
            CP_CG(dA + (uint32_t)(r * SSTRW + lcw) * 4, Ab + (size_t)(bm + r) * la + k0 + lcw * 2);
            CP_CG(dB + (uint32_t)(r * SSTRW + lcw) * 4, Bb + (size_t)(bn + r) * lb + k0 + lcw * 2);
        }
        CP_COMMIT();
    };

    prefetch(0, 0);
    if (nk > 1) prefetch(1, 1);

    for (int it = 0; it < nk; it++) {
        if (it == nk - 1) { CP_WAIT(0); } else { CP_WAIT(1); }
        __syncthreads();

        uint32_t stA = sbase + (uint32_t)(it % 3) * STAGEW * 4;
        uint32_t stB = stA + ABUFW * 4;

        #pragma unroll
        for (int kk = 0; kk < 4; kk++) {
            uint32_t af[4][4], bf[4][2];
            #pragma unroll
            for (int mt = 0; mt < 4; mt++)
                ldsm4(af[mt][0], af[mt][1], af[mt][2], af[mt][3],
                      stA + aoff[mt] + kk * 32);
            ldsm4(bf[0][0], bf[0][1], bf[1][0], bf[1][1], stB + boff0 + kk * 32);
            ldsm4(bf[2][0], bf[2][1], bf[3][0], bf[3][1], stB + boff1 + kk * 32);
            #pragma unroll
            for (int mt = 0; mt < 4; mt++)
                #pragma unroll
                for (int nt = 0; nt < 4; nt++)
                    mma_f16(acc[mt][nt][0], acc[mt][nt][1],
                            acc[mt][nt][2], acc[mt][nt][3],
                            af[mt][0], af[mt][1], af[mt][2], af[mt][3],
                            bf[nt][0], bf[nt][1]);
        }
        if (it + 2 < nk) prefetch(it + 2, (it + 2) % 3);
    }
    __syncthreads();   // protect smem reuse in region-0 epilogue

    int region = (mode != 1) ? -1 : ((bn < 2 * DIMC) ? 0 : (bn < 3 * DIMC ? 1 : 2));

    if (region == 0) {
        // ---------- fused per-head QK layernorm ----------
        float* ssum = reinterpret_cast<float*>(smw);       // [128][4]
        float* ssq  = ssum + 128 * 4;                      // [128][4]
        int ch = wn >> 5;

        #pragma unroll
        for (int mt = 0; mt < 4; mt++) {
            float slo = 0.f, sqlo = 0.f, shi = 0.f, sqhi = 0.f;
            #pragma unroll
            for (int nt = 0; nt < 4; nt++) {
                int c = bn + wn + nt * 8 + tig * 2;
                float b0 = bias[c], b1v = bias[c + 1];
                acc[mt][nt][0] += b0; acc[mt][nt][1] += b1v;
                acc[mt][nt][2] += b0; acc[mt][nt][3] += b1v;
                slo  += acc[mt][nt][0] + acc[mt][nt][1];
                sqlo += acc[mt][nt][0] * acc[mt][nt][0] + acc[mt][nt][1] * acc[mt][nt][1];
                shi  += acc[mt][nt][2] + acc[mt][nt][3];
                sqhi += acc[mt][nt][2] * acc[mt][nt][2] + acc[mt][nt][3] * acc[mt][nt][3];
            }
            slo  += __shfl_xor_sync(0xffffffffu, slo, 1);
            slo  += __shfl_xor_sync(0xffffffffu, slo, 2);
            sqlo += __shfl_xor_sync(0xffffffffu, sqlo, 1);
            sqlo += __shfl_xor_sync(0xffffffffu, sqlo, 2);
            shi  += __shfl_xor_sync(0xffffffffu, shi, 1);
            shi  += __shfl_xor_sync(0xffffffffu, shi, 2);
            sqhi += __shfl_xor_sync(0xffffffffu, sqhi, 1);
            sqhi += __shfl_xor_sync(0xffffffffu, sqhi, 2);
            if (tig == 0) {
                int rl = wm + mt * 16 + quad;
                ssum[rl * 4 + ch] = slo;        ssq[rl * 4 + ch] = sqlo;
                ssum[(rl + 8) * 4 + ch] = shi;  ssq[(rl + 8) * 4 + ch] = sqhi;
            }
        }
        __syncthreads();

        int hb = (wn >> 6) << 1;                 // head-half base (0 or 2)
        bool isq = (bn < DIMC);
        const float* gv = isq ? qg : kg;
        const float* bv = isq ? qb : kb;
        float qsc = isq ? 0.125f : 1.f;

        #pragma unroll
        for (int mt = 0; mt < 4; mt++) {
            int rl = wm + mt * 16 + quad;
            float mlo = (ssum[rl * 4 + hb] + ssum[rl * 4 + hb + 1]) * (1.f / 64.f);
            float vlo = (ssq[rl * 4 + hb] + ssq[rl * 4 + hb + 1]) * (1.f / 64.f) - mlo * mlo;
            float rlo = rsqrtf(vlo + LN_EPS);
            float mhi = (ssum[(rl + 8) * 4 + hb] + ssum[(rl + 8) * 4 + hb + 1]) * (1.f / 64.f);
            float vhi = (ssq[(rl + 8) * 4 + hb] + ssq[(rl + 8) * 4 + hb + 1]) * (1.f / 64.f) - mhi * mhi;
            float rhi = rsqrtf(vhi + LN_EPS);
            int r0 = bm + rl;
            #pragma unroll
            for (int nt = 0; nt < 4; nt++) {
                int c = bn + wn + nt * 8 + tig * 2;
                int d = c & 63;
                float g0 = gv[d], g1 = gv[d + 1];
                float e0 = bv[d], e1 = bv[d + 1];
                float o0 = ((acc[mt][nt][0] - mlo) * rlo * g0 + e0) * qsc;
                float o1 = ((acc[mt][nt][1] - mlo) * rlo * g1 + e1) * qsc;
                float o2 = ((acc[mt][nt][2] - mhi) * rhi * g0 + e0) * qsc;
                float o3 = ((acc[mt][nt][3] - mhi) * rhi * g1 + e1) * qsc;
                *reinterpret_cast<uint32_t*>(Ch + (size_t)r0 * ldch + c) = h2pack(o0, o1);
                *reinterpret_cast<uint32_t*>(Ch + (size_t)(r0 + 8) * ldch + c) = h2pack(o2, o3);
            }
        }
        return;
    }

    #pragma unroll
    for (int mt = 0; mt < 4; mt++) {
        int r0 = bm + wm + mt * 16 + quad;
        #pragma unroll
        for (int nt = 0; nt < 4; nt++) {
            int c = bn + wn + nt * 8 + tig * 2;
            float2 v0 = make_float2(acc[mt][nt][0], acc[mt][nt][1]);
            float2 v1 = make_float2(acc[mt][nt][2], acc[mt][nt][3]);
            if (bias) {
                float bx = (c     < nbias) ? bias[c]     : 0.f;
                float by = (c + 1 < nbias) ? bias[c + 1] : 0.f;
                v0.x += bx; v0.y += by;
                v1.x += bx; v1.y += by;
            }
            if (mode == 2) {
                float2 ra = *reinterpret_cast<const float2*>(resid + (size_t)r0 * ldr + c);
                float2 rb = *reinterpret_cast<const float2*>(resid + (size_t)(r0 + 8) * ldr + c);
                v0.x += ra.x; v0.y += ra.y;
                v1.x += rb.x; v1.y += rb.y;
                *reinterpret_cast<float2*>(Cf + (size_t)r0 * ldcf + c) = v0;
                *reinterpret_cast<float2*>(Cf + (size_t)(r0 + 8) * ldcf + c) = v1;
            } else if (region == 1) {
                int d = c - 2 * DIMC;
                int hh = d >> 6, dd = d & 63;
                int bbk = r0 >> 11, nn = r0 & 2047;
                size_t base = ((size_t)(bbk * NHEADS + hh) * DHEAD);
                g_vt[(base + dd    ) * NSEQ + nn    ] = __float2half(v0.x);
                g_vt[(base + dd + 1) * NSEQ + nn    ] = __float2half(v0.y);
                g_vt[(base + dd    ) * NSEQ + nn + 8] = __float2half(v1.x);
                g_vt[(base + dd + 1) * NSEQ + nn + 8] = __float2half(v1.y);
            } else {
                if (region == 2) {
                    v0.x = gelu1(v0.x); v0.y = gelu1(v0.y);
                    v1.x = gelu1(v1.x); v1.y = gelu1(v1.y);
                }
                *reinterpret_cast<uint32_t*>(Ch + (size_t)r0 * ldch + c) = h2pack(v0.x, v0.y);
                *reinterpret_cast<uint32_t*>(Ch + (size_t)(r0 + 8) * ldch + c) = h2pack(v1.x, v1.y);
            }
        }
    }
}

// ============================================================
// Flash attention, fp16 m16n8k16, ldmatrix/stmatrix fragments.
// ============================================================
#define KSTRW 36
#define QWORDS (128 * KSTRW)
#define KVWORDS (64 * KSTRW)
#define ATTN_SMEM ((QWORDS + 4 * KVWORDS) * 4)   // 55296 B

__global__ void __launch_bounds__(256, 2)
fattn_kernel(const __half* __restrict__ fused, __half* __restrict__ aout)
{
    extern __shared__ uint32_t smw[];
    uint32_t sbase = smem_u32(smw);

    int tid  = threadIdx.x;
    int wid  = tid >> 5, lane = tid & 31;
    int quad = lane >> 2, tig = lane & 3;
    int lane15 = lane & 15;
    int h  = blockIdx.y;
    int bb = blockIdx.z;
    int q0 = blockIdx.x * 128;
    int tq0 = bb * NSEQ + q0;
    int kvb = bb * NSEQ;
    const __half* vtb = g_vt + (size_t)(bb * NHEADS + h) * DHEAD * NSEQ;

    auto prefetch_kv = [&](int kt, int buf) {
        uint32_t dK = sbase + (uint32_t)(QWORDS + buf * 2 * KVWORDS) * 4;
        uint32_t dV = dK + KVWORDS * 4;
        #pragma unroll
        for (int i = 0; i < 2; i++) {
            int idx = i * 256 + tid;
            int r = idx >> 3, chh = (idx & 7) * 8;
            CP_CG(dK + (uint32_t)(r * KSTRW + chh / 2) * 4,
                  fused + (size_t)(kvb + kt + r) * FWP + DIMC + h * DHEAD + chh);
            CP_CG(dV + (uint32_t)(r * KSTRW + chh / 2) * 4,
                  vtb + (size_t)r * NSEQ + kt + chh);
        }
        CP_COMMIT();
    };

    #pragma unroll
    for (int i = 0; i < 4; i++) {
        int idx = i * 256 + tid;
        int r = idx >> 3, chh = (idx & 7) * 8;
        CP_CA(sbase + (uint32_t)(r * KSTRW + chh / 2) * 4,
              fused + (size_t)(tq0 + r) * FWP + h * DHEAD + chh);
    }
    prefetch_kv(0, 0);
    CP_WAIT(0);
    __syncthreads();

    uint32_t aPat = (uint32_t)(lane15 * KSTRW) * 4 + (lane >> 4) * 16;
    uint32_t bPat = (uint32_t)((((lane >> 4) << 3) + (lane & 7)) * KSTRW) * 4
                  + ((lane >> 3) & 1) * 16;
    uint32_t sPat = (uint32_t)(((((lane >> 3) & 1) << 3) + (lane & 7)) * KSTRW) * 4
                  + (lane >> 4) * 16;

    uint32_t qf[4][4];
    {
        uint32_t qbase = sbase + (uint32_t)(wid * 16 * KSTRW) * 4 + aPat;
        #pragma unroll
        for (int kc = 0; kc < 4; kc++)
            ldsm4(qf[kc][0], qf[kc][1], qf[kc][2], qf[kc][3], qbase + kc * 32);
    }
    uint32_t pBase = sbase + (uint32_t)(wid * 16 * KSTRW) * 4;

    float o[8][4];
    #pragma unroll
    for (int i = 0; i < 8; i++)
        #pragma unroll
        for (int j = 0; j < 4; j++) o[i][j] = 0.f;
    float m0 = -1e30f, m1 = -1e30f, l0 = 0.f, l1 = 0.f;

    for (int t = 0; t < NSEQ / 64; t++) {
        int b = t & 1;
        if (t + 1 < NSEQ / 64) prefetch_kv((t + 1) * 64, b ^ 1);

        uint32_t kBase = sbase + (uint32_t)(QWORDS + b * 2 * KVWORDS) * 4;
        uint32_t vBase = kBase + KVWORDS * 4;

        float sc[8][4];
        #pragma unroll
        for (int i = 0; i < 8; i++)
            #pragma unroll
            for (int j = 0; j < 4; j++) sc[i][j] = 0.f;

        #pragma unroll
        for (int kc = 0; kc < 4; kc++) {
            #pragma unroll
            for (int np = 0; np < 4; np++) {
                uint32_t b00, b01, b10, b11;
                ldsm4(b00, b01, b10, b11,
                      kBase + (uint32_t)(np * 16 * KSTRW) * 4 + bPat + kc * 32);
                mma_f16(sc[2*np][0], sc[2*np][1], sc[2*np][2], sc[2*np][3],
                        qf[kc][0], qf[kc][1], qf[kc][2], qf[kc][3], b00, b01);
                mma_f16(sc[2*np+1][0], sc[2*np+1][1], sc[2*np+1][2], sc[2*np+1][3],
                        qf[kc][0], qf[kc][1], qf[kc][2], qf[kc][3], b10, b11);
            }
        }

        float rm0 = -1e30f, rm1 = -1e30f;
        #pragma unroll
        for (int nf = 0; nf < 8; nf++) {
            rm0 = fmaxf(rm0, fmaxf(sc[nf][0], sc[nf][1]));
            rm1 = fmaxf(rm1, fmaxf(sc[nf][2], sc[nf][3]));
        }
        rm0 = fmaxf(rm0, __shfl_xor_sync(0xffffffffu, rm0, 1));
        rm0 = fmaxf(rm0, __shfl_xor_sync(0xffffffffu, rm0, 2));
        rm1 = fmaxf(rm1, __shfl_xor_sync(0xffffffffu, rm1, 1));
        rm1 = fmaxf(rm1, __shfl_xor_sync(0xffffffffu, rm1, 2));

        float mn0 = fmaxf(m0, rm0), mn1 = fmaxf(m1, rm1);
        float c0 = __expf(m0 - mn0), c1 = __expf(m1 - mn1);
        m0 = mn0; m1 = mn1;

        float rs0 = 0.f, rs1 = 0.f;
        uint32_t hl0[8], hl1[8];
        #pragma unroll
        for (int nf = 0; nf < 8; nf++) {
            float p0 = __expf(sc[nf][0] - m0);
            float p1 = __expf(sc[nf][1] - m0);
            float p2 = __expf(sc[nf][2] - m1);
            float p3 = __expf(sc[nf][3] - m1);
            rs0 += p0 + p1; rs1 += p2 + p3;
            hl0[nf] = h2pack(p0, p1);
            hl1[nf] = h2pack(p2, p3);
        }
        #pragma unroll
        for (int np = 0; np < 4; np++)
            stsm4(pBase + sPat + np * 32,
                  hl0[2*np], hl1[2*np], hl0[2*np+1], hl1[2*np+1]);

        rs0 += __shfl_xor_sync(0xffffffffu, rs0, 1);
        rs0 += __shfl_xor_sync(0xffffffffu, rs0, 2);
        rs1 += __shfl_xor_sync(0xffffffffu, rs1, 1);
        rs1 += __shfl_xor_sync(0xffffffffu, rs1, 2);
        l0 = l0 * c0 + rs0;
        l1 = l1 * c1 + rs1;

        #pragma unroll
        for (int nf = 0; nf < 8; nf++) {
            o[nf][0] *= c0; o[nf][1] *= c0;
            o[nf][2] *= c1; o[nf][3] *= c1;
        }
        __syncwarp();

        #pragma unroll
        for (int kc = 0; kc < 4; kc++) {
            uint32_t a0, a1, a2, a3;
            ldsm4(a0, a1, a2, a3, pBase + aPat + kc * 32);
            #pragma unroll
            for (int np = 0; np < 4; np++) {
                uint32_t b00, b01, b10, b11;
                ldsm4(b00, b01, b10, b11,
                      vBase + (uint32_t)(np * 16 * KSTRW) * 4 + bPat + kc * 32);
                mma_f16(o[2*np][0], o[2*np][1], o[2*np][2], o[2*np][3],
                        a0, a1, a2, a3, b00, b01);
                mma_f16(o[2*np+1][0], o[2*np+1][1], o[2*np+1][2], o[2*np+1][3],
                        a0, a1, a2, a3, b10, b11);
            }
        }
        __syncwarp();

        if (t + 1 < NSEQ / 64) { CP_WAIT(0); }
        __syncthreads();
    }

    float il0 = 1.f / l0, il1 = 1.f / l1;
    int r0 = tq0 + wid * 16 + quad;
    #pragma unroll
    for (int nf = 0; nf < 8; nf++) {
        int c = h * DHEAD + nf * 8 + tig * 2;
        *reinterpret_cast<uint32_t*>(aout + (size_t)r0 * DIMC + c) =
            h2pack(o[nf][0] * il0, o[nf][1] * il0);
        *reinterpret_cast<uint32_t*>(aout + (size_t)(r0 + 8) * DIMC + c) =
            h2pack(o[nf][2] * il1, o[nf][3] * il1);
    }
}

// ============================================================
// launch — dual-stream fork/join (graph-capture compatible)
// ============================================================
extern "C" void kernel_launch(void* const* d_in, const int* in_sizes, int n_in,
                              void* d_out, int out_size)
{
    const float* x      = (const float*)d_in[0];
    const float* norm_g = (const float*)d_in[1];
    const float* norm_b = (const float*)d_in[2];
    const float* W1     = (const float*)d_in[3];
    const float* b1     = (const float*)d_in[4];
    const float* qn_g   = (const float*)d_in[5];
    const float* qn_b   = (const float*)d_in[6];
    const float* kn_g   = (const float*)d_in[7];
    const float* kn_b   = (const float*)d_in[8];
    const float* Wao    = (const float*)d_in[9];
    const float* bao    = (const float*)d_in[10];
    const float* Wmo    = (const float*)d_in[11];
    const float* bmo    = (const float*)d_in[12];
    const float* W2     = (const float*)d_in[13];
    const float* b2     = (const float*)d_in[14];
    float*       out    = (float*)d_out;

    __half *norm, *fused, *attn, *w1t, *wfa, *wfm;
    float *beff;
    cudaGetSymbolAddress((void**)&norm,  g_norm);
    cudaGetSymbolAddress((void**)&fused, g_fused);
    cudaGetSymbolAddress((void**)&attn,  g_attn);
    cudaGetSymbolAddress((void**)&w1t,   g_w1t);
    cudaGetSymbolAddress((void**)&wfa,   g_wfa);
    cudaGetSymbolAddress((void**)&wfm,   g_wfm);
    cudaGetSymbolAddress((void**)&beff,  g_beff);

    static bool inited = false;
    static cudaStream_t s2;
    static cudaEvent_t ev1, ev2;
    if (!inited) {
        cudaStreamCreateWithFlags(&s2, cudaStreamNonBlocking);
        cudaEventCreateWithFlags(&ev1, cudaEventDisableTiming);
        cudaEventCreateWithFlags(&ev2, cudaEventDisableTiming);
        cudaFuncSetAttribute(mma_gemm, cudaFuncAttributeMaxDynamicSharedMemorySize, GEMM_SMEM);
        cudaFuncSetAttribute(fold_kernel, cudaFuncAttributeMaxDynamicSharedMemorySize, GEMM_SMEM);
        cudaFuncSetAttribute(fattn_kernel, cudaFuncAttributeMaxDynamicSharedMemorySize, ATTN_SMEM);
        inited = true;
    }

    // ---- fork: side chain (prep_rest -> fold) feeds only the final apply ----
    cudaEventRecord(ev1, 0);
    cudaStreamWaitEvent(s2, ev1, 0);
    prep_rest_kernel<<<9280, 256, 0, s2>>>(W2, Wao, Wmo, bao, bmo, b2);
    fold_kernel<<<116, 256, GEMM_SMEM, s2>>>();
    cudaEventRecord(ev2, s2);

    // ---- main chain ----
    prep_w1_kernel<<<3840, 256>>>(W1);
    ln_kernel<<<NTOK, 256>>>(x, norm_g, norm_b, norm);

    // GEMM1: qk->LN'd fused, V->g_vt transposed, mlp->gelu
    mma_gemm<<<dim3(FWP / 128, NTOK / 128), 256, GEMM_SMEM>>>(
        norm, DIMC, w1t, DIMC, DIMC,
        nullptr, 0, nullptr, 0, 0,
        fused, FWP, nullptr, 0, b1, FW, nullptr, 0,
        qn_g, qn_b, kn_g, kn_b, 1);

    // flash attention
    fattn_kernel<<<dim3(NSEQ / 128, NHEADS, 2), 256, ATTN_SMEM>>>(fused, attn);

    // ---- join, then apply: out = x + attn @ wfa^T + gelu_hidden @ wfm^T + beff
    cudaStreamWaitEvent(0, ev2, 0);
    mma_gemm<<<dim3(DIMC / 128, NTOK / 128), 256, GEMM_SMEM>>>(
        attn, DIMC, wfa, DIMC, DIMC,
        fused + 3 * DIMC, FWP, wfm, HIDPAD, HIDPAD,
        nullptr, 0, out, DIMC, beff, DIMC, x, DIMC,
        nullptr, nullptr, nullptr, nullptr, 2);
}

// round 11
// speedup vs baseline: 9.6664x; 1.0604x over previous
#include <cuda_runtime.h>
#include <cuda_fp16.h>
#include <math.h>
#include <stdint.h>

// ---------------- problem constants ----------------
#define NTOK   4096              // B*N = 2*2048
#define DIMC   1024
#define NHEADS 16
#define DHEAD  64
#define MLPHID 716
#define FW     3788              // 3*DIM + MLP_HID (true width)
#define FWP    3840              // padded to 30*128
#define HIDPAD 768               // Wmo rows padded; K2 of apply
#define NSEQ   2048
#define LN_EPS 1e-6f
#define NSLICE 16

// ---------------- scratch (static device globals) ------
__device__ __half g_norm [NTOK * DIMC];
__device__ __half g_fused[NTOK * FWP];
__device__ __half g_vt   [2 * NHEADS * DHEAD * NSEQ];   // V transposed [b][h][d][n]
__device__ __half g_attn [NTOK * DIMC];
__device__ __half g_w1t  [FWP  * DIMC];
__device__ __half g_w2t  [DIMC * 2 * DIMC];
__device__ __half g_waor [DIMC * DIMC];
__device__ __half g_wmor [HIDPAD * DIMC];
__device__ __half g_wfa  [DIMC * DIMC];
__device__ __half g_wfm  [DIMC * HIDPAD];
__device__ float  g_beff [DIMC];
__device__ float  g_beffp[NSLICE * DIMC];

// ================= helpers =================
__device__ __forceinline__ uint32_t smem_u32(const void* p) {
    uint32_t a;
    asm("{ .reg .u64 t; cvta.to.shared.u64 t, %1; cvt.u32.u64 %0, t; }" : "=r"(a) : "l"(p));
    return a;
}
__device__ __forceinline__ void mma_f16(float& d0, float& d1, float& d2, float& d3,
                                        uint32_t a0, uint32_t a1, uint32_t a2, uint32_t a3,
                                        uint32_t b0, uint32_t b1)
{
    asm volatile(
        "mma.sync.aligned.m16n8k16.row.col.f32.f16.f16.f32 "
        "{%0,%1,%2,%3}, {%4,%5,%6,%7}, {%8,%9}, {%0,%1,%2,%3};"
        : "+f"(d0), "+f"(d1), "+f"(d2), "+f"(d3)
        : "r"(a0), "r"(a1), "r"(a2), "r"(a3), "r"(b0), "r"(b1));
}
__device__ __forceinline__ void ldsm4(uint32_t& r0, uint32_t& r1, uint32_t& r2, uint32_t& r3,
                                      uint32_t addr)
{
    asm volatile("ldmatrix.sync.aligned.m8n8.x4.shared.b16 {%0,%1,%2,%3}, [%4];"
                 : "=r"(r0), "=r"(r1), "=r"(r2), "=r"(r3) : "r"(addr));
}
__device__ __forceinline__ void stsm4(uint32_t addr, uint32_t r0, uint32_t r1,
                                      uint32_t r2, uint32_t r3)
{
    asm volatile("stmatrix.sync.aligned.m8n8.x4.shared.b16 [%0], {%1,%2,%3,%4};"
                 :: "r"(addr), "r"(r0), "r"(r1), "r"(r2), "r"(r3) : "memory");
}
__device__ __forceinline__ float gelu1(float x) {
    float u = 0.7978845608028654f * (x + 0.044715f * x * x * x);
    return 0.5f * x * (1.f + tanhf(u));
}
__device__ __forceinline__ uint32_t h2pack(float a, float b) {
    __half2 h = __floats2half2_rn(a, b);
    return *reinterpret_cast<uint32_t*>(&h);
}
#define CP_CA(dst, src) asm volatile("cp.async.ca.shared.global [%0], [%1], 16;" :: "r"(dst), "l"(src) : "memory")
#define CP_CG(dst, src) asm volatile("cp.async.cg.shared.global [%0], [%1], 16;" :: "r"(dst), "l"(src) : "memory")
#define CP_COMMIT()     asm volatile("cp.async.commit_group;" ::: "memory")
#define CP_WAIT(n)      asm volatile("cp.async.wait_group %0;" :: "n"(n) : "memory")

// ============================================================
// prep_w1: W1 [1024 x 3788] -> w1t [3840][1024] (half), 3840 blocks
// ============================================================
__global__ void prep_w1_kernel(const float* __restrict__ W1)
{
    __shared__ float t[32][33];
    int bid = blockIdx.x, tid = threadIdx.x;
    int tx = tid & 31, ty = tid >> 5;
    int bx = bid % (FWP / 32), by = bid / (FWP / 32);
    int n0 = bx * 32, k0 = by * 32;
    #pragma unroll
    for (int i = 0; i < 32; i += 8) {
        int n = n0 + tx;
        t[ty + i][tx] = (n < FW) ? W1[(size_t)(k0 + ty + i) * FW + n] : 0.f;
    }
    __syncthreads();
    #pragma unroll
    for (int i = 0; i < 32; i += 8)
        g_w1t[(size_t)(n0 + ty + i) * DIMC + k0 + tx] = __float2half(t[tx][ty + i]);
}

// ============================================================
// prep_rest: W2^T, Wao copy, Wmo copy(pad), beff partials — 9280 blocks
// ============================================================
__global__ void prep_rest_kernel(const float* __restrict__ W2,
                                 const float* __restrict__ Wao,
                                 const float* __restrict__ Wmo,
                                 const float* __restrict__ bao,
                                 const float* __restrict__ bmo,
                                 const float* __restrict__ b2)
{
    __shared__ float t[32][33];
    int bid = blockIdx.x, tid = threadIdx.x;
    int tx = tid & 31, ty = tid >> 5;

    if (bid < 2048) {
        int bx = bid % 32, by = bid / 32;
        int n0 = bx * 32, k0 = by * 32;
        #pragma unroll
        for (int i = 0; i < 32; i += 8)
            t[ty + i][tx] = W2[(size_t)(k0 + ty + i) * DIMC + n0 + tx];
        __syncthreads();
        #pragma unroll
        for (int i = 0; i < 32; i += 8)
            g_w2t[(size_t)(n0 + ty + i) * 2 * DIMC + k0 + tx] = __float2half(t[tx][ty + i]);
    } else if (bid < 6144) {
        int idx = (bid - 2048) * 256 + tid;
        g_waor[idx] = __float2half(Wao[idx]);
    } else if (bid < 9216) {
        int idx = (bid - 6144) * 256 + tid;
        int r = idx >> 10, c = idx & 1023;
        g_wmor[idx] = (r < MLPHID) ? __float2half(Wmo[(size_t)r * DIMC + c])
                                   : __float2half(0.f);
    } else {
        int b = bid - 9216;
        int n = (b & 3) * 256 + tid;
        int s = b >> 2;
        float acc = (s == 0) ? b2[n] : 0.f;
        int k0 = s * (2048 / NSLICE), k1 = k0 + (2048 / NSLICE);
        for (int k = k0; k < k1; k++) {
            float c = (k < 1024) ? bao[k] : bmo[k - 1024];
            acc += c * W2[(size_t)k * DIMC + n];
        }
        g_beffp[s * DIMC + n] = acc;
    }
}

// ============================================================
// merged fold launch: BOTH weight folds + beff reduce, one wave.
// ============================================================
#define SSTRW 36
#define ABUFW (128 * SSTRW)
#define STAGEW (2 * ABUFW)
#define GEMM_SMEM (3 * STAGEW * 4)   // 110592 B

__global__ void __launch_bounds__(256, 2)
fold_kernel()
{
    extern __shared__ uint32_t smw[];
    int bid = blockIdx.x, tid = threadIdx.x;

    if (bid >= 112) {
        int n = (bid - 112) * 256 + tid;
        float s = 0.f;
        #pragma unroll
        for (int i = 0; i < NSLICE; i++) s += g_beffp[i * DIMC + n];
        g_beff[n] = s;
        return;
    }

    const __half* A; const __half* Bt; __half* C;
    int lda, ldb, ldc, bm, bn;
    if (bid < 64) {
        A = g_w2t;  lda = 2 * DIMC; Bt = g_waor; ldb = DIMC;
        C = g_wfa;  ldc = DIMC;
        bn = (bid & 7) * 128; bm = (bid >> 3) * 128;
    } else {
        int b = bid - 64;
        A = g_w2t + DIMC; lda = 2 * DIMC; Bt = g_wmor; ldb = DIMC;
        C = g_wfm; ldc = HIDPAD;
        bn = (b % 6) * 128; bm = (b / 6) * 128;
    }

    uint32_t sbase = smem_u32(smw);
    int wid = tid >> 5, lane = tid & 31;
    int quad = lane >> 2, tig = lane & 3;
    int wm = (wid & 1) * 64, wn = (wid >> 1) * 32;
    int lr = tid >> 3, lcw = (tid & 7) * 4;
    int lane15 = lane & 15;

    float acc[4][4][4];
    #pragma unroll
    for (int i = 0; i < 4; i++)
        #pragma unroll
        for (int j = 0; j < 4; j++)
            #pragma unroll
            for (int r = 0; r < 4; r++) acc[i][j][r] = 0.f;

    uint32_t aoff[4];
    #pragma unroll
    for (int mt = 0; mt < 4; mt++)
        aoff[mt] = (uint32_t)((wm + mt * 16 + lane15) * SSTRW) * 4 + (lane >> 4) * 16;
    uint32_t boff0 = (uint32_t)((wn + ((lane >> 4) << 3) + (lane & 7)) * SSTRW) * 4
                   + ((lane >> 3) & 1) * 16;
    uint32_t boff1 = boff0 + 16 * SSTRW * 4;

    const int nk = DIMC >> 6;     // 16

    auto prefetch = [&](int it, int st) {
        int k0 = it << 6;
        uint32_t dA = sbase + (uint32_t)st * STAGEW * 4;
        uint32_t dB = dA + ABUFW * 4;
        #pragma unroll
        for (int i = 0; i < 4; i++) {
            int r = i * 32 + lr;
            CP_CG(dA + (uint32_t)(r * SSTRW + lcw) * 4, A + (size_t)(bm + r) * lda + k0 + lcw * 2);
            CP_CG(dB + (uint32_t)(r * SSTRW + lcw) * 4, Bt + (size_t)(bn + r) * ldb + k0 + lcw * 2);
        }
        CP_COMMIT();
    };

    prefetch(0, 0);
    prefetch(1, 1);

    for (int it = 0; it < nk; it++) {
        if (it == nk - 1) { CP_WAIT(0); } else { CP_WAIT(1); }
        __syncthreads();

        uint32_t stA = sbase + (uint32_t)(it % 3) * STAGEW * 4;
        uint32_t stB = stA + ABUFW * 4;
        #pragma unroll
        for (int kk = 0; kk < 4; kk++) {
            uint32_t af[4][4], bf[4][2];
            #pragma unroll
            for (int mt = 0; mt < 4; mt++)
                ldsm4(af[mt][0], af[mt][1], af[mt][2], af[mt][3],
                      stA + aoff[mt] + kk * 32);
            ldsm4(bf[0][0], bf[0][1], bf[1][0], bf[1][1], stB + boff0 + kk * 32);
            ldsm4(bf[2][0], bf[2][1], bf[3][0], bf[3][1], stB + boff1 + kk * 32);
            #pragma unroll
            for (int mt = 0; mt < 4; mt++)
                #pragma unroll
                for (int nt = 0; nt < 4; nt++)
                    mma_f16(acc[mt][nt][0], acc[mt][nt][1],
                            acc[mt][nt][2], acc[mt][nt][3],
                            af[mt][0], af[mt][1], af[mt][2], af[mt][3],
                            bf[nt][0], bf[nt][1]);
        }
        if (it + 2 < nk) prefetch(it + 2, (it + 2) % 3);
    }

    #pragma unroll
    for (int mt = 0; mt < 4; mt++) {
        int r0 = bm + wm + mt * 16 + quad;
        #pragma unroll
        for (int nt = 0; nt < 4; nt++) {
            int c = bn + wn + nt * 8 + tig * 2;
            *reinterpret_cast<uint32_t*>(C + (size_t)r0 * ldc + c) =
                h2pack(acc[mt][nt][0], acc[mt][nt][1]);
            *reinterpret_cast<uint32_t*>(C + (size_t)(r0 + 8) * ldc + c) =
                h2pack(acc[mt][nt][2], acc[mt][nt][3]);
        }
    }
}

// ============================================================
// LayerNorm over DIM=1024, half output
// ============================================================
__global__ void ln_kernel(const float* __restrict__ x,
                          const float* __restrict__ g,
                          const float* __restrict__ b,
                          __half* __restrict__ out)
{
    int row = blockIdx.x;
    int tid = threadIdx.x;
    const float4 v = reinterpret_cast<const float4*>(x + (size_t)row * DIMC)[tid];

    float s  = v.x + v.y + v.z + v.w;
    float sq = v.x*v.x + v.y*v.y + v.z*v.z + v.w*v.w;
    #pragma unroll
    for (int o = 16; o > 0; o >>= 1) {
        s  += __shfl_xor_sync(0xffffffffu, s,  o);
        sq += __shfl_xor_sync(0xffffffffu, sq, o);
    }
    __shared__ float ws[8], wq[8];
    int warp = tid >> 5, lane = tid & 31;
    if (lane == 0) { ws[warp] = s; wq[warp] = sq; }
    __syncthreads();
    if (warp == 0) {
        float s2  = (lane < 8) ? ws[lane] : 0.f;
        float sq2 = (lane < 8) ? wq[lane] : 0.f;
        #pragma unroll
        for (int o = 4; o > 0; o >>= 1) {
            s2  += __shfl_xor_sync(0xffffffffu, s2,  o);
            sq2 += __shfl_xor_sync(0xffffffffu, sq2, o);
        }
        if (lane == 0) { ws[0] = s2; wq[0] = sq2; }
    }
    __syncthreads();
    float mean = ws[0] * (1.f / DIMC);
    float var  = wq[0] * (1.f / DIMC) - mean * mean;
    float rstd = rsqrtf(var + LN_EPS);

    float4 gg = reinterpret_cast<const float4*>(g)[tid];
    float4 bb = reinterpret_cast<const float4*>(b)[tid];
    uint2 o2;
    o2.x = h2pack((v.x - mean) * rstd * gg.x + bb.x,
                  (v.y - mean) * rstd * gg.y + bb.y);
    o2.y = h2pack((v.z - mean) * rstd * gg.z + bb.z,
                  (v.w - mean) * rstd * gg.w + bb.w);
    reinterpret_cast<uint2*>(out + (size_t)row * DIMC)[tid] = o2;
}

// ============================================================
// fp16 mma.sync GEMM, 3-stage cp.async pipeline, ldmatrix frags.
// mode 1: GEMM1 — region 0 (qk): FUSED per-head LN (+0.125 q scale)
//                 region 1: V->g_vt transposed   region 2: gelu
// mode 2: C float + bias + resid (apply)
// ============================================================
__global__ void __launch_bounds__(256, 2)
mma_gemm(const __half* __restrict__ A, int lda,
         const __half* __restrict__ Bt, int ldb, int K1,
         const __half* __restrict__ A2, int lda2,
         const __half* __restrict__ Bt2, int ldb2, int K2,
         __half* __restrict__ Ch, int ldch,
         float* __restrict__ Cf, int ldcf,
         const float* __restrict__ bias, int nbias,
         const float* __restrict__ resid, int ldr,
         const float* __restrict__ qg, const float* __restrict__ qb,
         const float* __restrict__ kg, const float* __restrict__ kb,
         int mode)
{
    extern __shared__ uint32_t smw[];
    uint32_t sbase = smem_u32(smw);
    int tid  = threadIdx.x;
    int wid  = tid >> 5, lane = tid & 31;
    int quad = lane >> 2, tig = lane & 3;
    int bm = blockIdx.y * 128, bn = blockIdx.x * 128;
    int wm = (wid & 1) * 64, wn = (wid >> 1) * 32;

    float acc[4][4][4];
    #pragma unroll
    for (int i = 0; i < 4; i++)
        #pragma unroll
        for (int j = 0; j < 4; j++)
            #pragma unroll
            for (int r = 0; r < 4; r++) acc[i][j][r] = 0.f;

    int lr = tid >> 3;
    int lcw = (tid & 7) * 4;

    int lane15 = lane & 15;
    uint32_t aoff[4];
    #pragma unroll
    for (int mt = 0; mt < 4; mt++)
        aoff[mt] = (uint32_t)((wm + mt * 16 + lane15) * SSTRW) * 4 + (lane >> 4) * 16;
    uint32_t boff0 = (uint32_t)((wn + ((lane >> 4) << 3) + (lane & 7)) * SSTRW) * 4
                   + ((lane >> 3) & 1) * 16;
    uint32_t boff1 = boff0 + 16 * SSTRW * 4;

    const int nk1 = K1 >> 6;
    const int nk  = nk1 + (K2 >> 6);

    auto prefetch = [&](int it, int st) {
        const __half* Ab; const __half* Bb; int la, lb, k0;
        if (it < nk1) { Ab = A;  Bb = Bt;  la = lda;  lb = ldb;  k0 = it << 6; }
        else          { Ab = A2; Bb = Bt2; la = lda2; lb = ldb2; k0 = (it - nk1) << 6; }
        uint32_t dA = sbase + (uint32_t)st * STAGEW * 4;
        uint32_t dB = dA + ABUFW * 4;
        #pragma unroll
        for (int i = 0; i < 4; i++) {
            int r = i * 32 + lr;
            CP_CG(dA + (uint32_t)(r * SSTRW + lcw) * 4, Ab + (size_t)(bm + r) * la + k0 + lcw * 2);
            CP_CG(dB + (uint32_t)(r * SSTRW + lcw) * 4, Bb + (size_t)(bn + r) * lb + k0 + lcw * 2);
        }
        CP_COMMIT();
    };

    prefetch(0, 0);
    if (nk > 1) prefetch(1, 1);

    for (int it = 0; it < nk; it++) {
        if (it == nk - 1) { CP_WAIT(0); } else { CP_WAIT(1); }
        __syncthreads();

        uint32_t stA = sbase + (uint32_t)(it % 3) * STAGEW * 4;
        uint32_t stB = stA + ABUFW * 4;

        #pragma unroll
        for (int kk = 0; kk < 4; kk++) {
            uint32_t af[4][4], bf[4][2];
            #pragma unroll
            for (int mt = 0; mt < 4; mt++)
                ldsm4(af[mt][0], af[mt][1], af[mt][2], af[mt][3],
                      stA + aoff[mt] + kk * 32);
            ldsm4(bf[0][0], bf[0][1], bf[1][0], bf[1][1], stB + boff0 + kk * 32);
            ldsm4(bf[2][0], bf[2][1], bf[3][0], bf[3][1], stB + boff1 + kk * 32);
            #pragma unroll
            for (int mt = 0; mt < 4; mt++)
                #pragma unroll
                for (int nt = 0; nt < 4; nt++)
                    mma_f16(acc[mt][nt][0], acc[mt][nt][1],
                            acc[mt][nt][2], acc[mt][nt][3],
                            af[mt][0], af[mt][1], af[mt][2], af[mt][3],
                            bf[nt][0], bf[nt][1]);
        }
        if (it + 2 < nk) prefetch(it + 2, (it + 2) % 3);
    }
    __syncthreads();   // protect smem reuse in region-0 epilogue

    int region = (mode != 1) ? -1 : ((bn < 2 * DIMC) ? 0 : (bn < 3 * DIMC ? 1 : 2));

    if (region == 0) {
        // ---------- fused per-head QK layernorm ----------
        float* ssum = reinterpret_cast<float*>(smw);       // [128][4]
        float* ssq  = ssum + 128 * 4;                      // [128][4]
        int ch = wn >> 5;

        #pragma unroll
        for (int mt = 0; mt < 4; mt++) {
            float slo = 0.f, sqlo = 0.f, shi = 0.f, sqhi = 0.f;
            #pragma unroll
            for (int nt = 0; nt < 4; nt++) {
                int c = bn + wn + nt * 8 + tig * 2;
                float b0 = bias[c], b1v = bias[c + 1];
                acc[mt][nt][0] += b0; acc[mt][nt][1] += b1v;
                acc[mt][nt][2] += b0; acc[mt][nt][3] += b1v;
                slo  += acc[mt][nt][0] + acc[mt][nt][1];
                sqlo += acc[mt][nt][0] * acc[mt][nt][0] + acc[mt][nt][1] * acc[mt][nt][1];
                shi  += acc[mt][nt][2] + acc[mt][nt][3];
                sqhi += acc[mt][nt][2] * acc[mt][nt][2] + acc[mt][nt][3] * acc[mt][nt][3];
            }
            slo  += __shfl_xor_sync(0xffffffffu, slo, 1);
            slo  += __shfl_xor_sync(0xffffffffu, slo, 2);
            sqlo += __shfl_xor_sync(0xffffffffu, sqlo, 1);
            sqlo += __shfl_xor_sync(0xffffffffu, sqlo, 2);
            shi  += __shfl_xor_sync(0xffffffffu, shi, 1);
            shi  += __shfl_xor_sync(0xffffffffu, shi, 2);
            sqhi += __shfl_xor_sync(0xffffffffu, sqhi, 1);
            sqhi += __shfl_xor_sync(0xffffffffu, sqhi, 2);
            if (tig == 0) {
                int rl = wm + mt * 16 + quad;
                ssum[rl * 4 + ch] = slo;        ssq[rl * 4 + ch] = sqlo;
                ssum[(rl + 8) * 4 + ch] = shi;  ssq[(rl + 8) * 4 + ch] = sqhi;
            }
        }
        __syncthreads();

        int hb = (wn >> 6) << 1;                 // head-half base (0 or 2)
        bool isq = (bn < DIMC);
        const float* gv = isq ? qg : kg;
        const float* bv = isq ? qb : kb;
        float qsc = isq ? 0.125f : 1.f;

        #pragma unroll
        for (int mt = 0; mt < 4; mt++) {
            int rl = wm + mt * 16 + quad;
            float mlo = (ssum[rl * 4 + hb] + ssum[rl * 4 + hb + 1]) * (1.f / 64.f);
            float vlo = (ssq[rl * 4 + hb] + ssq[rl * 4 + hb + 1]) * (1.f / 64.f) - mlo * mlo;
            float rlo = rsqrtf(vlo + LN_EPS);
            float mhi = (ssum[(rl + 8) * 4 + hb] + ssum[(rl + 8) * 4 + hb + 1]) * (1.f / 64.f);
            float vhi = (ssq[(rl + 8) * 4 + hb] + ssq[(rl + 8) * 4 + hb + 1]) * (1.f / 64.f) - mhi * mhi;
            float rhi = rsqrtf(vhi + LN_EPS);
            int r0 = bm + rl;
            #pragma unroll
            for (int nt = 0; nt < 4; nt++) {
                int c = bn + wn + nt * 8 + tig * 2;
                int d = c & 63;
                float g0 = gv[d], g1 = gv[d + 1];
                float e0 = bv[d], e1 = bv[d + 1];
                float o0 = ((acc[mt][nt][0] - mlo) * rlo * g0 + e0) * qsc;
                float o1 = ((acc[mt][nt][1] - mlo) * rlo * g1 + e1) * qsc;
                float o2 = ((acc[mt][nt][2] - mhi) * rhi * g0 + e0) * qsc;
                float o3 = ((acc[mt][nt][3] - mhi) * rhi * g1 + e1) * qsc;
                *reinterpret_cast<uint32_t*>(Ch + (size_t)r0 * ldch + c) = h2pack(o0, o1);
                *reinterpret_cast<uint32_t*>(Ch + (size_t)(r0 + 8) * ldch + c) = h2pack(o2, o3);
            }
        }
        return;
    }

    #pragma unroll
    for (int mt = 0; mt < 4; mt++) {
        int r0 = bm + wm + mt * 16 + quad;
        #pragma unroll
        for (int nt = 0; nt < 4; nt++) {
            int c = bn + wn + nt * 8 + tig * 2;
            float2 v0 = make_float2(acc[mt][nt][0], acc[mt][nt][1]);
            float2 v1 = make_float2(acc[mt][nt][2], acc[mt][nt][3]);
            if (bias) {
                float bx = (c     < nbias) ? bias[c]     : 0.f;
                float by = (c + 1 < nbias) ? bias[c + 1] : 0.f;
                v0.x += bx; v0.y += by;
                v1.x += bx; v1.y += by;
            }
            if (mode == 2) {
                float2 ra = *reinterpret_cast<const float2*>(resid + (size_t)r0 * ldr + c);
                float2 rb = *reinterpret_cast<const float2*>(resid + (size_t)(r0 + 8) * ldr + c);
                v0.x += ra.x; v0.y += ra.y;
                v1.x += rb.x; v1.y += rb.y;
                *reinterpret_cast<float2*>(Cf + (size_t)r0 * ldcf + c) = v0;
                *reinterpret_cast<float2*>(Cf + (size_t)(r0 + 8) * ldcf + c) = v1;
            } else if (region == 1) {
                int d = c - 2 * DIMC;
                int hh = d >> 6, dd = d & 63;
                int bbk = r0 >> 11, nn = r0 & 2047;
                size_t base = ((size_t)(bbk * NHEADS + hh) * DHEAD);
                g_vt[(base + dd    ) * NSEQ + nn    ] = __float2half(v0.x);
                g_vt[(base + dd + 1) * NSEQ + nn    ] = __float2half(v0.y);
                g_vt[(base + dd    ) * NSEQ + nn + 8] = __float2half(v1.x);
                g_vt[(base + dd + 1) * NSEQ + nn + 8] = __float2half(v1.y);
            } else {
                if (region == 2) {
                    v0.x = gelu1(v0.x); v0.y = gelu1(v0.y);
                    v1.x = gelu1(v1.x); v1.y = gelu1(v1.y);
                }
                *reinterpret_cast<uint32_t*>(Ch + (size_t)r0 * ldch + c) = h2pack(v0.x, v0.y);
                *reinterpret_cast<uint32_t*>(Ch + (size_t)(r0 + 8) * ldch + c) = h2pack(v1.x, v1.y);
            }
        }
    }
}

// ============================================================
// Flash attention, fp16 m16n8k16, NO online max (scores provably
// bounded |s|<~9 by per-head LN + Cauchy-Schwarz; unshifted exp sums
// safely in fp32, P<=e^9 fits fp16). fminf(25) clamp as safety net.
// ============================================================
#define KSTRW 36
#define QWORDS (128 * KSTRW)
#define KVWORDS (64 * KSTRW)
#define ATTN_SMEM ((QWORDS + 4 * KVWORDS) * 4)   // 55296 B

__global__ void __launch_bounds__(256, 2)
fattn_kernel(const __half* __restrict__ fused, __half* __restrict__ aout)
{
    extern __shared__ uint32_t smw[];
    uint32_t sbase = smem_u32(smw);

    int tid  = threadIdx.x;
    int wid  = tid >> 5, lane = tid & 31;
    int quad = lane >> 2, tig = lane & 3;
    int lane15 = lane & 15;
    int h  = blockIdx.y;
    int bb = blockIdx.z;
    int q0 = blockIdx.x * 128;
    int tq0 = bb * NSEQ + q0;
    int kvb = bb * NSEQ;
    const __half* vtb = g_vt + (size_t)(bb * NHEADS + h) * DHEAD * NSEQ;

    auto prefetch_kv = [&](int kt, int buf) {
        uint32_t dK = sbase + (uint32_t)(QWORDS + buf * 2 * KVWORDS) * 4;
        uint32_t dV = dK + KVWORDS * 4;
        #pragma unroll
        for (int i = 0; i < 2; i++) {
            int idx = i * 256 + tid;
            int r = idx >> 3, chh = (idx & 7) * 8;
            CP_CG(dK + (uint32_t)(r * KSTRW + chh / 2) * 4,
                  fused + (size_t)(kvb + kt + r) * FWP + DIMC + h * DHEAD + chh);
            CP_CG(dV + (uint32_t)(r * KSTRW + chh / 2) * 4,
                  vtb + (size_t)r * NSEQ + kt + chh);
        }
        CP_COMMIT();
    };

    #pragma unroll
    for (int i = 0; i < 4; i++) {
        int idx = i * 256 + tid;
        int r = idx >> 3, chh = (idx & 7) * 8;
        CP_CA(sbase + (uint32_t)(r * KSTRW + chh / 2) * 4,
              fused + (size_t)(tq0 + r) * FWP + h * DHEAD + chh);
    }
    prefetch_kv(0, 0);
    CP_WAIT(0);
    __syncthreads();

    uint32_t aPat = (uint32_t)(lane15 * KSTRW) * 4 + (lane >> 4) * 16;
    uint32_t bPat = (uint32_t)((((lane >> 4) << 3) + (lane & 7)) * KSTRW) * 4
                  + ((lane >> 3) & 1) * 16;
    uint32_t sPat = (uint32_t)(((((lane >> 3) & 1) << 3) + (lane & 7)) * KSTRW) * 4
                  + (lane >> 4) * 16;

    uint32_t qf[4][4];
    {
        uint32_t qbase = sbase + (uint32_t)(wid * 16 * KSTRW) * 4 + aPat;
        #pragma unroll
        for (int kc = 0; kc < 4; kc++)
            ldsm4(qf[kc][0], qf[kc][1], qf[kc][2], qf[kc][3], qbase + kc * 32);
    }
    uint32_t pBase = sbase + (uint32_t)(wid * 16 * KSTRW) * 4;

    float o[8][4];
    #pragma unroll
    for (int i = 0; i < 8; i++)
        #pragma unroll
        for (int j = 0; j < 4; j++) o[i][j] = 0.f;
    float l0 = 0.f, l1 = 0.f;

    for (int t = 0; t < NSEQ / 64; t++) {
        int b = t & 1;
        if (t + 1 < NSEQ / 64) prefetch_kv((t + 1) * 64, b ^ 1);

        uint32_t kBase = sbase + (uint32_t)(QWORDS + b * 2 * KVWORDS) * 4;
        uint32_t vBase = kBase + KVWORDS * 4;

        float sc[8][4];
        #pragma unroll
        for (int i = 0; i < 8; i++)
            #pragma unroll
            for (int j = 0; j < 4; j++) sc[i][j] = 0.f;

        #pragma unroll
        for (int kc = 0; kc < 4; kc++) {
            #pragma unroll
            for (int np = 0; np < 4; np++) {
                uint32_t b00, b01, b10, b11;
                ldsm4(b00, b01, b10, b11,
                      kBase + (uint32_t)(np * 16 * KSTRW) * 4 + bPat + kc * 32);
                mma_f16(sc[2*np][0], sc[2*np][1], sc[2*np][2], sc[2*np][3],
                        qf[kc][0], qf[kc][1], qf[kc][2], qf[kc][3], b00, b01);
                mma_f16(sc[2*np+1][0], sc[2*np+1][1], sc[2*np+1][2], sc[2*np+1][3],
                        qf[kc][0], qf[kc][1], qf[kc][2], qf[kc][3], b10, b11);
            }
        }

        // unshifted softmax accumulation (scores bounded by LN)
        float rs0 = 0.f, rs1 = 0.f;
        uint32_t hl0[8], hl1[8];
        #pragma unroll
        for (int nf = 0; nf < 8; nf++) {
            float p0 = __expf(fminf(sc[nf][0], 25.f));
            float p1 = __expf(fminf(sc[nf][1], 25.f));
            float p2 = __expf(fminf(sc[nf][2], 25.f));
            float p3 = __expf(fminf(sc[nf][3], 25.f));
            rs0 += p0 + p1; rs1 += p2 + p3;
            hl0[nf] = h2pack(p0, p1);
            hl1[nf] = h2pack(p2, p3);
        }
        #pragma unroll
        for (int np = 0; np < 4; np++)
            stsm4(pBase + sPat + np * 32,
                  hl0[2*np], hl1[2*np], hl0[2*np+1], hl1[2*np+1]);

        rs0 += __shfl_xor_sync(0xffffffffu, rs0, 1);
        rs0 += __shfl_xor_sync(0xffffffffu, rs0, 2);
        rs1 += __shfl_xor_sync(0xffffffffu, rs1, 1);
        rs1 += __shfl_xor_sync(0xffffffffu, rs1, 2);
        l0 += rs0;
        l1 += rs1;
        __syncwarp();

        #pragma unroll
        for (int kc = 0; kc < 4; kc++) {
            uint32_t a0, a1, a2, a3;
            ldsm4(a0, a1, a2, a3, pBase + aPat + kc * 32);
            #pragma unroll
            for (int np = 0; np < 4; np++) {
                uint32_t b00, b01, b10, b11;
                ldsm4(b00, b01, b10, b11,
                      vBase + (uint32_t)(np * 16 * KSTRW) * 4 + bPat + kc * 32);
                mma_f16(o[2*np][0], o[2*np][1], o[2*np][2], o[2*np][3],
                        a0, a1, a2, a3, b00, b01);
                mma_f16(o[2*np+1][0], o[2*np+1][1], o[2*np+1][2], o[2*np+1][3],
                        a0, a1, a2, a3, b10, b11);
            }
        }
        __syncwarp();

        if (t + 1 < NSEQ / 64) { CP_WAIT(0); }
        __syncthreads();
    }

    float il0 = 1.f / l0, il1 = 1.f / l1;
    int r0 = tq0 + wid * 16 + quad;
    #pragma unroll
    for (int nf = 0; nf < 8; nf++) {
        int c = h * DHEAD + nf * 8 + tig * 2;
        *reinterpret_cast<uint32_t*>(aout + (size_t)r0 * DIMC + c) =
            h2pack(o[nf][0] * il0, o[nf][1] * il0);
        *reinterpret_cast<uint32_t*>(aout + (size_t)(r0 + 8) * DIMC + c) =
            h2pack(o[nf][2] * il1, o[nf][3] * il1);
    }
}

// ============================================================
// launch — dual-stream fork/join (graph-capture compatible)
// ============================================================
extern "C" void kernel_launch(void* const* d_in, const int* in_sizes, int n_in,
                              void* d_out, int out_size)
{
    const float* x      = (const float*)d_in[0];
    const float* norm_g = (const float*)d_in[1];
    const float* norm_b = (const float*)d_in[2];
    const float* W1     = (const float*)d_in[3];
    const float* b1     = (const float*)d_in[4];
    const float* qn_g   = (const float*)d_in[5];
    const float* qn_b   = (const float*)d_in[6];
    const float* kn_g   = (const float*)d_in[7];
    const float* kn_b   = (const float*)d_in[8];
    const float* Wao    = (const float*)d_in[9];
    const float* bao    = (const float*)d_in[10];
    const float* Wmo    = (const float*)d_in[11];
    const float* bmo    = (const float*)d_in[12];
    const float* W2     = (const float*)d_in[13];
    const float* b2     = (const float*)d_in[14];
    float*       out    = (float*)d_out;

    __half *norm, *fused, *attn, *w1t, *wfa, *wfm;
    float *beff;
    cudaGetSymbolAddress((void**)&norm,  g_norm);
    cudaGetSymbolAddress((void**)&fused, g_fused);
    cudaGetSymbolAddress((void**)&attn,  g_attn);
    cudaGetSymbolAddress((void**)&w1t,   g_w1t);
    cudaGetSymbolAddress((void**)&wfa,   g_wfa);
    cudaGetSymbolAddress((void**)&wfm,   g_wfm);
    cudaGetSymbolAddress((void**)&beff,  g_beff);

    static bool inited = false;
    static cudaStream_t s2;
    static cudaEvent_t ev1, ev2, evw1;
    if (!inited) {
        cudaStreamCreateWithFlags(&s2, cudaStreamNonBlocking);
        cudaEventCreateWithFlags(&ev1, cudaEventDisableTiming);
        cudaEventCreateWithFlags(&ev2, cudaEventDisableTiming);
        cudaEventCreateWithFlags(&evw1, cudaEventDisableTiming);
        cudaFuncSetAttribute(mma_gemm, cudaFuncAttributeMaxDynamicSharedMemorySize, GEMM_SMEM);
        cudaFuncSetAttribute(fold_kernel, cudaFuncAttributeMaxDynamicSharedMemorySize, GEMM_SMEM);
        cudaFuncSetAttribute(fattn_kernel, cudaFuncAttributeMaxDynamicSharedMemorySize, ATTN_SMEM);
        inited = true;
    }

    // ---- fork: side chain runs prep_w1 (needed by GEMM1) then the fold chain
    cudaEventRecord(ev1, 0);
    cudaStreamWaitEvent(s2, ev1, 0);
    prep_w1_kernel<<<3840, 256, 0, s2>>>(W1);
    cudaEventRecord(evw1, s2);
    prep_rest_kernel<<<9280, 256, 0, s2>>>(W2, Wao, Wmo, bao, bmo, b2);
    fold_kernel<<<116, 256, GEMM_SMEM, s2>>>();
    cudaEventRecord(ev2, s2);

    // ---- main chain: ln runs concurrently with prep_w1
    ln_kernel<<<NTOK, 256>>>(x, norm_g, norm_b, norm);
    cudaStreamWaitEvent(0, evw1, 0);

    // GEMM1: qk->LN'd fused, V->g_vt transposed, mlp->gelu
    mma_gemm<<<dim3(FWP / 128, NTOK / 128), 256, GEMM_SMEM>>>(
        norm, DIMC, w1t, DIMC, DIMC,
        nullptr, 0, nullptr, 0, 0,
        fused, FWP, nullptr, 0, b1, FW, nullptr, 0,
        qn_g, qn_b, kn_g, kn_b, 1);

    // flash attention
    fattn_kernel<<<dim3(NSEQ / 128, NHEADS, 2), 256, ATTN_SMEM>>>(fused, attn);

    // ---- join, then apply: out = x + attn @ wfa^T + gelu_hidden @ wfm^T + beff
    cudaStreamWaitEvent(0, ev2, 0);
    mma_gemm<<<dim3(DIMC / 128, NTOK / 128), 256, GEMM_SMEM>>>(
        attn, DIMC, wfa, DIMC, DIMC,
        fused + 3 * DIMC, FWP, wfm, HIDPAD, HIDPAD,
        nullptr, 0, out, DIMC, beff, DIMC, x, DIMC,
        nullptr, nullptr, nullptr, nullptr, 2);
}

// round 12
// speedup vs baseline: 10.4700x; 1.0831x over previous
#include <cuda_runtime.h>
#include <cuda_fp16.h>
#include <math.h>
#include <stdint.h>

// ---------------- problem constants ----------------
#define NTOK   4096              // B*N = 2*2048
#define DIMC   1024
#define NHEADS 16
#define DHEAD  64
#define MLPHID 716
#define FW     3788              // 3*DIM + MLP_HID (true width)
#define FWP    3840              // padded to 30*128
#define HIDPAD 768               // Wmo rows padded; K2 of apply
#define NSEQ   2048
#define LN_EPS 1e-6f
#define NSLICE 16
#define QSCALE 0.1803368801111204f   // 0.125 * log2(e): softmax in 2^s domain

// ---------------- scratch (static device globals) ------
__device__ __half g_norm [NTOK * DIMC];
__device__ __half g_fused[NTOK * FWP];
__device__ __half g_vt   [2 * NHEADS * DHEAD * NSEQ];   // V transposed [b][h][d][n]
__device__ __half g_attn [NTOK * DIMC];
__device__ __half g_w1t  [FWP  * DIMC];
__device__ __half g_w2t  [DIMC * 2 * DIMC];
__device__ __half g_waor [DIMC * DIMC];
__device__ __half g_wmor [HIDPAD * DIMC];
__device__ __half g_wfa  [DIMC * DIMC];
__device__ __half g_wfm  [DIMC * HIDPAD];
__device__ float  g_beff [DIMC];
__device__ float  g_beffp[NSLICE * DIMC];

// ================= helpers =================
__device__ __forceinline__ uint32_t smem_u32(const void* p) {
    uint32_t a;
    asm("{ .reg .u64 t; cvta.to.shared.u64 t, %1; cvt.u32.u64 %0, t; }" : "=r"(a) : "l"(p));
    return a;
}
__device__ __forceinline__ void mma_f16(float& d0, float& d1, float& d2, float& d3,
                                        uint32_t a0, uint32_t a1, uint32_t a2, uint32_t a3,
                                        uint32_t b0, uint32_t b1)
{
    asm volatile(
        "mma.sync.aligned.m16n8k16.row.col.f32.f16.f16.f32 "
        "{%0,%1,%2,%3}, {%4,%5,%6,%7}, {%8,%9}, {%0,%1,%2,%3};"
        : "+f"(d0), "+f"(d1), "+f"(d2), "+f"(d3)
        : "r"(a0), "r"(a1), "r"(a2), "r"(a3), "r"(b0), "r"(b1));
}
__device__ __forceinline__ void ldsm4(uint32_t& r0, uint32_t& r1, uint32_t& r2, uint32_t& r3,
                                      uint32_t addr)
{
    asm volatile("ldmatrix.sync.aligned.m8n8.x4.shared.b16 {%0,%1,%2,%3}, [%4];"
                 : "=r"(r0), "=r"(r1), "=r"(r2), "=r"(r3) : "r"(addr));
}
__device__ __forceinline__ void stsm4(uint32_t addr, uint32_t r0, uint32_t r1,
                                      uint32_t r2, uint32_t r3)
{
    asm volatile("stmatrix.sync.aligned.m8n8.x4.shared.b16 [%0], {%1,%2,%3,%4};"
                 :: "r"(addr), "r"(r0), "r"(r1), "r"(r2), "r"(r3) : "memory");
}
__device__ __forceinline__ float gelu1(float x) {
    float u = 0.7978845608028654f * (x + 0.044715f * x * x * x);
    return 0.5f * x * (1.f + tanhf(u));
}
__device__ __forceinline__ uint32_t h2pack(float a, float b) {
    __half2 h = __floats2half2_rn(a, b);
    return *reinterpret_cast<uint32_t*>(&h);
}
__device__ __forceinline__ uint32_t h2exp2(uint32_t v) {
    uint32_t r; asm("ex2.approx.f16x2 %0, %1;" : "=r"(r) : "r"(v)); return r;
}
__device__ __forceinline__ uint32_t h2minc(uint32_t v, uint32_t c) {
    __half2 a = *reinterpret_cast<__half2*>(&v);
    __half2 b = *reinterpret_cast<__half2*>(&c);
    __half2 m = __hmin2(a, b);
    return *reinterpret_cast<uint32_t*>(&m);
}
#define CP_CA(dst, src) asm volatile("cp.async.ca.shared.global [%0], [%1], 16;" :: "r"(dst), "l"(src) : "memory")
#define CP_CG(dst, src) asm volatile("cp.async.cg.shared.global [%0], [%1], 16;" :: "r"(dst), "l"(src) : "memory")
#define CP_COMMIT()     asm volatile("cp.async.commit_group;" ::: "memory")
#define CP_WAIT(n)      asm volatile("cp.async.wait_group %0;" :: "n"(n) : "memory")

// ============================================================
// prep_w1: W1 [1024 x 3788] -> w1t [3840][1024] (half), 3840 blocks
// ============================================================
__global__ void prep_w1_kernel(const float* __restrict__ W1)
{
    __shared__ float t[32][33];
    int bid = blockIdx.x, tid = threadIdx.x;
    int tx = tid & 31, ty = tid >> 5;
    int bx = bid % (FWP / 32), by = bid / (FWP / 32);
    int n0 = bx * 32, k0 = by * 32;
    #pragma unroll
    for (int i = 0; i < 32; i += 8) {
        int n = n0 + tx;
        t[ty + i][tx] = (n < FW) ? W1[(size_t)(k0 + ty + i) * FW + n] : 0.f;
    }
    __syncthreads();
    #pragma unroll
    for (int i = 0; i < 32; i += 8)
        g_w1t[(size_t)(n0 + ty + i) * DIMC + k0 + tx] = __float2half(t[tx][ty + i]);
}

// ============================================================
// prep_rest: W2^T, Wao copy, Wmo copy(pad), beff partials — 9280 blocks
// ============================================================
__global__ void prep_rest_kernel(const float* __restrict__ W2,
                                 const float* __restrict__ Wao,
                                 const float* __restrict__ Wmo,
                                 const float* __restrict__ bao,
                                 const float* __restrict__ bmo,
                                 const float* __restrict__ b2)
{
    __shared__ float t[32][33];
    int bid = blockIdx.x, tid = threadIdx.x;
    int tx = tid & 31, ty = tid >> 5;

    if (bid < 2048) {
        int bx = bid % 32, by = bid / 32;
        int n0 = bx * 32, k0 = by * 32;
        #pragma unroll
        for (int i = 0; i < 32; i += 8)
            t[ty + i][tx] = W2[(size_t)(k0 + ty + i) * DIMC + n0 + tx];
        __syncthreads();
        #pragma unroll
        for (int i = 0; i < 32; i += 8)
            g_w2t[(size_t)(n0 + ty + i) * 2 * DIMC + k0 + tx] = __float2half(t[tx][ty + i]);
    } else if (bid < 6144) {
        int idx = (bid - 2048) * 256 + tid;
        g_waor[idx] = __float2half(Wao[idx]);
    } else if (bid < 9216) {
        int idx = (bid - 6144) * 256 + tid;
        int r = idx >> 10, c = idx & 1023;
        g_wmor[idx] = (r < MLPHID) ? __float2half(Wmo[(size_t)r * DIMC + c])
                                   : __float2half(0.f);
    } else {
        int b = bid - 9216;
        int n = (b & 3) * 256 + tid;
        int s = b >> 2;
        float acc = (s == 0) ? b2[n] : 0.f;
        int k0 = s * (2048 / NSLICE), k1 = k0 + (2048 / NSLICE);
        for (int k = k0; k < k1; k++) {
            float c = (k < 1024) ? bao[k] : bmo[k - 1024];
            acc += c * W2[(size_t)k * DIMC + n];
        }
        g_beffp[s * DIMC + n] = acc;
    }
}

// ============================================================
// merged fold launch: BOTH weight folds + beff reduce, one wave.
// ============================================================
#define SSTRW 36
#define ABUFW (128 * SSTRW)
#define STAGEW (2 * ABUFW)
#define GEMM_SMEM (3 * STAGEW * 4)   // 110592 B

__global__ void __launch_bounds__(256, 2)
fold_kernel()
{
    extern __shared__ uint32_t smw[];
    int bid = blockIdx.x, tid = threadIdx.x;

    if (bid >= 112) {
        int n = (bid - 112) * 256 + tid;
        float s = 0.f;
        #pragma unroll
        for (int i = 0; i < NSLICE; i++) s += g_beffp[i * DIMC + n];
        g_beff[n] = s;
        return;
    }

    const __half* A; const __half* Bt; __half* C;
    int lda, ldb, ldc, bm, bn;
    if (bid < 64) {
        A = g_w2t;  lda = 2 * DIMC; Bt = g_waor; ldb = DIMC;
        C = g_wfa;  ldc = DIMC;
        bn = (bid & 7) * 128; bm = (bid >> 3) * 128;
    } else {
        int b = bid - 64;
        A = g_w2t + DIMC; lda = 2 * DIMC; Bt = g_wmor; ldb = DIMC;
        C = g_wfm; ldc = HIDPAD;
        bn = (b % 6) * 128; bm = (b / 6) * 128;
    }

    uint32_t sbase = smem_u32(smw);
    int wid = tid >> 5, lane = tid & 31;
    int quad = lane >> 2, tig = lane & 3;
    int wm = (wid & 1) * 64, wn = (wid >> 1) * 32;
    int lr = tid >> 3, lcw = (tid & 7) * 4;
    int lane15 = lane & 15;

    float acc[4][4][4];
    #pragma unroll
    for (int i = 0; i < 4; i++)
        #pragma unroll
        for (int j = 0; j < 4; j++)
            #pragma unroll
            for (int r = 0; r < 4; r++) acc[i][j][r] = 0.f;

    uint32_t aoff[4];
    #pragma unroll
    for (int mt = 0; mt < 4; mt++)
        aoff[mt] = (uint32_t)((wm + mt * 16 + lane15) * SSTRW) * 4 + (lane >> 4) * 16;
    uint32_t boff0 = (uint32_t)((wn + ((lane >> 4) << 3) + (lane & 7)) * SSTRW) * 4
                   + ((lane >> 3) & 1) * 16;
    uint32_t boff1 = boff0 + 16 * SSTRW * 4;

    const int nk = DIMC >> 6;     // 16

    auto prefetch = [&](int it, int st) {
        int k0 = it << 6;
        uint32_t dA = sbase + (uint32_t)st * STAGEW * 4;
        uint32_t dB = dA + ABUFW * 4;
        #pragma unroll
        for (int i = 0; i < 4; i++) {
            int r = i * 32 + lr;
            CP_CG(dA + (uint32_t)(r * SSTRW + lcw) * 4, A + (size_t)(bm + r) * lda + k0 + lcw * 2);
            CP_CG(dB + (uint32_t)(r * SSTRW + lcw) * 4, Bt + (size_t)(bn + r) * ldb + k0 + lcw * 2);
        }
        CP_COMMIT();
    };

    prefetch(0, 0);
    prefetch(1, 1);

    for (int it = 0; it < nk; it++) {
        if (it == nk - 1) { CP_WAIT(0); } else { CP_WAIT(1); }
        __syncthreads();

        uint32_t stA = sbase + (uint32_t)(it % 3) * STAGEW * 4;
        uint32_t stB = stA + ABUFW * 4;
        #pragma unroll
        for (int kk = 0; kk < 4; kk++) {
            uint32_t af[4][4], bf[4][2];
            #pragma unroll
            for (int mt = 0; mt < 4; mt++)
                ldsm4(af[mt][0], af[mt][1], af[mt][2], af[mt][3],
                      stA + aoff[mt] + kk * 32);
            ldsm4(bf[0][0], bf[0][1], bf[1][0], bf[1][1], stB + boff0 + kk * 32);
            ldsm4(bf[2][0], bf[2][1], bf[3][0], bf[3][1], stB + boff1 + kk * 32);
            #pragma unroll
            for (int mt = 0; mt < 4; mt++)
                #pragma unroll
                for (int nt = 0; nt < 4; nt++)
                    mma_f16(acc[mt][nt][0], acc[mt][nt][1],
                            acc[mt][nt][2], acc[mt][nt][3],
                            af[mt][0], af[mt][1], af[mt][2], af[mt][3],
                            bf[nt][0], bf[nt][1]);
        }
        if (it + 2 < nk) prefetch(it + 2, (it + 2) % 3);
    }

    #pragma unroll
    for (int mt = 0; mt < 4; mt++) {
        int r0 = bm + wm + mt * 16 + quad;
        #pragma unroll
        for (int nt = 0; nt < 4; nt++) {
            int c = bn + wn + nt * 8 + tig * 2;
            *reinterpret_cast<uint32_t*>(C + (size_t)r0 * ldc + c) =
                h2pack(acc[mt][nt][0], acc[mt][nt][1]);
            *reinterpret_cast<uint32_t*>(C + (size_t)(r0 + 8) * ldc + c) =
                h2pack(acc[mt][nt][2], acc[mt][nt][3]);
        }
    }
}

// ============================================================
// LayerNorm over DIM=1024, half output
// ============================================================
__global__ void ln_kernel(const float* __restrict__ x,
                          const float* __restrict__ g,
                          const float* __restrict__ b,
                          __half* __restrict__ out)
{
    int row = blockIdx.x;
    int tid = threadIdx.x;
    const float4 v = reinterpret_cast<const float4*>(x + (size_t)row * DIMC)[tid];

    float s  = v.x + v.y + v.z + v.w;
    float sq = v.x*v.x + v.y*v.y + v.z*v.z + v.w*v.w;
    #pragma unroll
    for (int o = 16; o > 0; o >>= 1) {
        s  += __shfl_xor_sync(0xffffffffu, s,  o);
        sq += __shfl_xor_sync(0xffffffffu, sq, o);
    }
    __shared__ float ws[8], wq[8];
    int warp = tid >> 5, lane = tid & 31;
    if (lane == 0) { ws[warp] = s; wq[warp] = sq; }
    __syncthreads();
    if (warp == 0) {
        float s2  = (lane < 8) ? ws[lane] : 0.f;
        float sq2 = (lane < 8) ? wq[lane] : 0.f;
        #pragma unroll
        for (int o = 4; o > 0; o >>= 1) {
            s2  += __shfl_xor_sync(0xffffffffu, s2,  o);
            sq2 += __shfl_xor_sync(0xffffffffu, sq2, o);
        }
        if (lane == 0) { ws[0] = s2; wq[0] = sq2; }
    }
    __syncthreads();
    float mean = ws[0] * (1.f / DIMC);
    float var  = wq[0] * (1.f / DIMC) - mean * mean;
    float rstd = rsqrtf(var + LN_EPS);

    float4 gg = reinterpret_cast<const float4*>(g)[tid];
    float4 bb = reinterpret_cast<const float4*>(b)[tid];
    uint2 o2;
    o2.x = h2pack((v.x - mean) * rstd * gg.x + bb.x,
                  (v.y - mean) * rstd * gg.y + bb.y);
    o2.y = h2pack((v.z - mean) * rstd * gg.z + bb.z,
                  (v.w - mean) * rstd * gg.w + bb.w);
    reinterpret_cast<uint2*>(out + (size_t)row * DIMC)[tid] = o2;
}

// ============================================================
// fp16 mma.sync GEMM, 3-stage cp.async pipeline, ldmatrix frags.
// mode 1: GEMM1-qkv — region 0 (qk): fused per-head LN (+log2 q scale)
//                     region 1: V->g_vt transposed
// mode 3: GEMM1-mlp slice: gelu epilogue, half out
// mode 2: C float + bias + resid (apply)    mode 0: plain half out
// ============================================================
__global__ void __launch_bounds__(256, 2)
mma_gemm(const __half* __restrict__ A, int lda,
         const __half* __restrict__ Bt, int ldb, int K1,
         const __half* __restrict__ A2, int lda2,
         const __half* __restrict__ Bt2, int ldb2, int K2,
         __half* __restrict__ Ch, int ldch,
         float* __restrict__ Cf, int ldcf,
         const float* __restrict__ bias, int nbias,
         const float* __restrict__ resid, int ldr,
         const float* __restrict__ qg, const float* __restrict__ qb,
         const float* __restrict__ kg, const float* __restrict__ kb,
         int mode)
{
    extern __shared__ uint32_t smw[];
    uint32_t sbase = smem_u32(smw);
    int tid  = threadIdx.x;
    int wid  = tid >> 5, lane = tid & 31;
    int quad = lane >> 2, tig = lane & 3;
    int bm = blockIdx.y * 128, bn = blockIdx.x * 128;
    int wm = (wid & 1) * 64, wn = (wid >> 1) * 32;

    float acc[4][4][4];
    #pragma unroll
    for (int i = 0; i < 4; i++)
        #pragma unroll
        for (int j = 0; j < 4; j++)
            #pragma unroll
            for (int r = 0; r < 4; r++) acc[i][j][r] = 0.f;

    int lr = tid >> 3;
    int lcw = (tid & 7) * 4;

    int lane15 = lane & 15;
    uint32_t aoff[4];
    #pragma unroll
    for (int mt = 0; mt < 4; mt++)
        aoff[mt] = (uint32_t)((wm + mt * 16 + lane15) * SSTRW) * 4 + (lane >> 4) * 16;
    uint32_t boff0 = (uint32_t)((wn + ((lane >> 4) << 3) + (lane & 7)) * SSTRW) * 4
                   + ((lane >> 3) & 1) * 16;
    uint32_t boff1 = boff0 + 16 * SSTRW * 4;

    const int nk1 = K1 >> 6;
    const int nk  = nk1 + (K2 >> 6);

    auto prefetch = [&](int it, int st) {
        const __half* Ab; const __half* Bb; int la, lb, k0;
        if (it < nk1) { Ab = A;  Bb = Bt;  la = lda;  lb = ldb;  k0 = it << 6; }
        else          { Ab = A2; Bb = Bt2; la = lda2; lb = ldb2; k0 = (it - nk1) << 6; }
        uint32_t dA = sbase + (uint32_t)st * STAGEW * 4;
        uint32_t dB = dA + ABUFW * 4;
        #pragma unroll
        for (int i = 0; i < 4; i++) {
            int r = i * 32 + lr;
            CP_CG(dA + (uint32_t)(r * SSTRW + lcw) * 4, Ab + (size_t)(bm + r) * la + k0 + lcw * 2);
            CP_CG(dB + (uint32_t)(r * SSTRW + lcw) * 4, Bb + (size_t)(bn + r) * lb + k0 + lcw * 2);
        }
        CP_COMMIT();
    };

    prefetch(0, 0);
    if (nk > 1) prefetch(1, 1);

    for (int it = 0; it < nk; it++) {
        if (it == nk - 1) { CP_WAIT(0); } else { CP_WAIT(1); }
        __syncthreads();

        uint32_t stA = sbase + (uint32_t)(it % 3) * STAGEW * 4;
        uint32_t stB = stA + ABUFW * 4;

        #pragma unroll
        for (int kk = 0; kk < 4; kk++) {
            uint32_t af[4][4], bf[4][2];
            #pragma unroll
            for (int mt = 0; mt < 4; mt++)
                ldsm4(af[mt][0], af[mt][1], af[mt][2], af[mt][3],
                      stA + aoff[mt] + kk * 32);
            ldsm4(bf[0][0], bf[0][1], bf[1][0], bf[1][1], stB + boff0 + kk * 32);
            ldsm4(bf[2][0], bf[2][1], bf[3][0], bf[3][1], stB + boff1 + kk * 32);
            #pragma unroll
            for (int mt = 0; mt < 4; mt++)
                #pragma unroll
                for (int nt = 0; nt < 4; nt++)
                    mma_f16(acc[mt][nt][0], acc[mt][nt][1],
                            acc[mt][nt][2], acc[mt][nt][3],
                            af[mt][0], af[mt][1], af[mt][2], af[mt][3],
                            bf[nt][0], bf[nt][1]);
        }
        if (it + 2 < nk) prefetch(it + 2, (it + 2) % 3);
    }
    __syncthreads();   // protect smem reuse in region-0 epilogue

    int region = (mode != 1) ? -1 : ((bn < 2 * DIMC) ? 0 : 1);

    if (region == 0) {
        float* ssum = reinterpret_cast<float*>(smw);       // [128][4]
        float* ssq  = ssum + 128 * 4;                      // [128][4]
        int ch = wn >> 5;

        #pragma unroll
        for (int mt = 0; mt < 4; mt++) {
            float slo = 0.f, sqlo = 0.f, shi = 0.f, sqhi = 0.f;
            #pragma unroll
            for (int nt = 0; nt < 4; nt++) {
                int c = bn + wn + nt * 8 + tig * 2;
                float b0 = bias[c], b1v = bias[c + 1];
                acc[mt][nt][0] += b0; acc[mt][nt][1] += b1v;
                acc[mt][nt][2] += b0; acc[mt][nt][3] += b1v;
                slo  += acc[mt][nt][0] + acc[mt][nt][1];
                sqlo += acc[mt][nt][0] * acc[mt][nt][0] + acc[mt][nt][1] * acc[mt][nt][1];
                shi  += acc[mt][nt][2] + acc[mt][nt][3];
                sqhi += acc[mt][nt][2] * acc[mt][nt][2] + acc[mt][nt][3] * acc[mt][nt][3];
            }
            slo  += __shfl_xor_sync(0xffffffffu, slo, 1);
            slo  += __shfl_xor_sync(0xffffffffu, slo, 2);
            sqlo += __shfl_xor_sync(0xffffffffu, sqlo, 1);
            sqlo += __shfl_xor_sync(0xffffffffu, sqlo, 2);
            shi  += __shfl_xor_sync(0xffffffffu, shi, 1);
            shi  += __shfl_xor_sync(0xffffffffu, shi, 2);
            sqhi += __shfl_xor_sync(0xffffffffu, sqhi, 1);
            sqhi += __shfl_xor_sync(0xffffffffu, sqhi, 2);
            if (tig == 0) {
                int rl = wm + mt * 16 + quad;
                ssum[rl * 4 + ch] = slo;        ssq[rl * 4 + ch] = sqlo;
                ssum[(rl + 8) * 4 + ch] = shi;  ssq[(rl + 8) * 4 + ch] = sqhi;
            }
        }
        __syncthreads();

        int hb = (wn >> 6) << 1;
        bool isq = (bn < DIMC);
        const float* gv = isq ? qg : kg;
        const float* bv = isq ? qb : kb;
        float qsc = isq ? QSCALE : 1.f;

        #pragma unroll
        for (int mt = 0; mt < 4; mt++) {
            int rl = wm + mt * 16 + quad;
            float mlo = (ssum[rl * 4 + hb] + ssum[rl * 4 + hb + 1]) * (1.f / 64.f);
            float vlo = (ssq[rl * 4 + hb] + ssq[rl * 4 + hb + 1]) * (1.f / 64.f) - mlo * mlo;
            float rlo = rsqrtf(vlo + LN_EPS);
            float mhi = (ssum[(rl + 8) * 4 + hb] + ssum[(rl + 8) * 4 + hb + 1]) * (1.f / 64.f);
            float vhi = (ssq[(rl + 8) * 4 + hb] + ssq[(rl + 8) * 4 + hb + 1]) * (1.f / 64.f) - mhi * mhi;
            float rhi = rsqrtf(vhi + LN_EPS);
            int r0 = bm + rl;
            #pragma unroll
            for (int nt = 0; nt < 4; nt++) {
                int c = bn + wn + nt * 8 + tig * 2;
                int d = c & 63;
                float g0 = gv[d], g1 = gv[d + 1];
                float e0 = bv[d], e1 = bv[d + 1];
                float o0 = ((acc[mt][nt][0] - mlo) * rlo * g0 + e0) * qsc;
                float o1 = ((acc[mt][nt][1] - mlo) * rlo * g1 + e1) * qsc;
                float o2 = ((acc[mt][nt][2] - mhi) * rhi * g0 + e0) * qsc;
                float o3 = ((acc[mt][nt][3] - mhi) * rhi * g1 + e1) * qsc;
                *reinterpret_cast<uint32_t*>(Ch + (size_t)r0 * ldch + c) = h2pack(o0, o1);
                *reinterpret_cast<uint32_t*>(Ch + (size_t)(r0 + 8) * ldch + c) = h2pack(o2, o3);
            }
        }
        return;
    }

    #pragma unroll
    for (int mt = 0; mt < 4; mt++) {
        int r0 = bm + wm + mt * 16 + quad;
        #pragma unroll
        for (int nt = 0; nt < 4; nt++) {
            int c = bn + wn + nt * 8 + tig * 2;
            float2 v0 = make_float2(acc[mt][nt][0], acc[mt][nt][1]);
            float2 v1 = make_float2(acc[mt][nt][2], acc[mt][nt][3]);
            if (bias) {
                float bx = (c     < nbias) ? bias[c]     : 0.f;
                float by = (c + 1 < nbias) ? bias[c + 1] : 0.f;
                v0.x += bx; v0.y += by;
                v1.x += bx; v1.y += by;
            }
            if (mode == 2) {
                float2 ra = *reinterpret_cast<const float2*>(resid + (size_t)r0 * ldr + c);
                float2 rb = *reinterpret_cast<const float2*>(resid + (size_t)(r0 + 8) * ldr + c);
                v0.x += ra.x; v0.y += ra.y;
                v1.x += rb.x; v1.y += rb.y;
                *reinterpret_cast<float2*>(Cf + (size_t)r0 * ldcf + c) = v0;
                *reinterpret_cast<float2*>(Cf + (size_t)(r0 + 8) * ldcf + c) = v1;
            } else if (region == 1) {
                int d = c - 2 * DIMC;
                int hh = d >> 6, dd = d & 63;
                int bbk = r0 >> 11, nn = r0 & 2047;
                size_t base = ((size_t)(bbk * NHEADS + hh) * DHEAD);
                g_vt[(base + dd    ) * NSEQ + nn    ] = __float2half(v0.x);
                g_vt[(base + dd + 1) * NSEQ + nn    ] = __float2half(v0.y);
                g_vt[(base + dd    ) * NSEQ + nn + 8] = __float2half(v1.x);
                g_vt[(base + dd + 1) * NSEQ + nn + 8] = __float2half(v1.y);
            } else {
                if (mode == 3) {
                    v0.x = gelu1(v0.x); v0.y = gelu1(v0.y);
                    v1.x = gelu1(v1.x); v1.y = gelu1(v1.y);
                }
                *reinterpret_cast<uint32_t*>(Ch + (size_t)r0 * ldch + c) = h2pack(v0.x, v0.y);
                *reinterpret_cast<uint32_t*>(Ch + (size_t)(r0 + 8) * ldch + c) = h2pack(v1.x, v1.y);
            }
        }
    }
}

// ============================================================
// Flash attention: fp16 m16n8k16, no online max (LN-bounded scores),
// p = 2^s via ex2.approx.f16x2 (log2e folded into q), row-sum l via
// one extra MMA against an all-ones B fragment (no shuffles).
// ============================================================
#define KSTRW 36
#define QWORDS (128 * KSTRW)
#define KVWORDS (64 * KSTRW)
#define ATTN_SMEM ((QWORDS + 4 * KVWORDS) * 4)   // 55296 B
#define ONESF  0x3C003C00u
#define CLAMP2 0x4BC04BC0u   // half2(15.5); score bound is ~13.3

__global__ void __launch_bounds__(256, 2)
fattn_kernel(const __half* __restrict__ fused, __half* __restrict__ aout)
{
    extern __shared__ uint32_t smw[];
    uint32_t sbase = smem_u32(smw);

    int tid  = threadIdx.x;
    int wid  = tid >> 5, lane = tid & 31;
    int quad = lane >> 2, tig = lane & 3;
    int lane15 = lane & 15;
    int h  = blockIdx.y;
    int bb = blockIdx.z;
    int q0 = blockIdx.x * 128;
    int tq0 = bb * NSEQ + q0;
    int kvb = bb * NSEQ;
    const __half* vtb = g_vt + (size_t)(bb * NHEADS + h) * DHEAD * NSEQ;

    auto prefetch_kv = [&](int kt, int buf) {
        uint32_t dK = sbase + (uint32_t)(QWORDS + buf * 2 * KVWORDS) * 4;
        uint32_t dV = dK + KVWORDS * 4;
        #pragma unroll
        for (int i = 0; i < 2; i++) {
            int idx = i * 256 + tid;
            int r = idx >> 3, chh = (idx & 7) * 8;
            CP_CG(dK + (uint32_t)(r * KSTRW + chh / 2) * 4,
                  fused + (size_t)(kvb + kt + r) * FWP + DIMC + h * DHEAD + chh);
            CP_CG(dV + (uint32_t)(r * KSTRW + chh / 2) * 4,
                  vtb + (size_t)r * NSEQ + kt + chh);
        }
        CP_COMMIT();
    };

    #pragma unroll
    for (int i = 0; i < 4; i++) {
        int idx = i * 256 + tid;
        int r = idx >> 3, chh = (idx & 7) * 8;
        CP_CA(sbase + (uint32_t)(r * KSTRW + chh / 2) * 4,
              fused + (size_t)(tq0 + r) * FWP + h * DHEAD + chh);
    }
    prefetch_kv(0, 0);
    CP_WAIT(0);
    __syncthreads();

    uint32_t aPat = (uint32_t)(lane15 * KSTRW) * 4 + (lane >> 4) * 16;
    uint32_t bPat = (uint32_t)((((lane >> 4) << 3) + (lane & 7)) * KSTRW) * 4
                  + ((lane >> 3) & 1) * 16;
    uint32_t sPat = (uint32_t)(((((lane >> 3) & 1) << 3) + (lane & 7)) * KSTRW) * 4
                  + (lane >> 4) * 16;

    uint32_t qf[4][4];
    {
        uint32_t qbase = sbase + (uint32_t)(wid * 16 * KSTRW) * 4 + aPat;
        #pragma unroll
        for (int kc = 0; kc < 4; kc++)
            ldsm4(qf[kc][0], qf[kc][1], qf[kc][2], qf[kc][3], qbase + kc * 32);
    }
    uint32_t pBase = sbase + (uint32_t)(wid * 16 * KSTRW) * 4;

    float o[8][4];
    #pragma unroll
    for (int i = 0; i < 8; i++)
        #pragma unroll
        for (int j = 0; j < 4; j++) o[i][j] = 0.f;
    float ls[4] = {0.f, 0.f, 0.f, 0.f};

    for (int t = 0; t < NSEQ / 64; t++) {
        int b = t & 1;
        if (t + 1 < NSEQ / 64) prefetch_kv((t + 1) * 64, b ^ 1);

        uint32_t kBase = sbase + (uint32_t)(QWORDS + b * 2 * KVWORDS) * 4;
        uint32_t vBase = kBase + KVWORDS * 4;

        float sc[8][4];
        #pragma unroll
        for (int i = 0; i < 8; i++)
            #pragma unroll
            for (int j = 0; j < 4; j++) sc[i][j] = 0.f;

        #pragma unroll
        for (int kc = 0; kc < 4; kc++) {
            #pragma unroll
            for (int np = 0; np < 4; np++) {
                uint32_t b00, b01, b10, b11;
                ldsm4(b00, b01, b10, b11,
                      kBase + (uint32_t)(np * 16 * KSTRW) * 4 + bPat + kc * 32);
                mma_f16(sc[2*np][0], sc[2*np][1], sc[2*np][2], sc[2*np][3],
                        qf[kc][0], qf[kc][1], qf[kc][2], qf[kc][3], b00, b01);
                mma_f16(sc[2*np+1][0], sc[2*np+1][1], sc[2*np+1][2], sc[2*np+1][3],
                        qf[kc][0], qf[kc][1], qf[kc][2], qf[kc][3], b10, b11);
            }
        }

        // p = 2^s in f16x2 (s already log2-domain)
        uint32_t hl0[8], hl1[8];
        #pragma unroll
        for (int nf = 0; nf < 8; nf++) {
            hl0[nf] = h2exp2(h2minc(h2pack(sc[nf][0], sc[nf][1]), CLAMP2));
            hl1[nf] = h2exp2(h2minc(h2pack(sc[nf][2], sc[nf][3]), CLAMP2));
        }
        #pragma unroll
        for (int np = 0; np < 4; np++)
            stsm4(pBase + sPat + np * 32,
                  hl0[2*np], hl1[2*np], hl0[2*np+1], hl1[2*np+1]);
        __syncwarp();

        #pragma unroll
        for (int kc = 0; kc < 4; kc++) {
            uint32_t a0, a1, a2, a3;
            ldsm4(a0, a1, a2, a3, pBase + aPat + kc * 32);
            mma_f16(ls[0], ls[1], ls[2], ls[3], a0, a1, a2, a3, ONESF, ONESF);
            #pragma unroll
            for (int np = 0; np < 4; np++) {
                uint32_t b00, b01, b10, b11;
                ldsm4(b00, b01, b10, b11,
                      vBase + (uint32_t)(np * 16 * KSTRW) * 4 + bPat + kc * 32);
                mma_f16(o[2*np][0], o[2*np][1], o[2*np][2], o[2*np][3],
                        a0, a1, a2, a3, b00, b01);
                mma_f16(o[2*np+1][0], o[2*np+1][1], o[2*np+1][2], o[2*np+1][3],
                        a0, a1, a2, a3, b10, b11);
            }
        }
        __syncwarp();

        if (t + 1 < NSEQ / 64) { CP_WAIT(0); }
        __syncthreads();
    }

    float il0 = 1.f / ls[0], il1 = 1.f / ls[2];
    int r0 = tq0 + wid * 16 + quad;
    #pragma unroll
    for (int nf = 0; nf < 8; nf++) {
        int c = h * DHEAD + nf * 8 + tig * 2;
        *reinterpret_cast<uint32_t*>(aout + (size_t)r0 * DIMC + c) =
            h2pack(o[nf][0] * il0, o[nf][1] * il0);
        *reinterpret_cast<uint32_t*>(aout + (size_t)(r0 + 8) * DIMC + c) =
            h2pack(o[nf][2] * il1, o[nf][3] * il1);
    }
}

// ============================================================
// launch — dual-stream fork/join (graph-capture compatible)
// ============================================================
extern "C" void kernel_launch(void* const* d_in, const int* in_sizes, int n_in,
                              void* d_out, int out_size)
{
    const float* x      = (const float*)d_in[0];
    const float* norm_g = (const float*)d_in[1];
    const float* norm_b = (const float*)d_in[2];
    const float* W1     = (const float*)d_in[3];
    const float* b1     = (const float*)d_in[4];
    const float* qn_g   = (const float*)d_in[5];
    const float* qn_b   = (const float*)d_in[6];
    const float* kn_g   = (const float*)d_in[7];
    const float* kn_b   = (const float*)d_in[8];
    const float* Wao    = (const float*)d_in[9];
    const float* bao    = (const float*)d_in[10];
    const float* Wmo    = (const float*)d_in[11];
    const float* bmo    = (const float*)d_in[12];
    const float* W2     = (const float*)d_in[13];
    const float* b2     = (const float*)d_in[14];
    float*       out    = (float*)d_out;

    __half *norm, *fused, *attn, *w1t, *wfa, *wfm;
    float *beff;
    cudaGetSymbolAddress((void**)&norm,  g_norm);
    cudaGetSymbolAddress((void**)&fused, g_fused);
    cudaGetSymbolAddress((void**)&attn,  g_attn);
    cudaGetSymbolAddress((void**)&w1t,   g_w1t);
    cudaGetSymbolAddress((void**)&wfa,   g_wfa);
    cudaGetSymbolAddress((void**)&wfm,   g_wfm);
    cudaGetSymbolAddress((void**)&beff,  g_beff);

    static bool inited = false;
    static cudaStream_t s2;
    static cudaEvent_t ev1, ev3, evw1, evg1;
    if (!inited) {
        cudaStreamCreateWithFlags(&s2, cudaStreamNonBlocking);
        cudaEventCreateWithFlags(&ev1, cudaEventDisableTiming);
        cudaEventCreateWithFlags(&ev3, cudaEventDisableTiming);
        cudaEventCreateWithFlags(&evw1, cudaEventDisableTiming);
        cudaEventCreateWithFlags(&evg1, cudaEventDisableTiming);
        cudaFuncSetAttribute(mma_gemm, cudaFuncAttributeMaxDynamicSharedMemorySize, GEMM_SMEM);
        cudaFuncSetAttribute(fold_kernel, cudaFuncAttributeMaxDynamicSharedMemorySize, GEMM_SMEM);
        cudaFuncSetAttribute(fattn_kernel, cudaFuncAttributeMaxDynamicSharedMemorySize, ATTN_SMEM);
        inited = true;
    }

    // ---- fork: side chain (prep_w1 -> prep_rest -> fold), later the mlp slice
    cudaEventRecord(ev1, 0);
    cudaStreamWaitEvent(s2, ev1, 0);
    prep_w1_kernel<<<3840, 256, 0, s2>>>(W1);
    cudaEventRecord(evw1, s2);
    prep_rest_kernel<<<9280, 256, 0, s2>>>(W2, Wao, Wmo, bao, bmo, b2);
    fold_kernel<<<116, 256, GEMM_SMEM, s2>>>();

    // ---- main chain: ln concurrent with prep_w1
    ln_kernel<<<NTOK, 256>>>(x, norm_g, norm_b, norm);
    cudaStreamWaitEvent(0, evw1, 0);

    // GEMM1-qkv (cols 0..3071): qk->LN'd fused, V->g_vt transposed
    mma_gemm<<<dim3(24, NTOK / 128), 256, GEMM_SMEM>>>(
        norm, DIMC, w1t, DIMC, DIMC,
        nullptr, 0, nullptr, 0, 0,
        fused, FWP, nullptr, 0, b1, FW, nullptr, 0,
        qn_g, qn_b, kn_g, kn_b, 1);
    cudaEventRecord(evg1, 0);

    // side stream: GEMM1-mlp slice (cols 3072.., gelu) overlaps fattn
    cudaStreamWaitEvent(s2, evg1, 0);
    mma_gemm<<<dim3(6, NTOK / 128), 256, GEMM_SMEM, s2>>>(
        norm, DIMC, w1t + (size_t)(3 * DIMC) * DIMC, DIMC, DIMC,
        nullptr, 0, nullptr, 0, 0,
        fused + 3 * DIMC, FWP, nullptr, 0, b1 + 3 * DIMC, FW - 3 * DIMC, nullptr, 0,
        nullptr, nullptr, nullptr, nullptr, 3);
    cudaEventRecord(ev3, s2);

    // flash attention (concurrent with mlp slice)
    fattn_kernel<<<dim3(NSEQ / 128, NHEADS, 2), 256, ATTN_SMEM>>>(fused, attn);

    // ---- join, then apply: out = x + attn @ wfa^T + gelu_hidden @ wfm^T + beff
    cudaStreamWaitEvent(0, ev3, 0);
    mma_gemm<<<dim3(DIMC / 128, NTOK / 128), 256, GEMM_SMEM>>>(
        attn, DIMC, wfa, DIMC, DIMC,
        fused + 3 * DIMC, FWP, wfm, HIDPAD, HIDPAD,
        nullptr, 0, out, DIMC, beff, DIMC, x, DIMC,
        nullptr, nullptr, nullptr, nullptr, 2);
}